// round 5
// baseline (speedup 1.0000x reference)
#include <cuda_runtime.h>
#include <cuda_bf16.h>
#include <math.h>

#define NN 768
#define EE 24576
#define DD 1024

// ---------------- scratch ----------------
__device__ __align__(128) float g_Hs[DD * DD];
__device__ __align__(128) float g_Ho[DD * DD];
__device__ __align__(128) float g_K [DD * DD];
__device__ __align__(128) float g_M [4 * DD * DD];
__device__ __align__(128) float g_T [4 * NN * DD];
__device__ __align__(128) float g_S1[NN * DD];
__device__ __align__(128) float g_S2[NN * DD];
__device__ __align__(128) float g_G [NN * NN];
__device__ __align__(128) float g_ctx[NN * DD];
__device__ __align__(128) float g_W [8 * DD * DD];   // rounded: Wr_s Wr_o Wr_r Ws_v Ws_r Wo_v Wo_r W_ctx
__device__ __align__(128) float g_vft[NN * DD];      // rounded vf
__device__ float g_cs[DD], g_co[DD], g_c3[DD];
__device__ float g_d1[NN], g_d2[NN];
__device__ __align__(128) float g_logits[EE];
__device__ __align__(128) float g_wS[EE];
__device__ __align__(128) float g_wO[EE];
__device__ unsigned g_maxS[NN], g_maxO[NN];
__device__ float g_sumS[NN], g_sumO[NN];
__device__ int g_degS[NN], g_degO[NN], g_baseS[NN], g_baseO[NN], g_curO[NN];
__device__ int g_permO[EE];

#define ASTG (128 * 36)
#define BSTG_TB (128 * 36)
#define BSTG_NT (32 * 132)
#define SMEM_FLOATS (2 * ASTG + 2 * BSTG_TB)
#define SMEM_BYTES (SMEM_FLOATS * 4)

// ---------------- helpers ----------------
__device__ __forceinline__ unsigned f2tf(float f) {
    unsigned r;
    asm("cvt.rna.tf32.f32 %0, %1;" : "=r"(r) : "f"(f));
    return r;
}
__device__ __forceinline__ float rndtf(float f) { return __uint_as_float(f2tf(f)); }

__device__ __forceinline__ void mma_tf32(float c[4], unsigned a0, unsigned a1, unsigned a2, unsigned a3,
                                         unsigned b0, unsigned b1) {
    asm volatile(
        "mma.sync.aligned.m16n8k8.row.col.f32.tf32.tf32.f32 "
        "{%0,%1,%2,%3},{%4,%5,%6,%7},{%8,%9},{%0,%1,%2,%3};"
        : "+f"(c[0]), "+f"(c[1]), "+f"(c[2]), "+f"(c[3])
        : "r"(a0), "r"(a1), "r"(a2), "r"(a3), "r"(b0), "r"(b1));
}
__device__ __forceinline__ void cpa16(float* s, const float* g) {
    unsigned sa = (unsigned)__cvta_generic_to_shared(s);
    asm volatile("cp.async.cg.shared.global [%0], [%1], 16;" :: "r"(sa), "l"(g));
}
__device__ __forceinline__ void cpa_commit() { asm volatile("cp.async.commit_group;"); }
template<int N> __device__ __forceinline__ void cpa_wait() { asm volatile("cp.async.wait_group %0;" :: "n"(N)); }

__device__ __forceinline__ unsigned fkey(float f) {
    unsigned u = __float_as_uint(f);
    return (u & 0x80000000u) ? ~u : (u | 0x80000000u);
}
__device__ __forceinline__ float funkey(unsigned k) {
    return (k & 0x80000000u) ? __uint_as_float(k ^ 0x80000000u) : __uint_as_float(~k);
}

// ---------------- pipelined tf32 mainloop (128x128 tile, K=1024, BK=32, 2-stage cp.async) ----------------
// CVA: apply cvt.rna to A fragments (used only when A is a raw fp32 input, i.e. gemm_logit).
template<bool TB, bool CVA>
__device__ __forceinline__ void run_mainloop(const float* __restrict__ A,
                                             const float* __restrict__ B,
                                             int bm, int bn,
                                             float (&acc)[2][8][4],
                                             float* __restrict__ As,
                                             float* __restrict__ Bs) {
    const int BSTG = TB ? BSTG_TB : BSTG_NT;
    int tid = threadIdx.x;
    int lane = tid & 31;
    int warp = tid >> 5;
    int wm = (warp & 3) * 32;
    int wn = (warp >> 2) * 64;

    auto issue = [&](int kt, int stg) {
        float* as = As + stg * ASTG;
        float* bs = Bs + stg * BSTG;
#pragma unroll
        for (int p = 0; p < 4; p++) {
            int r = p * 32 + (tid >> 3);
            int c = (tid & 7) * 4;
            cpa16(as + r * 36 + c, A + (size_t)(bm + r) * DD + kt * 32 + c);
        }
        if (TB) {
#pragma unroll
            for (int p = 0; p < 4; p++) {
                int r = p * 32 + (tid >> 3);
                int c = (tid & 7) * 4;
                cpa16(bs + r * 36 + c, B + (size_t)(bn + r) * DD + kt * 32 + c);
            }
        } else {
#pragma unroll
            for (int p = 0; p < 4; p++) {
                int r = tid >> 3;
                int c = p * 32 + (tid & 7) * 4;
                cpa16(bs + r * 132 + c, B + (size_t)(kt * 32 + r) * DD + bn + c);
            }
        }
        cpa_commit();
    };

    issue(0, 0);
    for (int kt = 0; kt < 32; kt++) {
        if (kt + 1 < 32) { issue(kt + 1, (kt + 1) & 1); cpa_wait<1>(); }
        else cpa_wait<0>();
        __syncthreads();
        const float* as = As + (kt & 1) * ASTG;
        const float* bs = Bs + (kt & 1) * BSTG;
#pragma unroll
        for (int kk = 0; kk < 4; kk++) {
            int k0 = kk * 8;
            unsigned af[2][4], bf[8][2];
#pragma unroll
            for (int mt = 0; mt < 2; mt++) {
                int r = wm + mt * 16 + (lane >> 2);
                int c = k0 + (lane & 3);
                if (CVA) {
                    af[mt][0] = f2tf(as[r * 36 + c]);
                    af[mt][1] = f2tf(as[(r + 8) * 36 + c]);
                    af[mt][2] = f2tf(as[r * 36 + c + 4]);
                    af[mt][3] = f2tf(as[(r + 8) * 36 + c + 4]);
                } else {
                    af[mt][0] = __float_as_uint(as[r * 36 + c]);
                    af[mt][1] = __float_as_uint(as[(r + 8) * 36 + c]);
                    af[mt][2] = __float_as_uint(as[r * 36 + c + 4]);
                    af[mt][3] = __float_as_uint(as[(r + 8) * 36 + c + 4]);
                }
            }
#pragma unroll
            for (int nt = 0; nt < 8; nt++) {
                int cc = wn + nt * 8 + (lane >> 2);
                int rr = k0 + (lane & 3);
                if (TB) {
                    bf[nt][0] = __float_as_uint(bs[cc * 36 + rr]);
                    bf[nt][1] = __float_as_uint(bs[cc * 36 + rr + 4]);
                } else {
                    bf[nt][0] = __float_as_uint(bs[rr * 132 + cc]);
                    bf[nt][1] = __float_as_uint(bs[(rr + 4) * 132 + cc]);
                }
            }
#pragma unroll
            for (int mt = 0; mt < 2; mt++)
#pragma unroll
                for (int nt = 0; nt < 8; nt++)
                    mma_tf32(acc[mt][nt], af[mt][0], af[mt][1], af[mt][2], af[mt][3],
                             bf[nt][0], bf[nt][1]);
        }
        __syncthreads();
    }
}

// ---------------- batched store GEMM ----------------
struct Desc { const float* A; const float* B; const float* A2; const float* B2; const float* Cadd; float* C; };
struct Batch { Desc d[6]; };

// roundC: RNA-round outputs (set when C is consumed as a later GEMM operand)
__global__ __launch_bounds__(256) void gemm_store(Batch p, int transB, int dual, int ldc, int roundC) {
    extern __shared__ float sm[];
    float* As = sm;
    float* Bs = sm + 2 * ASTG;
    Desc d = p.d[blockIdx.z];
    int bm = blockIdx.y * 128;
    int bn = blockIdx.x * 128;

    float acc[2][8][4];
#pragma unroll
    for (int a = 0; a < 2; a++)
#pragma unroll
        for (int b = 0; b < 8; b++)
#pragma unroll
            for (int c = 0; c < 4; c++) acc[a][b][c] = 0.f;

    if (transB) {
        run_mainloop<true, false>(d.A, d.B, bm, bn, acc, As, Bs);
        if (dual) { __syncthreads(); run_mainloop<true, false>(d.A2, d.B2, bm, bn, acc, As, Bs); }
    } else {
        run_mainloop<false, false>(d.A, d.B, bm, bn, acc, As, Bs);
        if (dual) { __syncthreads(); run_mainloop<false, false>(d.A2, d.B2, bm, bn, acc, As, Bs); }
    }

    int lane = threadIdx.x & 31;
    int warp = threadIdx.x >> 5;
    int wm = (warp & 3) * 32;
    int wn = (warp >> 2) * 64;
#pragma unroll
    for (int mt = 0; mt < 2; mt++)
#pragma unroll
        for (int half = 0; half < 2; half++) {
            int r = bm + wm + mt * 16 + (lane >> 2) + half * 8;
#pragma unroll
            for (int nt = 0; nt < 8; nt++) {
                int c = bn + wn + nt * 8 + (lane & 3) * 2;
                float2 v;
                v.x = acc[mt][nt][half * 2 + 0];
                v.y = acc[mt][nt][half * 2 + 1];
                if (d.Cadd) {
                    v.x += d.Cadd[(size_t)r * ldc + c];
                    v.y += d.Cadd[(size_t)r * ldc + c + 1];
                }
                if (roundC) { v.x = rndtf(v.x); v.y = rndtf(v.y); }
                *(float2*)(d.C + (size_t)r * ldc + c) = v;
            }
        }
}

// ---------------- E-GEMM with fused logit epilogue (A=R raw -> CVA=true) ----------------
__global__ __launch_bounds__(256) void gemm_logit(const float* __restrict__ R,
                                                  const int* __restrict__ sbj,
                                                  const int* __restrict__ obj) {
    extern __shared__ float sm[];
    float* As = sm;
    float* Bs = sm + 2 * ASTG;
    int bm = blockIdx.y * 128;
    int bn = blockIdx.x * 128;

    float acc[2][8][4];
#pragma unroll
    for (int a = 0; a < 2; a++)
#pragma unroll
        for (int b = 0; b < 8; b++)
#pragma unroll
            for (int c = 0; c < 4; c++) acc[a][b][c] = 0.f;

    run_mainloop<false, true>(R, g_K, bm, bn, acc, As, Bs);

    int lane = threadIdx.x & 31;
    int warp = threadIdx.x >> 5;
    int wm = (warp & 3) * 32;
    int wn = (warp >> 2) * 64;
    const float scale = 0.03125f;

#pragma unroll
    for (int mt = 0; mt < 2; mt++) {
#pragma unroll
        for (int half = 0; half < 2; half++) {
            int r = bm + wm + mt * 16 + (lane >> 2) + half * 8;
            int s = sbj[r], o = obj[r];
            const float* Rr  = R    + (size_t)r * DD;
            const float* S1r = g_S1 + (size_t)s * DD;
            const float* S2r = g_S2 + (size_t)o * DD;
            float part = 0.f;
#pragma unroll
            for (int nt = 0; nt < 8; nt++) {
                int c = bn + wn + nt * 8 + (lane & 3) * 2;
                float2 Rv  = *(const float2*)(Rr + c);
                float2 s1v = *(const float2*)(S1r + c);
                float2 s2v = *(const float2*)(S2r + c);
                part += (acc[mt][nt][half * 2 + 0] + s1v.x + s2v.x) * Rv.x;
                part += (acc[mt][nt][half * 2 + 1] + s1v.y + s2v.y) * Rv.y;
            }
            part += __shfl_xor_sync(0xFFFFFFFF, part, 1);
            part += __shfl_xor_sync(0xFFFFFFFF, part, 2);
            if ((lane & 3) == 0) {
                if (bn == 0 && (warp >> 2) == 0)
                    part += g_G[(size_t)s * NN + o] + g_d1[s] + g_d2[o];
                atomicAdd(&g_logits[r], part * scale);
            }
        }
    }
}

// ---------------- final vj GEMM ----------------
__global__ __launch_bounds__(256) void gemm_vj(const float* __restrict__ Wctx,
                                               const float* __restrict__ bias,
                                               const float* __restrict__ vf,
                                               float* __restrict__ out) {
    extern __shared__ float sm[];
    float* As = sm;
    float* Bs = sm + 2 * ASTG;
    int bm = blockIdx.y * 128;
    int bn = blockIdx.x * 128;

    float acc[2][8][4];
#pragma unroll
    for (int a = 0; a < 2; a++)
#pragma unroll
        for (int b = 0; b < 8; b++)
#pragma unroll
            for (int c = 0; c < 4; c++) acc[a][b][c] = 0.f;

    run_mainloop<false, false>(g_ctx, Wctx, bm, bn, acc, As, Bs);

    int lane = threadIdx.x & 31;
    int warp = threadIdx.x >> 5;
    int wm = (warp & 3) * 32;
    int wn = (warp >> 2) * 64;
#pragma unroll
    for (int mt = 0; mt < 2; mt++)
#pragma unroll
        for (int half = 0; half < 2; half++) {
            int r = bm + wm + mt * 16 + (lane >> 2) + half * 8;
            bool inv = (g_degS[r] + g_degO[r]) > 0;
            const float* vfr = vf + (size_t)r * DD;
            float* outr = out + (size_t)r * DD;
#pragma unroll
            for (int nt = 0; nt < 8; nt++) {
                int c = bn + wn + nt * 8 + (lane & 3) * 2;
                float2 v;
                v.x = vfr[c]     + acc[mt][nt][half * 2 + 0] + (inv ? bias[c] : 0.f);
                v.y = vfr[c + 1] + acc[mt][nt][half * 2 + 1] + (inv ? bias[c + 1] : 0.f);
                *(float2*)(outr + c) = v;
            }
        }
}

// ---------------- small kernels ----------------
__global__ void k_round(const float* __restrict__ src, float* __restrict__ dst, int n4) {
    int i = blockIdx.x * blockDim.x + threadIdx.x;
    if (i < n4) {
        float4 v = ((const float4*)src)[i];
        v.x = rndtf(v.x); v.y = rndtf(v.y); v.z = rndtf(v.z); v.w = rndtf(v.w);
        ((float4*)dst)[i] = v;
    }
}
__global__ void k_init() {
    int i = blockIdx.x * blockDim.x + threadIdx.x;
    if (i < NN * DD) g_ctx[i] = 0.f;
    if (i < EE) g_logits[i] = 0.f;
    if (i < NN) {
        g_sumS[i] = 0.f; g_sumO[i] = 0.f;
        g_maxS[i] = 0u; g_maxO[i] = 0u;
        g_degS[i] = 0; g_degO[i] = 0;
    }
}
__global__ void k_hist(const int* __restrict__ sbj, const int* __restrict__ obj) {
    int e = blockIdx.x * blockDim.x + threadIdx.x;
    if (e < EE) { atomicAdd(&g_degS[sbj[e]], 1); atomicAdd(&g_degO[obj[e]], 1); }
}
__global__ void k_scan() {
    if (threadIdx.x == 0) {
        int s = 0, o = 0;
        for (int n = 0; n < NN; n++) {
            g_baseS[n] = s; s += g_degS[n];
            g_baseO[n] = o; g_curO[n] = o; o += g_degO[n];
        }
    }
}
__global__ void k_scatter(const int* __restrict__ obj) {
    int e = blockIdx.x * blockDim.x + threadIdx.x;
    if (e < EE) { int p = atomicAdd(&g_curO[obj[e]], 1); g_permO[p] = e; }
}
__global__ void k_vecs1(const float* __restrict__ b_rel, const float* __restrict__ b_sbj,
                        const float* __restrict__ b_obj, const float* __restrict__ Ws_r,
                        const float* __restrict__ Wo_r) {
    int j = blockIdx.x * blockDim.x + threadIdx.x;
    if (j >= DD) return;
    float s = 0.f, o = 0.f;
    for (int i = 0; i < DD; i++) {
        float br = b_rel[i];
        s += br * Ws_r[(size_t)i * DD + j];
        o += br * Wo_r[(size_t)i * DD + j];
    }
    g_cs[j] = s + b_sbj[j];
    g_co[j] = o + b_obj[j];
}
__global__ void k_c3() {
    int j = blockIdx.x * 8 + (threadIdx.x >> 5);
    int lane = threadIdx.x & 31;
    if (j >= DD) return;
    float a = 0.f;
    for (int i = lane; i < DD; i += 32)
        a += g_cs[i] * g_Ho[(size_t)j * DD + i] + g_co[i] * g_Hs[(size_t)j * DD + i];
#pragma unroll
    for (int off = 16; off > 0; off >>= 1) a += __shfl_xor_sync(0xFFFFFFFF, a, off);
    if (lane == 0) g_c3[j] = a;
}
__global__ void k_addc3() {
    int i = blockIdx.x * blockDim.x + threadIdx.x;
    if (i < NN * DD) g_S1[i] += g_c3[i & (DD - 1)];
}
__global__ void k_scal() {
    int n = blockIdx.x * 8 + (threadIdx.x >> 5);
    int lane = threadIdx.x & 31;
    if (n >= NN) return;
    const float* Ts = g_T + 0 * NN * DD + (size_t)n * DD;
    const float* Us = g_T + 1 * NN * DD + (size_t)n * DD;
    const float* To = g_T + 2 * NN * DD + (size_t)n * DD;
    const float* Uo = g_T + 3 * NN * DD + (size_t)n * DD;
    float t1 = 0.f, t2 = 0.f, t3 = 0.f;
    for (int c = lane; c < DD; c += 32) {
        float cs = g_cs[c], co = g_co[c];
        t1 += (Ts[c] + cs) * (Uo[c] + co);
        t2 += (Us[c] + cs) * (To[c] + co);
        t3 += cs * co;
    }
#pragma unroll
    for (int off = 16; off > 0; off >>= 1) {
        t1 += __shfl_xor_sync(0xFFFFFFFF, t1, off);
        t2 += __shfl_xor_sync(0xFFFFFFFF, t2, off);
        t3 += __shfl_xor_sync(0xFFFFFFFF, t3, off);
    }
    if (lane == 0) { g_d1[n] = t1; g_d2[n] = t2 - t3; }
}
__global__ void k_max(const int* __restrict__ sbj, const int* __restrict__ obj) {
    int e = blockIdx.x * blockDim.x + threadIdx.x;
    if (e < EE) {
        unsigned k = fkey(g_logits[e]);
        atomicMax(&g_maxS[sbj[e]], k);
        atomicMax(&g_maxO[obj[e]], k);
    }
}
__global__ void k_exp(const int* __restrict__ sbj, const int* __restrict__ obj) {
    int e = blockIdx.x * blockDim.x + threadIdx.x;
    if (e < EE) {
        float l = g_logits[e];
        float es = expf(l - funkey(g_maxS[sbj[e]]));
        float eo = expf(l - funkey(g_maxO[obj[e]]));
        g_wS[e] = es; g_wO[e] = eo;
        atomicAdd(&g_sumS[sbj[e]], es);
        atomicAdd(&g_sumO[obj[e]], eo);
    }
}
// ctx kernels: fold 1/sum; round final ctx (GEMM operand for gemm_vj)
__global__ void k_ctxS(const int* __restrict__ obj, const float* __restrict__ vf) {
    int n = blockIdx.x, t = threadIdx.x;
    int beg = g_baseS[n], cnt = g_degS[n];
    if (cnt == 0) return;
    float inv = 1.f / g_sumS[n];
    const float4* vf4 = (const float4*)vf;
    float4 acc = make_float4(0.f, 0.f, 0.f, 0.f);
    for (int i = 0; i < cnt; i++) {
        int e = beg + i;
        float w = g_wS[e];
        float4 v = vf4[(size_t)obj[e] * 256 + t];
        acc.x += w * v.x; acc.y += w * v.y; acc.z += w * v.z; acc.w += w * v.w;
    }
    acc.x *= inv; acc.y *= inv; acc.z *= inv; acc.w *= inv;
    ((float4*)g_ctx)[(size_t)n * 256 + t] = acc;
}
__global__ void k_ctxO(const int* __restrict__ sbj, const float* __restrict__ vf) {
    int n = blockIdx.x, t = threadIdx.x;
    // Always finalize (round) ctx row, even when degO == 0.
    int beg = g_baseO[n], cnt = g_degO[n];
    float4* c4 = (float4*)g_ctx;
    float4 old = c4[(size_t)n * 256 + t];
    if (cnt > 0) {
        float inv = 1.f / g_sumO[n];
        const float4* vf4 = (const float4*)vf;
        float4 acc = make_float4(0.f, 0.f, 0.f, 0.f);
        for (int i = 0; i < cnt; i++) {
            int e = g_permO[beg + i];
            float w = g_wO[e];
            float4 v = vf4[(size_t)sbj[e] * 256 + t];
            acc.x += w * v.x; acc.y += w * v.y; acc.z += w * v.z; acc.w += w * v.w;
        }
        old.x += acc.x * inv; old.y += acc.y * inv; old.z += acc.z * inv; old.w += acc.w * inv;
    }
    old.x = rndtf(old.x); old.y = rndtf(old.y); old.z = rndtf(old.z); old.w = rndtf(old.w);
    c4[(size_t)n * 256 + t] = old;
}

// ---------------- launch ----------------
extern "C" void kernel_launch(void* const* d_in, const int* in_sizes, int n_in,
                              void* d_out, int out_size) {
    const float* vf    = (const float*)d_in[0];
    const float* R     = (const float*)d_in[1];
    const float* W_rel = (const float*)d_in[2];
    const float* b_rel = (const float*)d_in[3];
    const float* W_sbj = (const float*)d_in[4];
    const float* b_sbj = (const float*)d_in[5];
    const float* W_obj = (const float*)d_in[6];
    const float* b_obj = (const float*)d_in[7];
    const float* W_ctx = (const float*)d_in[8];
    const float* b_ctx = (const float*)d_in[9];
    const int* sbj     = (const int*)d_in[10];
    const int* obj     = (const int*)d_in[11];
    float* out = (float*)d_out;

    cudaFuncSetAttribute(gemm_store, cudaFuncAttributeMaxDynamicSharedMemorySize, SMEM_BYTES);
    cudaFuncSetAttribute(gemm_logit, cudaFuncAttributeMaxDynamicSharedMemorySize, SMEM_BYTES);
    cudaFuncSetAttribute(gemm_vj,    cudaFuncAttributeMaxDynamicSharedMemorySize, SMEM_BYTES);

    float *pHs, *pHo, *pK, *pM, *pT, *pS1, *pS2, *pG, *pW, *pVf;
    cudaGetSymbolAddress((void**)&pHs, g_Hs);
    cudaGetSymbolAddress((void**)&pHo, g_Ho);
    cudaGetSymbolAddress((void**)&pK,  g_K);
    cudaGetSymbolAddress((void**)&pM,  g_M);
    cudaGetSymbolAddress((void**)&pT,  g_T);
    cudaGetSymbolAddress((void**)&pS1, g_S1);
    cudaGetSymbolAddress((void**)&pS2, g_S2);
    cudaGetSymbolAddress((void**)&pG,  g_G);
    cudaGetSymbolAddress((void**)&pW,  g_W);
    cudaGetSymbolAddress((void**)&pVf, g_vft);

    // rounded operand copies: [Wr_s Wr_o Wr_r | Ws_v Ws_r | Wo_v Wo_r | W_ctx]
    const float* rWr_s = pW + 0 * (size_t)DD * DD;
    const float* rWr_o = pW + 1 * (size_t)DD * DD;
    const float* rWr_r = pW + 2 * (size_t)DD * DD;
    const float* rWs_v = pW + 3 * (size_t)DD * DD;
    const float* rWs_r = pW + 4 * (size_t)DD * DD;
    const float* rWo_v = pW + 5 * (size_t)DD * DD;
    const float* rWo_r = pW + 6 * (size_t)DD * DD;
    const float* rWctx = pW + 7 * (size_t)DD * DD;

    const float* Ws_r = W_sbj + (size_t)DD * DD;   // raw (for k_vecs1)
    const float* Wo_r = W_obj + (size_t)DD * DD;

    cudaMemcpyAsync(out, R, (size_t)EE * DD * sizeof(float), cudaMemcpyDeviceToDevice);

    k_init<<<(NN * DD + 255) / 256, 256>>>();
    k_hist<<<(EE + 255) / 256, 256>>>(sbj, obj);
    k_scan<<<1, 32>>>();
    k_scatter<<<(EE + 255) / 256, 256>>>(obj);
    k_vecs1<<<4, 256>>>(b_rel, b_sbj, b_obj, Ws_r, Wo_r);

    // RNA-round external GEMM operands into scratch
    k_round<<<(3 * DD * DD / 4 + 255) / 256, 256>>>(W_rel, pW + 0,               3 * DD * DD / 4);
    k_round<<<(2 * DD * DD / 4 + 255) / 256, 256>>>(W_sbj, pW + 3 * (size_t)DD * DD, 2 * DD * DD / 4);
    k_round<<<(2 * DD * DD / 4 + 255) / 256, 256>>>(W_obj, pW + 5 * (size_t)DD * DD, 2 * DD * DD / 4);
    k_round<<<(1 * DD * DD / 4 + 255) / 256, 256>>>(W_ctx, pW + 7 * (size_t)DD * DD, 1 * DD * DD / 4);
    k_round<<<(NN * DD / 4 + 255) / 256, 256>>>(vf, pVf, NN * DD / 4);

    {
        Batch b{};
        b.d[0] = {rWr_r, rWs_r, nullptr, nullptr, nullptr, pHs};
        b.d[1] = {rWr_r, rWo_r, nullptr, nullptr, nullptr, pHo};
        b.d[2] = {rWr_s, rWs_r, nullptr, nullptr, rWs_v,   pM + 0 * (size_t)DD * DD};
        b.d[3] = {rWr_o, rWs_r, nullptr, nullptr, nullptr, pM + 1 * (size_t)DD * DD};
        b.d[4] = {rWr_o, rWo_r, nullptr, nullptr, rWo_v,   pM + 2 * (size_t)DD * DD};
        b.d[5] = {rWr_s, rWo_r, nullptr, nullptr, nullptr, pM + 3 * (size_t)DD * DD};
        gemm_store<<<dim3(8, 8, 6), 256, SMEM_BYTES>>>(b, 0, 0, DD, 1);
    }
    {
        Batch b{};
        for (int z = 0; z < 4; z++)
            b.d[z] = {pVf, pM + (size_t)z * DD * DD, nullptr, nullptr, nullptr, pT + (size_t)z * NN * DD};
        gemm_store<<<dim3(8, 6, 4), 256, SMEM_BYTES>>>(b, 0, 0, DD, 1);
    }
    {
        Batch b{};
        b.d[0] = {pHs, pHo, nullptr, nullptr, nullptr, pK};
        gemm_store<<<dim3(8, 8, 1), 256, SMEM_BYTES>>>(b, 1, 0, DD, 1);
    }
    {
        Batch b{};
        b.d[0] = {pT + 0 * (size_t)NN * DD, pHo, pT + 3 * (size_t)NN * DD, pHs, nullptr, pS1};
        b.d[1] = {pT + 1 * (size_t)NN * DD, pHo, pT + 2 * (size_t)NN * DD, pHs, nullptr, pS2};
        gemm_store<<<dim3(8, 6, 2), 256, SMEM_BYTES>>>(b, 1, 1, DD, 0);
    }
    {
        Batch b{};
        b.d[0] = {pT + 0 * (size_t)NN * DD, pT + 2 * (size_t)NN * DD,
                  pT + 3 * (size_t)NN * DD, pT + 1 * (size_t)NN * DD, nullptr, pG};
        gemm_store<<<dim3(6, 6, 1), 256, SMEM_BYTES>>>(b, 1, 1, NN, 0);
    }
    k_c3<<<128, 256>>>();
    k_addc3<<<(NN * DD + 255) / 256, 256>>>();
    k_scal<<<96, 256>>>();

    gemm_logit<<<dim3(8, 192), 256, SMEM_BYTES>>>(R, sbj, obj);

    k_max<<<(EE + 255) / 256, 256>>>(sbj, obj);
    k_exp<<<(EE + 255) / 256, 256>>>(sbj, obj);
    k_ctxS<<<NN, 256>>>(obj, vf);
    k_ctxO<<<NN, 256>>>(sbj, vf);

    gemm_vj<<<dim3(8, 6), 256, SMEM_BYTES>>>(rWctx, b_ctx, vf, out + (size_t)EE * DD);

    (void)in_sizes; (void)n_in; (void)out_size;
}

// round 6
// speedup vs baseline: 1.1078x; 1.1078x over previous
#include <cuda_runtime.h>
#include <cuda_bf16.h>
#include <math.h>

#define NN 768
#define EE 24576
#define DD 1024

// ---------------- scratch ----------------
__device__ __align__(128) float g_Hs[DD * DD];
__device__ __align__(128) float g_Ho[DD * DD];
__device__ __align__(128) float g_K [DD * DD];
__device__ __align__(128) float g_M [4 * DD * DD];
__device__ __align__(128) float g_T [4 * NN * DD];
__device__ __align__(128) float g_S1[NN * DD];
__device__ __align__(128) float g_S2[NN * DD];
__device__ __align__(128) float g_G [NN * NN];
__device__ __align__(128) float g_ctx[NN * DD];
__device__ __align__(128) float g_W [8 * DD * DD];   // rounded: Wr_s Wr_o Wr_r Ws_v Ws_r Wo_v Wo_r W_ctx
__device__ __align__(128) float g_vft[NN * DD];      // rounded vf
__device__ float g_cs[DD], g_co[DD], g_c3[DD];
__device__ float g_d1[NN], g_d2[NN];
__device__ __align__(128) float g_logits[EE];
__device__ __align__(128) float g_wS[EE];
__device__ __align__(128) float g_wO[EE];
__device__ unsigned g_maxS[NN], g_maxO[NN];
__device__ float g_sumS[NN], g_sumO[NN];
__device__ int g_degS[NN], g_degO[NN], g_baseS[NN], g_baseO[NN], g_curO[NN];
__device__ int g_permO[EE];

#define ASTG (128 * 36)
#define BSTG_TB (128 * 36)
#define BSTG_NT (32 * 132)
#define SMEM_FLOATS (2 * ASTG + 2 * BSTG_TB)
#define SMEM_BYTES (SMEM_FLOATS * 4)

// ---------------- helpers ----------------
__device__ __forceinline__ unsigned f2tf(float f) {
    unsigned r;
    asm("cvt.rna.tf32.f32 %0, %1;" : "=r"(r) : "f"(f));
    return r;
}
__device__ __forceinline__ float rndtf(float f) { return __uint_as_float(f2tf(f)); }

__device__ __forceinline__ void mma_tf32(float c[4], unsigned a0, unsigned a1, unsigned a2, unsigned a3,
                                         unsigned b0, unsigned b1) {
    asm volatile(
        "mma.sync.aligned.m16n8k8.row.col.f32.tf32.tf32.f32 "
        "{%0,%1,%2,%3},{%4,%5,%6,%7},{%8,%9},{%0,%1,%2,%3};"
        : "+f"(c[0]), "+f"(c[1]), "+f"(c[2]), "+f"(c[3])
        : "r"(a0), "r"(a1), "r"(a2), "r"(a3), "r"(b0), "r"(b1));
}
__device__ __forceinline__ void cpa16(float* s, const float* g) {
    unsigned sa = (unsigned)__cvta_generic_to_shared(s);
    asm volatile("cp.async.cg.shared.global [%0], [%1], 16;" :: "r"(sa), "l"(g));
}
__device__ __forceinline__ void cpa_commit() { asm volatile("cp.async.commit_group;"); }
template<int N> __device__ __forceinline__ void cpa_wait() { asm volatile("cp.async.wait_group %0;" :: "n"(N)); }

__device__ __forceinline__ unsigned fkey(float f) {
    unsigned u = __float_as_uint(f);
    return (u & 0x80000000u) ? ~u : (u | 0x80000000u);
}
__device__ __forceinline__ float funkey(unsigned k) {
    return (k & 0x80000000u) ? __uint_as_float(k ^ 0x80000000u) : __uint_as_float(~k);
}

// ---------------- pipelined tf32 mainloop ----------------
// 128x128 CTA tile, 4 warps (128 threads), 64x64 warp tiles, BK=32, 2-stage cp.async.
// CVA: cvt.rna on A fragments (only for raw-fp32 A, i.e. gemm_logit).
template<bool TB, bool CVA>
__device__ __forceinline__ void run_mainloop(const float* __restrict__ A,
                                             const float* __restrict__ B,
                                             int bm, int bn,
                                             float (&acc)[4][8][4],
                                             float* __restrict__ As,
                                             float* __restrict__ Bs) {
    const int BSTG = TB ? BSTG_TB : BSTG_NT;
    int tid = threadIdx.x;
    int lane = tid & 31;
    int warp = tid >> 5;
    int wm = (warp & 1) * 64;
    int wn = (warp >> 1) * 64;

    auto issue = [&](int kt, int stg) {
        float* as = As + stg * ASTG;
        float* bs = Bs + stg * BSTG;
#pragma unroll
        for (int p = 0; p < 8; p++) {
            int idx = p * 128 + tid;
            int r = idx >> 3;
            int c = (idx & 7) * 4;
            cpa16(as + r * 36 + c, A + (size_t)(bm + r) * DD + kt * 32 + c);
        }
        if (TB) {
#pragma unroll
            for (int p = 0; p < 8; p++) {
                int idx = p * 128 + tid;
                int r = idx >> 3;
                int c = (idx & 7) * 4;
                cpa16(bs + r * 36 + c, B + (size_t)(bn + r) * DD + kt * 32 + c);
            }
        } else {
#pragma unroll
            for (int p = 0; p < 8; p++) {
                int idx = p * 128 + tid;
                int r = idx >> 5;
                int c = (idx & 31) * 4;
                cpa16(bs + r * 132 + c, B + (size_t)(kt * 32 + r) * DD + bn + c);
            }
        }
        cpa_commit();
    };

    issue(0, 0);
    for (int kt = 0; kt < 32; kt++) {
        if (kt + 1 < 32) { issue(kt + 1, (kt + 1) & 1); cpa_wait<1>(); }
        else cpa_wait<0>();
        __syncthreads();
        const float* as = As + (kt & 1) * ASTG;
        const float* bs = Bs + (kt & 1) * BSTG;
#pragma unroll
        for (int kk = 0; kk < 4; kk++) {
            int k0 = kk * 8;
            unsigned af[4][4], bf[8][2];
#pragma unroll
            for (int mt = 0; mt < 4; mt++) {
                int r = wm + mt * 16 + (lane >> 2);
                int c = k0 + (lane & 3);
                if (CVA) {
                    af[mt][0] = f2tf(as[r * 36 + c]);
                    af[mt][1] = f2tf(as[(r + 8) * 36 + c]);
                    af[mt][2] = f2tf(as[r * 36 + c + 4]);
                    af[mt][3] = f2tf(as[(r + 8) * 36 + c + 4]);
                } else {
                    af[mt][0] = __float_as_uint(as[r * 36 + c]);
                    af[mt][1] = __float_as_uint(as[(r + 8) * 36 + c]);
                    af[mt][2] = __float_as_uint(as[r * 36 + c + 4]);
                    af[mt][3] = __float_as_uint(as[(r + 8) * 36 + c + 4]);
                }
            }
#pragma unroll
            for (int nt = 0; nt < 8; nt++) {
                int cc = wn + nt * 8 + (lane >> 2);
                int rr = k0 + (lane & 3);
                if (TB) {
                    bf[nt][0] = __float_as_uint(bs[cc * 36 + rr]);
                    bf[nt][1] = __float_as_uint(bs[cc * 36 + rr + 4]);
                } else {
                    bf[nt][0] = __float_as_uint(bs[rr * 132 + cc]);
                    bf[nt][1] = __float_as_uint(bs[(rr + 4) * 132 + cc]);
                }
            }
#pragma unroll
            for (int mt = 0; mt < 4; mt++)
#pragma unroll
                for (int nt = 0; nt < 8; nt++)
                    mma_tf32(acc[mt][nt], af[mt][0], af[mt][1], af[mt][2], af[mt][3],
                             bf[nt][0], bf[nt][1]);
        }
        __syncthreads();
    }
}

// ---------------- batched store GEMM ----------------
struct Desc { const float* A; const float* B; const float* A2; const float* B2; const float* Cadd; float* C; };
struct Batch { Desc d[6]; };

__global__ __launch_bounds__(128) void gemm_store(Batch p, int transB, int dual, int ldc, int roundC) {
    extern __shared__ float sm[];
    float* As = sm;
    float* Bs = sm + 2 * ASTG;
    Desc d = p.d[blockIdx.z];
    int bm = blockIdx.y * 128;
    int bn = blockIdx.x * 128;

    float acc[4][8][4];
#pragma unroll
    for (int a = 0; a < 4; a++)
#pragma unroll
        for (int b = 0; b < 8; b++)
#pragma unroll
            for (int c = 0; c < 4; c++) acc[a][b][c] = 0.f;

    if (transB) {
        run_mainloop<true, false>(d.A, d.B, bm, bn, acc, As, Bs);
        if (dual) { __syncthreads(); run_mainloop<true, false>(d.A2, d.B2, bm, bn, acc, As, Bs); }
    } else {
        run_mainloop<false, false>(d.A, d.B, bm, bn, acc, As, Bs);
        if (dual) { __syncthreads(); run_mainloop<false, false>(d.A2, d.B2, bm, bn, acc, As, Bs); }
    }

    int lane = threadIdx.x & 31;
    int warp = threadIdx.x >> 5;
    int wm = (warp & 1) * 64;
    int wn = (warp >> 1) * 64;
#pragma unroll
    for (int mt = 0; mt < 4; mt++)
#pragma unroll
        for (int half = 0; half < 2; half++) {
            int r = bm + wm + mt * 16 + (lane >> 2) + half * 8;
#pragma unroll
            for (int nt = 0; nt < 8; nt++) {
                int c = bn + wn + nt * 8 + (lane & 3) * 2;
                float2 v;
                v.x = acc[mt][nt][half * 2 + 0];
                v.y = acc[mt][nt][half * 2 + 1];
                if (d.Cadd) {
                    v.x += d.Cadd[(size_t)r * ldc + c];
                    v.y += d.Cadd[(size_t)r * ldc + c + 1];
                }
                if (roundC) { v.x = rndtf(v.x); v.y = rndtf(v.y); }
                *(float2*)(d.C + (size_t)r * ldc + c) = v;
            }
        }
}

// ---------------- E-GEMM with fused logit epilogue (A=R raw -> CVA) ----------------
__global__ __launch_bounds__(128) void gemm_logit(const float* __restrict__ R,
                                                  const int* __restrict__ sbj,
                                                  const int* __restrict__ obj) {
    extern __shared__ float sm[];
    float* As = sm;
    float* Bs = sm + 2 * ASTG;
    int bm = blockIdx.y * 128;
    int bn = blockIdx.x * 128;

    float acc[4][8][4];
#pragma unroll
    for (int a = 0; a < 4; a++)
#pragma unroll
        for (int b = 0; b < 8; b++)
#pragma unroll
            for (int c = 0; c < 4; c++) acc[a][b][c] = 0.f;

    run_mainloop<false, true>(R, g_K, bm, bn, acc, As, Bs);

    int lane = threadIdx.x & 31;
    int warp = threadIdx.x >> 5;
    int wm = (warp & 1) * 64;
    int wn = (warp >> 1) * 64;
    const float scale = 0.03125f;

#pragma unroll
    for (int mt = 0; mt < 4; mt++) {
#pragma unroll
        for (int half = 0; half < 2; half++) {
            int r = bm + wm + mt * 16 + (lane >> 2) + half * 8;
            int s = sbj[r], o = obj[r];
            const float* Rr  = R    + (size_t)r * DD;
            const float* S1r = g_S1 + (size_t)s * DD;
            const float* S2r = g_S2 + (size_t)o * DD;
            float part = 0.f;
#pragma unroll
            for (int nt = 0; nt < 8; nt++) {
                int c = bn + wn + nt * 8 + (lane & 3) * 2;
                float2 Rv  = *(const float2*)(Rr + c);
                float2 s1v = *(const float2*)(S1r + c);
                float2 s2v = *(const float2*)(S2r + c);
                part += (acc[mt][nt][half * 2 + 0] + s1v.x + s2v.x) * Rv.x;
                part += (acc[mt][nt][half * 2 + 1] + s1v.y + s2v.y) * Rv.y;
            }
            part += __shfl_xor_sync(0xFFFFFFFF, part, 1);
            part += __shfl_xor_sync(0xFFFFFFFF, part, 2);
            if ((lane & 3) == 0) {
                if (bn == 0 && wn == 0)
                    part += g_G[(size_t)s * NN + o] + g_d1[s] + g_d2[o];
                atomicAdd(&g_logits[r], part * scale);
            }
        }
    }
}

// ---------------- final vj GEMM ----------------
__global__ __launch_bounds__(128) void gemm_vj(const float* __restrict__ Wctx,
                                               const float* __restrict__ bias,
                                               const float* __restrict__ vf,
                                               float* __restrict__ out) {
    extern __shared__ float sm[];
    float* As = sm;
    float* Bs = sm + 2 * ASTG;
    int bm = blockIdx.y * 128;
    int bn = blockIdx.x * 128;

    float acc[4][8][4];
#pragma unroll
    for (int a = 0; a < 4; a++)
#pragma unroll
        for (int b = 0; b < 8; b++)
#pragma unroll
            for (int c = 0; c < 4; c++) acc[a][b][c] = 0.f;

    run_mainloop<false, false>(g_ctx, Wctx, bm, bn, acc, As, Bs);

    int lane = threadIdx.x & 31;
    int warp = threadIdx.x >> 5;
    int wm = (warp & 1) * 64;
    int wn = (warp >> 1) * 64;
#pragma unroll
    for (int mt = 0; mt < 4; mt++)
#pragma unroll
        for (int half = 0; half < 2; half++) {
            int r = bm + wm + mt * 16 + (lane >> 2) + half * 8;
            bool inv = (g_degS[r] + g_degO[r]) > 0;
            const float* vfr = vf + (size_t)r * DD;
            float* outr = out + (size_t)r * DD;
#pragma unroll
            for (int nt = 0; nt < 8; nt++) {
                int c = bn + wn + nt * 8 + (lane & 3) * 2;
                float2 v;
                v.x = vfr[c]     + acc[mt][nt][half * 2 + 0] + (inv ? bias[c] : 0.f);
                v.y = vfr[c + 1] + acc[mt][nt][half * 2 + 1] + (inv ? bias[c + 1] : 0.f);
                *(float2*)(outr + c) = v;
            }
        }
}

// ---------------- small kernels ----------------
__global__ void k_round(const float* __restrict__ src, float* __restrict__ dst, int n4) {
    int i = blockIdx.x * blockDim.x + threadIdx.x;
    if (i < n4) {
        float4 v = ((const float4*)src)[i];
        v.x = rndtf(v.x); v.y = rndtf(v.y); v.z = rndtf(v.z); v.w = rndtf(v.w);
        ((float4*)dst)[i] = v;
    }
}
__global__ void k_init() {
    int i = blockIdx.x * blockDim.x + threadIdx.x;
    if (i < NN * DD) g_ctx[i] = 0.f;
    if (i < EE) g_logits[i] = 0.f;
    if (i < NN) {
        g_sumS[i] = 0.f; g_sumO[i] = 0.f;
        g_maxS[i] = 0u; g_maxO[i] = 0u;
        g_degS[i] = 0; g_degO[i] = 0;
    }
}
__global__ void k_hist(const int* __restrict__ sbj, const int* __restrict__ obj) {
    int e = blockIdx.x * blockDim.x + threadIdx.x;
    if (e < EE) { atomicAdd(&g_degS[sbj[e]], 1); atomicAdd(&g_degO[obj[e]], 1); }
}
__global__ void k_scan() {
    if (threadIdx.x == 0) {
        int s = 0, o = 0;
        for (int n = 0; n < NN; n++) {
            g_baseS[n] = s; s += g_degS[n];
            g_baseO[n] = o; g_curO[n] = o; o += g_degO[n];
        }
    }
}
__global__ void k_scatter(const int* __restrict__ obj) {
    int e = blockIdx.x * blockDim.x + threadIdx.x;
    if (e < EE) { int p = atomicAdd(&g_curO[obj[e]], 1); g_permO[p] = e; }
}
__global__ void k_vecs1(const float* __restrict__ b_rel, const float* __restrict__ b_sbj,
                        const float* __restrict__ b_obj, const float* __restrict__ Ws_r,
                        const float* __restrict__ Wo_r) {
    int j = blockIdx.x * blockDim.x + threadIdx.x;
    if (j >= DD) return;
    float s = 0.f, o = 0.f;
    for (int i = 0; i < DD; i++) {
        float br = b_rel[i];
        s += br * Ws_r[(size_t)i * DD + j];
        o += br * Wo_r[(size_t)i * DD + j];
    }
    g_cs[j] = s + b_sbj[j];
    g_co[j] = o + b_obj[j];
}
__global__ void k_c3() {
    int j = blockIdx.x * 8 + (threadIdx.x >> 5);
    int lane = threadIdx.x & 31;
    if (j >= DD) return;
    float a = 0.f;
    for (int i = lane; i < DD; i += 32)
        a += g_cs[i] * g_Ho[(size_t)j * DD + i] + g_co[i] * g_Hs[(size_t)j * DD + i];
#pragma unroll
    for (int off = 16; off > 0; off >>= 1) a += __shfl_xor_sync(0xFFFFFFFF, a, off);
    if (lane == 0) g_c3[j] = a;
}
__global__ void k_addc3() {
    int i = blockIdx.x * blockDim.x + threadIdx.x;
    if (i < NN * DD) g_S1[i] += g_c3[i & (DD - 1)];
}
__global__ void k_scal() {
    int n = blockIdx.x * 8 + (threadIdx.x >> 5);
    int lane = threadIdx.x & 31;
    if (n >= NN) return;
    const float* Ts = g_T + 0 * NN * DD + (size_t)n * DD;
    const float* Us = g_T + 1 * NN * DD + (size_t)n * DD;
    const float* To = g_T + 2 * NN * DD + (size_t)n * DD;
    const float* Uo = g_T + 3 * NN * DD + (size_t)n * DD;
    float t1 = 0.f, t2 = 0.f, t3 = 0.f;
    for (int c = lane; c < DD; c += 32) {
        float cs = g_cs[c], co = g_co[c];
        t1 += (Ts[c] + cs) * (Uo[c] + co);
        t2 += (Us[c] + cs) * (To[c] + co);
        t3 += cs * co;
    }
#pragma unroll
    for (int off = 16; off > 0; off >>= 1) {
        t1 += __shfl_xor_sync(0xFFFFFFFF, t1, off);
        t2 += __shfl_xor_sync(0xFFFFFFFF, t2, off);
        t3 += __shfl_xor_sync(0xFFFFFFFF, t3, off);
    }
    if (lane == 0) { g_d1[n] = t1; g_d2[n] = t2 - t3; }
}
__global__ void k_max(const int* __restrict__ sbj, const int* __restrict__ obj) {
    int e = blockIdx.x * blockDim.x + threadIdx.x;
    if (e < EE) {
        unsigned k = fkey(g_logits[e]);
        atomicMax(&g_maxS[sbj[e]], k);
        atomicMax(&g_maxO[obj[e]], k);
    }
}
__global__ void k_exp(const int* __restrict__ sbj, const int* __restrict__ obj) {
    int e = blockIdx.x * blockDim.x + threadIdx.x;
    if (e < EE) {
        float l = g_logits[e];
        float es = expf(l - funkey(g_maxS[sbj[e]]));
        float eo = expf(l - funkey(g_maxO[obj[e]]));
        g_wS[e] = es; g_wO[e] = eo;
        atomicAdd(&g_sumS[sbj[e]], es);
        atomicAdd(&g_sumO[obj[e]], eo);
    }
}
__global__ void k_ctxS(const int* __restrict__ obj, const float* __restrict__ vf) {
    int n = blockIdx.x, t = threadIdx.x;
    int beg = g_baseS[n], cnt = g_degS[n];
    if (cnt == 0) return;
    float inv = 1.f / g_sumS[n];
    const float4* vf4 = (const float4*)vf;
    float4 acc = make_float4(0.f, 0.f, 0.f, 0.f);
    for (int i = 0; i < cnt; i++) {
        int e = beg + i;
        float w = g_wS[e];
        float4 v = vf4[(size_t)obj[e] * 256 + t];
        acc.x += w * v.x; acc.y += w * v.y; acc.z += w * v.z; acc.w += w * v.w;
    }
    acc.x *= inv; acc.y *= inv; acc.z *= inv; acc.w *= inv;
    ((float4*)g_ctx)[(size_t)n * 256 + t] = acc;
}
__global__ void k_ctxO(const int* __restrict__ sbj, const float* __restrict__ vf) {
    int n = blockIdx.x, t = threadIdx.x;
    int beg = g_baseO[n], cnt = g_degO[n];
    float4* c4 = (float4*)g_ctx;
    float4 old = c4[(size_t)n * 256 + t];
    if (cnt > 0) {
        float inv = 1.f / g_sumO[n];
        const float4* vf4 = (const float4*)vf;
        float4 acc = make_float4(0.f, 0.f, 0.f, 0.f);
        for (int i = 0; i < cnt; i++) {
            int e = g_permO[beg + i];
            float w = g_wO[e];
            float4 v = vf4[(size_t)sbj[e] * 256 + t];
            acc.x += w * v.x; acc.y += w * v.y; acc.z += w * v.z; acc.w += w * v.w;
        }
        old.x += acc.x * inv; old.y += acc.y * inv; old.z += acc.z * inv; old.w += acc.w * inv;
    }
    old.x = rndtf(old.x); old.y = rndtf(old.y); old.z = rndtf(old.z); old.w = rndtf(old.w);
    c4[(size_t)n * 256 + t] = old;
}

// ---------------- launch ----------------
extern "C" void kernel_launch(void* const* d_in, const int* in_sizes, int n_in,
                              void* d_out, int out_size) {
    const float* vf    = (const float*)d_in[0];
    const float* R     = (const float*)d_in[1];
    const float* W_rel = (const float*)d_in[2];
    const float* b_rel = (const float*)d_in[3];
    const float* W_sbj = (const float*)d_in[4];
    const float* b_sbj = (const float*)d_in[5];
    const float* W_obj = (const float*)d_in[6];
    const float* b_obj = (const float*)d_in[7];
    const float* W_ctx = (const float*)d_in[8];
    const float* b_ctx = (const float*)d_in[9];
    const int* sbj     = (const int*)d_in[10];
    const int* obj     = (const int*)d_in[11];
    float* out = (float*)d_out;

    cudaFuncSetAttribute(gemm_store, cudaFuncAttributeMaxDynamicSharedMemorySize, SMEM_BYTES);
    cudaFuncSetAttribute(gemm_logit, cudaFuncAttributeMaxDynamicSharedMemorySize, SMEM_BYTES);
    cudaFuncSetAttribute(gemm_vj,    cudaFuncAttributeMaxDynamicSharedMemorySize, SMEM_BYTES);

    float *pHs, *pHo, *pK, *pM, *pT, *pS1, *pS2, *pG, *pW, *pVf;
    cudaGetSymbolAddress((void**)&pHs, g_Hs);
    cudaGetSymbolAddress((void**)&pHo, g_Ho);
    cudaGetSymbolAddress((void**)&pK,  g_K);
    cudaGetSymbolAddress((void**)&pM,  g_M);
    cudaGetSymbolAddress((void**)&pT,  g_T);
    cudaGetSymbolAddress((void**)&pS1, g_S1);
    cudaGetSymbolAddress((void**)&pS2, g_S2);
    cudaGetSymbolAddress((void**)&pG,  g_G);
    cudaGetSymbolAddress((void**)&pW,  g_W);
    cudaGetSymbolAddress((void**)&pVf, g_vft);

    const float* rWr_s = pW + 0 * (size_t)DD * DD;
    const float* rWr_o = pW + 1 * (size_t)DD * DD;
    const float* rWr_r = pW + 2 * (size_t)DD * DD;
    const float* rWs_v = pW + 3 * (size_t)DD * DD;
    const float* rWs_r = pW + 4 * (size_t)DD * DD;
    const float* rWo_v = pW + 5 * (size_t)DD * DD;
    const float* rWo_r = pW + 6 * (size_t)DD * DD;
    const float* rWctx = pW + 7 * (size_t)DD * DD;

    const float* Ws_r = W_sbj + (size_t)DD * DD;   // raw (for k_vecs1)
    const float* Wo_r = W_obj + (size_t)DD * DD;

    cudaMemcpyAsync(out, R, (size_t)EE * DD * sizeof(float), cudaMemcpyDeviceToDevice);

    k_init<<<(NN * DD + 255) / 256, 256>>>();
    k_hist<<<(EE + 255) / 256, 256>>>(sbj, obj);
    k_scan<<<1, 32>>>();
    k_scatter<<<(EE + 255) / 256, 256>>>(obj);
    k_vecs1<<<4, 256>>>(b_rel, b_sbj, b_obj, Ws_r, Wo_r);

    k_round<<<(3 * DD * DD / 4 + 255) / 256, 256>>>(W_rel, pW + 0,               3 * DD * DD / 4);
    k_round<<<(2 * DD * DD / 4 + 255) / 256, 256>>>(W_sbj, pW + 3 * (size_t)DD * DD, 2 * DD * DD / 4);
    k_round<<<(2 * DD * DD / 4 + 255) / 256, 256>>>(W_obj, pW + 5 * (size_t)DD * DD, 2 * DD * DD / 4);
    k_round<<<(1 * DD * DD / 4 + 255) / 256, 256>>>(W_ctx, pW + 7 * (size_t)DD * DD, 1 * DD * DD / 4);
    k_round<<<(NN * DD / 4 + 255) / 256, 256>>>(vf, pVf, NN * DD / 4);

    {
        Batch b{};
        b.d[0] = {rWr_r, rWs_r, nullptr, nullptr, nullptr, pHs};
        b.d[1] = {rWr_r, rWo_r, nullptr, nullptr, nullptr, pHo};
        b.d[2] = {rWr_s, rWs_r, nullptr, nullptr, rWs_v,   pM + 0 * (size_t)DD * DD};
        b.d[3] = {rWr_o, rWs_r, nullptr, nullptr, nullptr, pM + 1 * (size_t)DD * DD};
        b.d[4] = {rWr_o, rWo_r, nullptr, nullptr, rWo_v,   pM + 2 * (size_t)DD * DD};
        b.d[5] = {rWr_s, rWo_r, nullptr, nullptr, nullptr, pM + 3 * (size_t)DD * DD};
        gemm_store<<<dim3(8, 8, 6), 128, SMEM_BYTES>>>(b, 0, 0, DD, 1);
    }
    {
        Batch b{};
        for (int z = 0; z < 4; z++)
            b.d[z] = {pVf, pM + (size_t)z * DD * DD, nullptr, nullptr, nullptr, pT + (size_t)z * NN * DD};
        gemm_store<<<dim3(8, 6, 4), 128, SMEM_BYTES>>>(b, 0, 0, DD, 1);
    }
    {
        Batch b{};
        b.d[0] = {pHs, pHo, nullptr, nullptr, nullptr, pK};
        gemm_store<<<dim3(8, 8, 1), 128, SMEM_BYTES>>>(b, 1, 0, DD, 1);
    }
    {
        Batch b{};
        b.d[0] = {pT + 0 * (size_t)NN * DD, pHo, pT + 3 * (size_t)NN * DD, pHs, nullptr, pS1};
        b.d[1] = {pT + 1 * (size_t)NN * DD, pHo, pT + 2 * (size_t)NN * DD, pHs, nullptr, pS2};
        gemm_store<<<dim3(8, 6, 2), 128, SMEM_BYTES>>>(b, 1, 1, DD, 0);
    }
    {
        Batch b{};
        b.d[0] = {pT + 0 * (size_t)NN * DD, pT + 2 * (size_t)NN * DD,
                  pT + 3 * (size_t)NN * DD, pT + 1 * (size_t)NN * DD, nullptr, pG};
        gemm_store<<<dim3(6, 6, 1), 128, SMEM_BYTES>>>(b, 1, 1, NN, 0);
    }
    k_c3<<<128, 256>>>();
    k_addc3<<<(NN * DD + 255) / 256, 256>>>();
    k_scal<<<96, 256>>>();

    gemm_logit<<<dim3(8, 192), 128, SMEM_BYTES>>>(R, sbj, obj);

    k_max<<<(EE + 255) / 256, 256>>>(sbj, obj);
    k_exp<<<(EE + 255) / 256, 256>>>(sbj, obj);
    k_ctxS<<<NN, 256>>>(obj, vf);
    k_ctxO<<<NN, 256>>>(sbj, vf);

    gemm_vj<<<dim3(8, 6), 128, SMEM_BYTES>>>(rWctx, b_ctx, vf, out + (size_t)EE * DD);

    (void)in_sizes; (void)n_in; (void)out_size;
}

// round 7
// speedup vs baseline: 1.2030x; 1.0859x over previous
#include <cuda_runtime.h>
#include <cuda_bf16.h>
#include <math.h>

#define NN 768
#define EE 24576
#define DD 1024

// ---------------- scratch ----------------
__device__ __align__(128) float g_Hs[DD * DD];
__device__ __align__(128) float g_Ho[DD * DD];
__device__ __align__(128) float g_K [DD * DD];
__device__ __align__(128) float g_M [4 * DD * DD];
__device__ __align__(128) float g_T [4 * NN * DD];
__device__ __align__(128) float g_S1[NN * DD];
__device__ __align__(128) float g_S2[NN * DD];
__device__ __align__(128) float g_G [NN * NN];
__device__ __align__(128) float g_ctx[NN * DD];
__device__ __align__(128) float g_W [8 * DD * DD];   // rounded: Wr_s Wr_o Wr_r Ws_v Ws_r Wo_v Wo_r W_ctx
__device__ __align__(128) float g_vft[NN * DD];      // rounded vf
__device__ float g_cs[DD], g_co[DD], g_c3[DD];
__device__ float g_d1[NN], g_d2[NN];
__device__ __align__(128) float g_logits[EE];
__device__ __align__(128) float g_wS[EE];
__device__ __align__(128) float g_wO[EE];
__device__ unsigned g_maxS[NN], g_maxO[NN];
__device__ float g_sumS[NN], g_sumO[NN];
__device__ int g_degS[NN], g_degO[NN], g_baseS[NN], g_baseO[NN], g_curO[NN];
__device__ int g_permO[EE];

// 3-stage pipeline smem
#define ASTG (128 * 36)
#define BSTG_TB (128 * 36)
#define BSTG_NT (32 * 132)
#define SMEM_FLOATS (3 * ASTG + 3 * BSTG_TB)
#define SMEM_BYTES (SMEM_FLOATS * 4)

// ---------------- helpers ----------------
__device__ __forceinline__ unsigned f2tf(float f) {
    unsigned r;
    asm("cvt.rna.tf32.f32 %0, %1;" : "=r"(r) : "f"(f));
    return r;
}
__device__ __forceinline__ float rndtf(float f) { return __uint_as_float(f2tf(f)); }

__device__ __forceinline__ void mma_tf32(float c[4], unsigned a0, unsigned a1, unsigned a2, unsigned a3,
                                         unsigned b0, unsigned b1) {
    asm volatile(
        "mma.sync.aligned.m16n8k8.row.col.f32.tf32.tf32.f32 "
        "{%0,%1,%2,%3},{%4,%5,%6,%7},{%8,%9},{%0,%1,%2,%3};"
        : "+f"(c[0]), "+f"(c[1]), "+f"(c[2]), "+f"(c[3])
        : "r"(a0), "r"(a1), "r"(a2), "r"(a3), "r"(b0), "r"(b1));
}
__device__ __forceinline__ void cpa16(float* s, const float* g) {
    unsigned sa = (unsigned)__cvta_generic_to_shared(s);
    asm volatile("cp.async.cg.shared.global [%0], [%1], 16;" :: "r"(sa), "l"(g));
}
__device__ __forceinline__ void cpa_commit() { asm volatile("cp.async.commit_group;"); }
template<int N> __device__ __forceinline__ void cpa_wait() { asm volatile("cp.async.wait_group %0;" :: "n"(N)); }

__device__ __forceinline__ unsigned fkey(float f) {
    unsigned u = __float_as_uint(f);
    return (u & 0x80000000u) ? ~u : (u | 0x80000000u);
}
__device__ __forceinline__ float funkey(unsigned k) {
    return (k & 0x80000000u) ? __uint_as_float(k ^ 0x80000000u) : __uint_as_float(~k);
}

// ---------------- pipelined tf32 mainloop ----------------
// 128x128 CTA tile, 4 warps, 64x64 warp tiles, BK=32, 3-stage cp.async, ONE sync per slab.
// Safety: buffer written by issue(kt+2) [= stage (kt-1)%3] was last consumed in compute(kt-1);
// every warp passed the sync at iter kt (which precedes compute(kt)) only after finishing
// compute(kt-1), and issue(kt+2) is after compute(kt) -> no WAR hazard with a single sync.
template<bool TB, bool CVA>
__device__ __forceinline__ void run_mainloop(const float* __restrict__ A,
                                             const float* __restrict__ B,
                                             int bm, int bn,
                                             float (&acc)[4][8][4],
                                             float* __restrict__ As,
                                             float* __restrict__ Bs) {
    const int BSTG = TB ? BSTG_TB : BSTG_NT;
    int tid = threadIdx.x;
    int lane = tid & 31;
    int warp = tid >> 5;
    int wm = (warp & 1) * 64;
    int wn = (warp >> 1) * 64;

    auto issue = [&](int kt) {
        int stg = kt % 3;
        float* as = As + stg * ASTG;
        float* bs = Bs + stg * BSTG;
#pragma unroll
        for (int p = 0; p < 8; p++) {
            int idx = p * 128 + tid;
            int r = idx >> 3;
            int c = (idx & 7) * 4;
            cpa16(as + r * 36 + c, A + (size_t)(bm + r) * DD + kt * 32 + c);
        }
        if (TB) {
#pragma unroll
            for (int p = 0; p < 8; p++) {
                int idx = p * 128 + tid;
                int r = idx >> 3;
                int c = (idx & 7) * 4;
                cpa16(bs + r * 36 + c, B + (size_t)(bn + r) * DD + kt * 32 + c);
            }
        } else {
#pragma unroll
            for (int p = 0; p < 8; p++) {
                int idx = p * 128 + tid;
                int r = idx >> 5;
                int c = (idx & 31) * 4;
                cpa16(bs + r * 132 + c, B + (size_t)(kt * 32 + r) * DD + bn + c);
            }
        }
        cpa_commit();
    };

    issue(0);
    issue(1);
    for (int kt = 0; kt < 32; kt++) {
        cpa_wait<1>();
        __syncthreads();
        const float* as = As + (kt % 3) * ASTG;
        const float* bs = Bs + (kt % 3) * BSTG;
#pragma unroll
        for (int kk = 0; kk < 4; kk++) {
            int k0 = kk * 8;
            unsigned af[4][4], bf[8][2];
#pragma unroll
            for (int mt = 0; mt < 4; mt++) {
                int r = wm + mt * 16 + (lane >> 2);
                int c = k0 + (lane & 3);
                if (CVA) {
                    af[mt][0] = f2tf(as[r * 36 + c]);
                    af[mt][1] = f2tf(as[(r + 8) * 36 + c]);
                    af[mt][2] = f2tf(as[r * 36 + c + 4]);
                    af[mt][3] = f2tf(as[(r + 8) * 36 + c + 4]);
                } else {
                    af[mt][0] = __float_as_uint(as[r * 36 + c]);
                    af[mt][1] = __float_as_uint(as[(r + 8) * 36 + c]);
                    af[mt][2] = __float_as_uint(as[r * 36 + c + 4]);
                    af[mt][3] = __float_as_uint(as[(r + 8) * 36 + c + 4]);
                }
            }
#pragma unroll
            for (int nt = 0; nt < 8; nt++) {
                int cc = wn + nt * 8 + (lane >> 2);
                int rr = k0 + (lane & 3);
                if (TB) {
                    bf[nt][0] = __float_as_uint(bs[cc * 36 + rr]);
                    bf[nt][1] = __float_as_uint(bs[cc * 36 + rr + 4]);
                } else {
                    bf[nt][0] = __float_as_uint(bs[rr * 132 + cc]);
                    bf[nt][1] = __float_as_uint(bs[(rr + 4) * 132 + cc]);
                }
            }
#pragma unroll
            for (int mt = 0; mt < 4; mt++)
#pragma unroll
                for (int nt = 0; nt < 8; nt++)
                    mma_tf32(acc[mt][nt], af[mt][0], af[mt][1], af[mt][2], af[mt][3],
                             bf[nt][0], bf[nt][1]);
        }
        if (kt + 2 < 32) issue(kt + 2);
    }
}

// ---------------- generalized batched GEMM ----------------
struct Desc { const float* A; const float* B; const float* A2; const float* B2;
              const float* Cadd; float* C; int M; int N; int ldc;
              int transB; int dual; int roundC; };
struct Batch { Desc d[6]; };

__global__ __launch_bounds__(128) void gemm_multi(Batch p) {
    Desc d = p.d[blockIdx.z];
    int bm = blockIdx.y * 128;
    int bn = blockIdx.x * 128;
    if (bm >= d.M || bn >= d.N) return;

    extern __shared__ float sm[];
    float* As = sm;
    float* Bs = sm + 3 * ASTG;

    float acc[4][8][4];
#pragma unroll
    for (int a = 0; a < 4; a++)
#pragma unroll
        for (int b = 0; b < 8; b++)
#pragma unroll
            for (int c = 0; c < 4; c++) acc[a][b][c] = 0.f;

    if (d.transB) {
        run_mainloop<true, false>(d.A, d.B, bm, bn, acc, As, Bs);
        if (d.dual) { __syncthreads(); run_mainloop<true, false>(d.A2, d.B2, bm, bn, acc, As, Bs); }
    } else {
        run_mainloop<false, false>(d.A, d.B, bm, bn, acc, As, Bs);
        if (d.dual) { __syncthreads(); run_mainloop<false, false>(d.A2, d.B2, bm, bn, acc, As, Bs); }
    }

    int lane = threadIdx.x & 31;
    int warp = threadIdx.x >> 5;
    int wm = (warp & 1) * 64;
    int wn = (warp >> 1) * 64;
#pragma unroll
    for (int mt = 0; mt < 4; mt++)
#pragma unroll
        for (int half = 0; half < 2; half++) {
            int r = bm + wm + mt * 16 + (lane >> 2) + half * 8;
#pragma unroll
            for (int nt = 0; nt < 8; nt++) {
                int c = bn + wn + nt * 8 + (lane & 3) * 2;
                float2 v;
                v.x = acc[mt][nt][half * 2 + 0];
                v.y = acc[mt][nt][half * 2 + 1];
                if (d.Cadd) {
                    v.x += d.Cadd[(size_t)r * d.ldc + c];
                    v.y += d.Cadd[(size_t)r * d.ldc + c + 1];
                }
                if (d.roundC) { v.x = rndtf(v.x); v.y = rndtf(v.y); }
                *(float2*)(d.C + (size_t)r * d.ldc + c) = v;
            }
        }
}

// ---------------- E-GEMM with fused logit epilogue (A=R raw -> CVA) ----------------
__global__ __launch_bounds__(128) void gemm_logit(const float* __restrict__ R,
                                                  const int* __restrict__ sbj,
                                                  const int* __restrict__ obj) {
    extern __shared__ float sm[];
    float* As = sm;
    float* Bs = sm + 3 * ASTG;
    int bm = blockIdx.y * 128;
    int bn = blockIdx.x * 128;

    float acc[4][8][4];
#pragma unroll
    for (int a = 0; a < 4; a++)
#pragma unroll
        for (int b = 0; b < 8; b++)
#pragma unroll
            for (int c = 0; c < 4; c++) acc[a][b][c] = 0.f;

    run_mainloop<false, true>(R, g_K, bm, bn, acc, As, Bs);

    int lane = threadIdx.x & 31;
    int warp = threadIdx.x >> 5;
    int wm = (warp & 1) * 64;
    int wn = (warp >> 1) * 64;
    const float scale = 0.03125f;

#pragma unroll
    for (int mt = 0; mt < 4; mt++) {
#pragma unroll
        for (int half = 0; half < 2; half++) {
            int r = bm + wm + mt * 16 + (lane >> 2) + half * 8;
            int s = sbj[r], o = obj[r];
            const float* Rr  = R    + (size_t)r * DD;
            const float* S1r = g_S1 + (size_t)s * DD;
            const float* S2r = g_S2 + (size_t)o * DD;
            float part = 0.f;
#pragma unroll
            for (int nt = 0; nt < 8; nt++) {
                int c = bn + wn + nt * 8 + (lane & 3) * 2;
                float2 Rv  = *(const float2*)(Rr + c);
                float2 s1v = *(const float2*)(S1r + c);
                float2 s2v = *(const float2*)(S2r + c);
                part += (acc[mt][nt][half * 2 + 0] + s1v.x + s2v.x) * Rv.x;
                part += (acc[mt][nt][half * 2 + 1] + s1v.y + s2v.y) * Rv.y;
            }
            part += __shfl_xor_sync(0xFFFFFFFF, part, 1);
            part += __shfl_xor_sync(0xFFFFFFFF, part, 2);
            if ((lane & 3) == 0) {
                if (bn == 0 && wn == 0)
                    part += g_G[(size_t)s * NN + o] + g_d1[s] + g_d2[o];
                atomicAdd(&g_logits[r], part * scale);
            }
        }
    }
}

// ---------------- final vj GEMM ----------------
__global__ __launch_bounds__(128) void gemm_vj(const float* __restrict__ Wctx,
                                               const float* __restrict__ bias,
                                               const float* __restrict__ vf,
                                               float* __restrict__ out) {
    extern __shared__ float sm[];
    float* As = sm;
    float* Bs = sm + 3 * ASTG;
    int bm = blockIdx.y * 128;
    int bn = blockIdx.x * 128;

    float acc[4][8][4];
#pragma unroll
    for (int a = 0; a < 4; a++)
#pragma unroll
        for (int b = 0; b < 8; b++)
#pragma unroll
            for (int c = 0; c < 4; c++) acc[a][b][c] = 0.f;

    run_mainloop<false, false>(g_ctx, Wctx, bm, bn, acc, As, Bs);

    int lane = threadIdx.x & 31;
    int warp = threadIdx.x >> 5;
    int wm = (warp & 1) * 64;
    int wn = (warp >> 1) * 64;
#pragma unroll
    for (int mt = 0; mt < 4; mt++)
#pragma unroll
        for (int half = 0; half < 2; half++) {
            int r = bm + wm + mt * 16 + (lane >> 2) + half * 8;
            bool inv = (g_degS[r] + g_degO[r]) > 0;
            const float* vfr = vf + (size_t)r * DD;
            float* outr = out + (size_t)r * DD;
#pragma unroll
            for (int nt = 0; nt < 8; nt++) {
                int c = bn + wn + nt * 8 + (lane & 3) * 2;
                float2 v;
                v.x = vfr[c]     + acc[mt][nt][half * 2 + 0] + (inv ? bias[c] : 0.f);
                v.y = vfr[c + 1] + acc[mt][nt][half * 2 + 1] + (inv ? bias[c + 1] : 0.f);
                *(float2*)(outr + c) = v;
            }
        }
}

// ---------------- small kernels ----------------
__global__ void k_round(const float* __restrict__ src, float* __restrict__ dst, int n4) {
    int i = blockIdx.x * blockDim.x + threadIdx.x;
    if (i < n4) {
        float4 v = ((const float4*)src)[i];
        v.x = rndtf(v.x); v.y = rndtf(v.y); v.z = rndtf(v.z); v.w = rndtf(v.w);
        ((float4*)dst)[i] = v;
    }
}
__global__ void k_init() {
    int i = blockIdx.x * blockDim.x + threadIdx.x;
    if (i < NN * DD) g_ctx[i] = 0.f;
    if (i < EE) g_logits[i] = 0.f;
    if (i < NN) {
        g_sumS[i] = 0.f; g_sumO[i] = 0.f;
        g_maxS[i] = 0u; g_maxO[i] = 0u;
        g_degS[i] = 0; g_degO[i] = 0;
    }
}
__global__ void k_hist(const int* __restrict__ sbj, const int* __restrict__ obj) {
    int e = blockIdx.x * blockDim.x + threadIdx.x;
    if (e < EE) { atomicAdd(&g_degS[sbj[e]], 1); atomicAdd(&g_degO[obj[e]], 1); }
}
__global__ void k_scan() {
    if (threadIdx.x == 0) {
        int s = 0, o = 0;
        for (int n = 0; n < NN; n++) {
            g_baseS[n] = s; s += g_degS[n];
            g_baseO[n] = o; g_curO[n] = o; o += g_degO[n];
        }
    }
}
__global__ void k_scatter(const int* __restrict__ obj) {
    int e = blockIdx.x * blockDim.x + threadIdx.x;
    if (e < EE) { int p = atomicAdd(&g_curO[obj[e]], 1); g_permO[p] = e; }
}
__global__ void k_vecs1(const float* __restrict__ b_rel, const float* __restrict__ b_sbj,
                        const float* __restrict__ b_obj, const float* __restrict__ Ws_r,
                        const float* __restrict__ Wo_r) {
    int j = blockIdx.x * blockDim.x + threadIdx.x;
    if (j >= DD) return;
    float s = 0.f, o = 0.f;
    for (int i = 0; i < DD; i++) {
        float br = b_rel[i];
        s += br * Ws_r[(size_t)i * DD + j];
        o += br * Wo_r[(size_t)i * DD + j];
    }
    g_cs[j] = s + b_sbj[j];
    g_co[j] = o + b_obj[j];
}
__global__ void k_c3() {
    int j = blockIdx.x * 8 + (threadIdx.x >> 5);
    int lane = threadIdx.x & 31;
    if (j >= DD) return;
    float a = 0.f;
    for (int i = lane; i < DD; i += 32)
        a += g_cs[i] * g_Ho[(size_t)j * DD + i] + g_co[i] * g_Hs[(size_t)j * DD + i];
#pragma unroll
    for (int off = 16; off > 0; off >>= 1) a += __shfl_xor_sync(0xFFFFFFFF, a, off);
    if (lane == 0) g_c3[j] = a;
}
__global__ void k_addc3() {
    int i = blockIdx.x * blockDim.x + threadIdx.x;
    if (i < NN * DD) g_S1[i] += g_c3[i & (DD - 1)];
}
__global__ void k_scal() {
    int n = blockIdx.x * 8 + (threadIdx.x >> 5);
    int lane = threadIdx.x & 31;
    if (n >= NN) return;
    const float* Ts = g_T + 0 * NN * DD + (size_t)n * DD;
    const float* Us = g_T + 1 * NN * DD + (size_t)n * DD;
    const float* To = g_T + 2 * NN * DD + (size_t)n * DD;
    const float* Uo = g_T + 3 * NN * DD + (size_t)n * DD;
    float t1 = 0.f, t2 = 0.f, t3 = 0.f;
    for (int c = lane; c < DD; c += 32) {
        float cs = g_cs[c], co = g_co[c];
        t1 += (Ts[c] + cs) * (Uo[c] + co);
        t2 += (Us[c] + cs) * (To[c] + co);
        t3 += cs * co;
    }
#pragma unroll
    for (int off = 16; off > 0; off >>= 1) {
        t1 += __shfl_xor_sync(0xFFFFFFFF, t1, off);
        t2 += __shfl_xor_sync(0xFFFFFFFF, t2, off);
        t3 += __shfl_xor_sync(0xFFFFFFFF, t3, off);
    }
    if (lane == 0) { g_d1[n] = t1; g_d2[n] = t2 - t3; }
}
__global__ void k_max(const int* __restrict__ sbj, const int* __restrict__ obj) {
    int e = blockIdx.x * blockDim.x + threadIdx.x;
    if (e < EE) {
        unsigned k = fkey(g_logits[e]);
        atomicMax(&g_maxS[sbj[e]], k);
        atomicMax(&g_maxO[obj[e]], k);
    }
}
__global__ void k_exp(const int* __restrict__ sbj, const int* __restrict__ obj) {
    int e = blockIdx.x * blockDim.x + threadIdx.x;
    if (e < EE) {
        float l = g_logits[e];
        float es = expf(l - funkey(g_maxS[sbj[e]]));
        float eo = expf(l - funkey(g_maxO[obj[e]]));
        g_wS[e] = es; g_wO[e] = eo;
        atomicAdd(&g_sumS[sbj[e]], es);
        atomicAdd(&g_sumO[obj[e]], eo);
    }
}
__global__ void k_ctxS(const int* __restrict__ obj, const float* __restrict__ vf) {
    int n = blockIdx.x, t = threadIdx.x;
    int beg = g_baseS[n], cnt = g_degS[n];
    if (cnt == 0) return;
    float inv = 1.f / g_sumS[n];
    const float4* vf4 = (const float4*)vf;
    float4 acc = make_float4(0.f, 0.f, 0.f, 0.f);
    for (int i = 0; i < cnt; i++) {
        int e = beg + i;
        float w = g_wS[e];
        float4 v = vf4[(size_t)obj[e] * 256 + t];
        acc.x += w * v.x; acc.y += w * v.y; acc.z += w * v.z; acc.w += w * v.w;
    }
    acc.x *= inv; acc.y *= inv; acc.z *= inv; acc.w *= inv;
    ((float4*)g_ctx)[(size_t)n * 256 + t] = acc;
}
__global__ void k_ctxO(const int* __restrict__ sbj, const float* __restrict__ vf) {
    int n = blockIdx.x, t = threadIdx.x;
    int beg = g_baseO[n], cnt = g_degO[n];
    float4* c4 = (float4*)g_ctx;
    float4 old = c4[(size_t)n * 256 + t];
    if (cnt > 0) {
        float inv = 1.f / g_sumO[n];
        const float4* vf4 = (const float4*)vf;
        float4 acc = make_float4(0.f, 0.f, 0.f, 0.f);
        for (int i = 0; i < cnt; i++) {
            int e = g_permO[beg + i];
            float w = g_wO[e];
            float4 v = vf4[(size_t)sbj[e] * 256 + t];
            acc.x += w * v.x; acc.y += w * v.y; acc.z += w * v.z; acc.w += w * v.w;
        }
        old.x += acc.x * inv; old.y += acc.y * inv; old.z += acc.z * inv; old.w += acc.w * inv;
    }
    old.x = rndtf(old.x); old.y = rndtf(old.y); old.z = rndtf(old.z); old.w = rndtf(old.w);
    c4[(size_t)n * 256 + t] = old;
}

// ---------------- launch ----------------
extern "C" void kernel_launch(void* const* d_in, const int* in_sizes, int n_in,
                              void* d_out, int out_size) {
    const float* vf    = (const float*)d_in[0];
    const float* R     = (const float*)d_in[1];
    const float* W_rel = (const float*)d_in[2];
    const float* b_rel = (const float*)d_in[3];
    const float* W_sbj = (const float*)d_in[4];
    const float* b_sbj = (const float*)d_in[5];
    const float* W_obj = (const float*)d_in[6];
    const float* b_obj = (const float*)d_in[7];
    const float* W_ctx = (const float*)d_in[8];
    const float* b_ctx = (const float*)d_in[9];
    const int* sbj     = (const int*)d_in[10];
    const int* obj     = (const int*)d_in[11];
    float* out = (float*)d_out;

    cudaFuncSetAttribute(gemm_multi, cudaFuncAttributeMaxDynamicSharedMemorySize, SMEM_BYTES);
    cudaFuncSetAttribute(gemm_logit, cudaFuncAttributeMaxDynamicSharedMemorySize, SMEM_BYTES);
    cudaFuncSetAttribute(gemm_vj,    cudaFuncAttributeMaxDynamicSharedMemorySize, SMEM_BYTES);

    float *pHs, *pHo, *pK, *pM, *pT, *pS1, *pS2, *pG, *pW, *pVf;
    cudaGetSymbolAddress((void**)&pHs, g_Hs);
    cudaGetSymbolAddress((void**)&pHo, g_Ho);
    cudaGetSymbolAddress((void**)&pK,  g_K);
    cudaGetSymbolAddress((void**)&pM,  g_M);
    cudaGetSymbolAddress((void**)&pT,  g_T);
    cudaGetSymbolAddress((void**)&pS1, g_S1);
    cudaGetSymbolAddress((void**)&pS2, g_S2);
    cudaGetSymbolAddress((void**)&pG,  g_G);
    cudaGetSymbolAddress((void**)&pW,  g_W);
    cudaGetSymbolAddress((void**)&pVf, g_vft);

    const float* rWr_s = pW + 0 * (size_t)DD * DD;
    const float* rWr_o = pW + 1 * (size_t)DD * DD;
    const float* rWr_r = pW + 2 * (size_t)DD * DD;
    const float* rWs_v = pW + 3 * (size_t)DD * DD;
    const float* rWs_r = pW + 4 * (size_t)DD * DD;
    const float* rWo_v = pW + 5 * (size_t)DD * DD;
    const float* rWo_r = pW + 6 * (size_t)DD * DD;
    const float* rWctx = pW + 7 * (size_t)DD * DD;

    const float* Ws_r = W_sbj + (size_t)DD * DD;   // raw (for k_vecs1)
    const float* Wo_r = W_obj + (size_t)DD * DD;

    cudaMemcpyAsync(out, R, (size_t)EE * DD * sizeof(float), cudaMemcpyDeviceToDevice);

    k_init<<<(NN * DD + 255) / 256, 256>>>();
    k_hist<<<(EE + 255) / 256, 256>>>(sbj, obj);
    k_scan<<<1, 32>>>();
    k_scatter<<<(EE + 255) / 256, 256>>>(obj);
    k_vecs1<<<4, 256>>>(b_rel, b_sbj, b_obj, Ws_r, Wo_r);

    k_round<<<(3 * DD * DD / 4 + 255) / 256, 256>>>(W_rel, pW + 0,               3 * DD * DD / 4);
    k_round<<<(2 * DD * DD / 4 + 255) / 256, 256>>>(W_sbj, pW + 3 * (size_t)DD * DD, 2 * DD * DD / 4);
    k_round<<<(2 * DD * DD / 4 + 255) / 256, 256>>>(W_obj, pW + 5 * (size_t)DD * DD, 2 * DD * DD / 4);
    k_round<<<(1 * DD * DD / 4 + 255) / 256, 256>>>(W_ctx, pW + 7 * (size_t)DD * DD, 1 * DD * DD / 4);
    k_round<<<(NN * DD / 4 + 255) / 256, 256>>>(vf, pVf, NN * DD / 4);

    // L1: 6 weight-weight GEMMs (NN, 1024^3)
    {
        Batch b{};
        b.d[0] = {rWr_r, rWs_r, nullptr, nullptr, nullptr, pHs, DD, DD, DD, 0, 0, 1};
        b.d[1] = {rWr_r, rWo_r, nullptr, nullptr, nullptr, pHo, DD, DD, DD, 0, 0, 1};
        b.d[2] = {rWr_s, rWs_r, nullptr, nullptr, rWs_v,   pM + 0 * (size_t)DD * DD, DD, DD, DD, 0, 0, 1};
        b.d[3] = {rWr_o, rWs_r, nullptr, nullptr, nullptr, pM + 1 * (size_t)DD * DD, DD, DD, DD, 0, 0, 1};
        b.d[4] = {rWr_o, rWo_r, nullptr, nullptr, rWo_v,   pM + 2 * (size_t)DD * DD, DD, DD, DD, 0, 0, 1};
        b.d[5] = {rWr_s, rWo_r, nullptr, nullptr, nullptr, pM + 3 * (size_t)DD * DD, DD, DD, DD, 0, 0, 1};
        gemm_multi<<<dim3(8, 8, 6), 128, SMEM_BYTES>>>(b);
    }
    // L2: node projections T (4, M=768, NN) + K = Hs@Ho^T (NT) in ONE launch
    {
        Batch b{};
        for (int z = 0; z < 4; z++)
            b.d[z] = {pVf, pM + (size_t)z * DD * DD, nullptr, nullptr, nullptr,
                      pT + (size_t)z * NN * DD, NN, DD, DD, 0, 0, 1};
        b.d[4] = {pHs, pHo, nullptr, nullptr, nullptr, pK, DD, DD, DD, 1, 0, 1};
        gemm_multi<<<dim3(8, 8, 5), 128, SMEM_BYTES>>>(b);
    }
    // L3: S1, S2 (dual NT, M=768), G (dual NT, 768x768) in ONE launch
    {
        Batch b{};
        b.d[0] = {pT + 0 * (size_t)NN * DD, pHo, pT + 3 * (size_t)NN * DD, pHs, nullptr, pS1,
                  NN, DD, DD, 1, 1, 0};
        b.d[1] = {pT + 1 * (size_t)NN * DD, pHo, pT + 2 * (size_t)NN * DD, pHs, nullptr, pS2,
                  NN, DD, DD, 1, 1, 0};
        b.d[2] = {pT + 0 * (size_t)NN * DD, pT + 2 * (size_t)NN * DD,
                  pT + 3 * (size_t)NN * DD, pT + 1 * (size_t)NN * DD, nullptr, pG,
                  NN, NN, NN, 1, 1, 0};
        gemm_multi<<<dim3(8, 6, 3), 128, SMEM_BYTES>>>(b);
    }
    k_c3<<<128, 256>>>();
    k_addc3<<<(NN * DD + 255) / 256, 256>>>();
    k_scal<<<96, 256>>>();

    gemm_logit<<<dim3(8, 192), 128, SMEM_BYTES>>>(R, sbj, obj);

    k_max<<<(EE + 255) / 256, 256>>>(sbj, obj);
    k_exp<<<(EE + 255) / 256, 256>>>(sbj, obj);
    k_ctxS<<<NN, 256>>>(obj, vf);
    k_ctxO<<<NN, 256>>>(sbj, vf);

    gemm_vj<<<dim3(8, 6), 128, SMEM_BYTES>>>(rWctx, b_ctx, vf, out + (size_t)EE * DD);

    (void)in_sizes; (void)n_in; (void)out_size;
}

// round 9
// speedup vs baseline: 1.6220x; 1.3483x over previous
#include <cuda_runtime.h>
#include <cuda_fp16.h>
#include <math.h>
#include <cstdint>

#define NN 768
#define EE 24576
#define DD 1024

// ---------------- fp16 GEMM operand scratch (all [x][1024] K-major) ----------------
__device__ __align__(128) __half g_Hs16[DD * DD];
__device__ __align__(128) __half g_Ho16[DD * DD];
__device__ __align__(128) __half g_Kt16[DD * DD];         // Kt[n,k] = K[k,n]
__device__ __align__(128) __half g_MT16[4 * DD * DD];     // M1T..M4T
__device__ __align__(128) __half g_T16 [4 * NN * DD];     // Ts,Us,To,Uo
__device__ __align__(128) __half g_Wr16[3 * DD * DD];     // Wr_s, Wr_o, Wr_r (straight round)
__device__ __align__(128) __half g_WT16[5 * DD * DD];     // Ws_rT, Wo_rT, WctxT, Ws_vT, Wo_vT
__device__ __align__(128) __half g_vf16[NN * DD];
__device__ __align__(128) __half g_R16 [(size_t)EE * DD];
__device__ __align__(128) __half g_ctx16[NN * DD];
// ---------------- fp32 scratch ----------------
__device__ __align__(128) float g_S1[NN * DD];
__device__ __align__(128) float g_S2[NN * DD];
__device__ __align__(128) float g_G [NN * NN];
__device__ __align__(128) float g_ctx[NN * DD];
__device__ float g_cs[DD], g_co[DD], g_c3[DD];
__device__ float g_d1[NN], g_d2[NN];
__device__ __align__(128) float g_logits[EE];
__device__ __align__(128) float g_wS[EE];
__device__ __align__(128) float g_wO[EE];
__device__ unsigned g_maxS[NN], g_maxO[NN];
__device__ float g_sumS[NN], g_sumO[NN];
__device__ int g_degS[NN], g_degO[NN], g_baseS[NN], g_baseO[NN], g_curO[NN];
__device__ int g_permO[EE];

// fp16 pipeline: per stage A tile 128 rows x 20 u32 (32 halves + pad), same for B
#define STR32 20
#define STG32 (128 * STR32)            // 2560 u32 per tile
#define SMEM16_BYTES (3 * 2 * STG32 * 4)  // 61440 B

// ---------------- helpers ----------------
__device__ __forceinline__ void mma16(float c[4], unsigned a0, unsigned a1, unsigned a2, unsigned a3,
                                      unsigned b0, unsigned b1) {
    asm volatile(
        "mma.sync.aligned.m16n8k16.row.col.f32.f16.f16.f32 "
        "{%0,%1,%2,%3},{%4,%5,%6,%7},{%8,%9},{%0,%1,%2,%3};"
        : "+f"(c[0]), "+f"(c[1]), "+f"(c[2]), "+f"(c[3])
        : "r"(a0), "r"(a1), "r"(a2), "r"(a3), "r"(b0), "r"(b1));
}
__device__ __forceinline__ void cpa16p(void* s, const void* g) {
    unsigned sa = (unsigned)__cvta_generic_to_shared(s);
    asm volatile("cp.async.cg.shared.global [%0], [%1], 16;" :: "r"(sa), "l"(g));
}
__device__ __forceinline__ void cpa_commit() { asm volatile("cp.async.commit_group;"); }
template<int N> __device__ __forceinline__ void cpa_wait() { asm volatile("cp.async.wait_group %0;" :: "n"(N)); }

__device__ __forceinline__ unsigned fkey(float f) {
    unsigned u = __float_as_uint(f);
    return (u & 0x80000000u) ? ~u : (u | 0x80000000u);
}
__device__ __forceinline__ float funkey(unsigned k) {
    return (k & 0x80000000u) ? __uint_as_float(k ^ 0x80000000u) : __uint_as_float(~k);
}

// ---------------- fp16 NT mainloop ----------------
// C[m,n] = sum_k A[m,k] * B[n,k], K=1024, BK=32, 3-stage cp.async, one sync/slab.
// 128x128 CTA tile, 4 warps, 64x64 warp tiles, m16n8k16.
__device__ __forceinline__ void run_ml16(const __half* __restrict__ A,
                                         const __half* __restrict__ B,
                                         int bm, int bn,
                                         float (&acc)[4][8][4],
                                         uint32_t* __restrict__ As,
                                         uint32_t* __restrict__ Bs) {
    int tid = threadIdx.x;
    int lane = tid & 31;
    int warp = tid >> 5;
    int wm = (warp & 1) * 64;
    int wn = (warp >> 1) * 64;
    int g = lane >> 2;
    int t4 = lane & 3;

    auto issue = [&](int s) {
        int stg = s % 3;
        uint32_t* as = As + stg * STG32;
        uint32_t* bs = Bs + stg * STG32;
#pragma unroll
        for (int p = 0; p < 4; p++) {
            int idx = p * 128 + tid;
            int row = idx >> 2;
            int c4 = idx & 3;
            cpa16p(as + row * STR32 + c4 * 4, A + (size_t)(bm + row) * DD + s * 32 + c4 * 8);
        }
#pragma unroll
        for (int p = 0; p < 4; p++) {
            int idx = p * 128 + tid;
            int row = idx >> 2;
            int c4 = idx & 3;
            cpa16p(bs + row * STR32 + c4 * 4, B + (size_t)(bn + row) * DD + s * 32 + c4 * 8);
        }
        cpa_commit();
    };

    issue(0);
    issue(1);
    for (int kt = 0; kt < 32; kt++) {
        cpa_wait<1>();
        __syncthreads();
        const uint32_t* as = As + (kt % 3) * STG32;
        const uint32_t* bs = Bs + (kt % 3) * STG32;
#pragma unroll
        for (int kk = 0; kk < 2; kk++) {
            int kb = kk * 8 + t4;
            unsigned af[4][4], bf[8][2];
#pragma unroll
            for (int mt = 0; mt < 4; mt++) {
                int r = wm + mt * 16 + g;
                af[mt][0] = as[r * STR32 + kb];
                af[mt][1] = as[(r + 8) * STR32 + kb];
                af[mt][2] = as[r * STR32 + kb + 4];
                af[mt][3] = as[(r + 8) * STR32 + kb + 4];
            }
#pragma unroll
            for (int nt = 0; nt < 8; nt++) {
                int cc = wn + nt * 8 + g;
                bf[nt][0] = bs[cc * STR32 + kb];
                bf[nt][1] = bs[cc * STR32 + kb + 4];
            }
#pragma unroll
            for (int mt = 0; mt < 4; mt++)
#pragma unroll
                for (int nt = 0; nt < 8; nt++)
                    mma16(acc[mt][nt], af[mt][0], af[mt][1], af[mt][2], af[mt][3],
                          bf[nt][0], bf[nt][1]);
        }
        if (kt + 2 < 32) issue(kt + 2);
    }
}

// ---------------- generalized batched NT GEMM ----------------
struct Desc {
    const __half* A; const __half* B; const __half* A2; const __half* B2;
    const __half* CaddH;          // optional half addend [m][n]
    float* C32; __half* C16;      // exactly one non-null
    int M; int N; int ldc; int dual;
};
struct Batch { Desc d[6]; };

__global__ __launch_bounds__(128) void gemm_multi(Batch p) {
    Desc d = p.d[blockIdx.z];
    int bm = blockIdx.y * 128;
    int bn = blockIdx.x * 128;
    if (bm >= d.M || bn >= d.N) return;

    extern __shared__ uint32_t sm16[];
    uint32_t* As = sm16;
    uint32_t* Bs = sm16 + 3 * STG32;

    float acc[4][8][4];
#pragma unroll
    for (int a = 0; a < 4; a++)
#pragma unroll
        for (int b = 0; b < 8; b++)
#pragma unroll
            for (int c = 0; c < 4; c++) acc[a][b][c] = 0.f;

    run_ml16(d.A, d.B, bm, bn, acc, As, Bs);
    if (d.dual) { __syncthreads(); run_ml16(d.A2, d.B2, bm, bn, acc, As, Bs); }

    int lane = threadIdx.x & 31;
    int warp = threadIdx.x >> 5;
    int wm = (warp & 1) * 64;
    int wn = (warp >> 1) * 64;
#pragma unroll
    for (int mt = 0; mt < 4; mt++)
#pragma unroll
        for (int half_ = 0; half_ < 2; half_++) {
            int r = bm + wm + mt * 16 + (lane >> 2) + half_ * 8;
#pragma unroll
            for (int nt = 0; nt < 8; nt++) {
                int c = bn + wn + nt * 8 + (lane & 3) * 2;
                float vx = acc[mt][nt][half_ * 2 + 0];
                float vy = acc[mt][nt][half_ * 2 + 1];
                if (d.CaddH) {
                    vx += __half2float(d.CaddH[(size_t)r * d.ldc + c]);
                    vy += __half2float(d.CaddH[(size_t)r * d.ldc + c + 1]);
                }
                if (d.C16) {
                    __half2 h;
                    h.x = __float2half_rn(vx);
                    h.y = __float2half_rn(vy);
                    *(__half2*)(d.C16 + (size_t)r * d.ldc + c) = h;
                } else {
                    float2 v; v.x = vx; v.y = vy;
                    *(float2*)(d.C32 + (size_t)r * d.ldc + c) = v;
                }
            }
        }
}

// ---------------- E-GEMM (fp16) with fused logit epilogue ----------------
__global__ __launch_bounds__(128) void gemm_logit16(const float* __restrict__ Rraw,
                                                    const int* __restrict__ sbj,
                                                    const int* __restrict__ obj) {
    extern __shared__ uint32_t sm16[];
    uint32_t* As = sm16;
    uint32_t* Bs = sm16 + 3 * STG32;
    int bm = blockIdx.y * 128;
    int bn = blockIdx.x * 128;

    float acc[4][8][4];
#pragma unroll
    for (int a = 0; a < 4; a++)
#pragma unroll
        for (int b = 0; b < 8; b++)
#pragma unroll
            for (int c = 0; c < 4; c++) acc[a][b][c] = 0.f;

    run_ml16(g_R16, g_Kt16, bm, bn, acc, As, Bs);

    int lane = threadIdx.x & 31;
    int warp = threadIdx.x >> 5;
    int wm = (warp & 1) * 64;
    int wn = (warp >> 1) * 64;
    const float scale = 0.03125f;

#pragma unroll
    for (int mt = 0; mt < 4; mt++) {
#pragma unroll
        for (int half_ = 0; half_ < 2; half_++) {
            int r = bm + wm + mt * 16 + (lane >> 2) + half_ * 8;
            int s = sbj[r], o = obj[r];
            const float* Rr  = Rraw + (size_t)r * DD;
            const float* S1r = g_S1 + (size_t)s * DD;
            const float* S2r = g_S2 + (size_t)o * DD;
            float part = 0.f;
#pragma unroll
            for (int nt = 0; nt < 8; nt++) {
                int c = bn + wn + nt * 8 + (lane & 3) * 2;
                float2 Rv  = *(const float2*)(Rr + c);
                float2 s1v = *(const float2*)(S1r + c);
                float2 s2v = *(const float2*)(S2r + c);
                part += (acc[mt][nt][half_ * 2 + 0] + s1v.x + s2v.x) * Rv.x;
                part += (acc[mt][nt][half_ * 2 + 1] + s1v.y + s2v.y) * Rv.y;
            }
            part += __shfl_xor_sync(0xFFFFFFFF, part, 1);
            part += __shfl_xor_sync(0xFFFFFFFF, part, 2);
            if ((lane & 3) == 0) {
                if (bn == 0 && wn == 0)
                    part += g_G[(size_t)s * NN + o] + g_d1[s] + g_d2[o];
                atomicAdd(&g_logits[r], part * scale);
            }
        }
    }
}

// ---------------- final vj GEMM (fp16) ----------------
__global__ __launch_bounds__(128) void gemm_vj16(const __half* __restrict__ WctxT,
                                                 const float* __restrict__ bias,
                                                 const float* __restrict__ vf,
                                                 float* __restrict__ out) {
    extern __shared__ uint32_t sm16[];
    uint32_t* As = sm16;
    uint32_t* Bs = sm16 + 3 * STG32;
    int bm = blockIdx.y * 128;
    int bn = blockIdx.x * 128;

    float acc[4][8][4];
#pragma unroll
    for (int a = 0; a < 4; a++)
#pragma unroll
        for (int b = 0; b < 8; b++)
#pragma unroll
            for (int c = 0; c < 4; c++) acc[a][b][c] = 0.f;

    run_ml16(g_ctx16, WctxT, bm, bn, acc, As, Bs);

    int lane = threadIdx.x & 31;
    int warp = threadIdx.x >> 5;
    int wm = (warp & 1) * 64;
    int wn = (warp >> 1) * 64;
#pragma unroll
    for (int mt = 0; mt < 4; mt++)
#pragma unroll
        for (int half_ = 0; half_ < 2; half_++) {
            int r = bm + wm + mt * 16 + (lane >> 2) + half_ * 8;
            bool inv = (g_degS[r] + g_degO[r]) > 0;
            const float* vfr = vf + (size_t)r * DD;
            float* outr = out + (size_t)r * DD;
#pragma unroll
            for (int nt = 0; nt < 8; nt++) {
                int c = bn + wn + nt * 8 + (lane & 3) * 2;
                float2 v;
                v.x = vfr[c]     + acc[mt][nt][half_ * 2 + 0] + (inv ? bias[c] : 0.f);
                v.y = vfr[c + 1] + acc[mt][nt][half_ * 2 + 1] + (inv ? bias[c + 1] : 0.f);
                *(float2*)(outr + c) = v;
            }
        }
}

// ---------------- conversion kernels ----------------
// passthrough fp32 + rounded fp16 copy of R
__global__ void k_copyround(const float* __restrict__ src, float* __restrict__ raw) {
    int i = blockIdx.x * 256 + threadIdx.x;   // float4 index (grid sized exactly)
    float4 v = ((const float4*)src)[i];
    ((float4*)raw)[i] = v;
    __half2 h0, h1;
    h0.x = __float2half_rn(v.x); h0.y = __float2half_rn(v.y);
    h1.x = __float2half_rn(v.z); h1.y = __float2half_rn(v.w);
    ((__half2*)g_R16)[2 * i] = h0;
    ((__half2*)g_R16)[2 * i + 1] = h1;
}
__global__ void k_roundh(const float* __restrict__ src, __half* __restrict__ dst, int n4) {
    int i = blockIdx.x * blockDim.x + threadIdx.x;
    if (i < n4) {
        float4 v = ((const float4*)src)[i];
        __half2 h0, h1;
        h0.x = __float2half_rn(v.x); h0.y = __float2half_rn(v.y);
        h1.x = __float2half_rn(v.z); h1.y = __float2half_rn(v.w);
        ((__half2*)dst)[2 * i] = h0;
        ((__half2*)dst)[2 * i + 1] = h1;
    }
}
// transpose + round: dst[n][k] = (half)src[k][n], DD x DD
struct TPair { const float* s; __half* d; };
struct TBatch { TPair p[5]; };
__global__ void k_troundh(TBatch tb) {
    __shared__ float t[32][33];
    TPair pr = tb.p[blockIdx.z];
    int x = blockIdx.x * 32 + threadIdx.x;       // n
    int y0 = blockIdx.y * 32 + threadIdx.y;      // k
#pragma unroll
    for (int j = 0; j < 4; j++)
        t[threadIdx.y + j * 8][threadIdx.x] = pr.s[(size_t)(y0 + j * 8) * DD + x];
    __syncthreads();
    int x2 = blockIdx.y * 32 + threadIdx.x;      // k
    int y2 = blockIdx.x * 32 + threadIdx.y;      // n
#pragma unroll
    for (int j = 0; j < 4; j++)
        pr.d[(size_t)(y2 + j * 8) * DD + x2] = __float2half_rn(t[threadIdx.x][threadIdx.y + j * 8]);
}

// ---------------- small kernels ----------------
__global__ void k_init() {
    int i = blockIdx.x * blockDim.x + threadIdx.x;
    if (i < NN * DD) g_ctx[i] = 0.f;
    if (i < EE) g_logits[i] = 0.f;
    if (i < NN) {
        g_sumS[i] = 0.f; g_sumO[i] = 0.f;
        g_maxS[i] = 0u; g_maxO[i] = 0u;
        g_degS[i] = 0; g_degO[i] = 0;
    }
}
__global__ void k_hist(const int* __restrict__ sbj, const int* __restrict__ obj) {
    int e = blockIdx.x * blockDim.x + threadIdx.x;
    if (e < EE) { atomicAdd(&g_degS[sbj[e]], 1); atomicAdd(&g_degO[obj[e]], 1); }
}
__global__ void k_scan() {
    if (threadIdx.x == 0) {
        int s = 0, o = 0;
        for (int n = 0; n < NN; n++) {
            g_baseS[n] = s; s += g_degS[n];
            g_baseO[n] = o; g_curO[n] = o; o += g_degO[n];
        }
    }
}
__global__ void k_scatter(const int* __restrict__ obj) {
    int e = blockIdx.x * blockDim.x + threadIdx.x;
    if (e < EE) { int p = atomicAdd(&g_curO[obj[e]], 1); g_permO[p] = e; }
}
__global__ void k_vecs1(const float* __restrict__ b_rel, const float* __restrict__ b_sbj,
                        const float* __restrict__ b_obj, const float* __restrict__ Ws_r,
                        const float* __restrict__ Wo_r) {
    int j = blockIdx.x * blockDim.x + threadIdx.x;
    if (j >= DD) return;
    float s = 0.f, o = 0.f;
    for (int i = 0; i < DD; i++) {
        float br = b_rel[i];
        s += br * Ws_r[(size_t)i * DD + j];
        o += br * Wo_r[(size_t)i * DD + j];
    }
    g_cs[j] = s + b_sbj[j];
    g_co[j] = o + b_obj[j];
}
// c3[j] = sum_i cs[i]*Ho[j,i] + co[i]*Hs[j,i]  (Hs/Ho now fp16)
__global__ void k_c3() {
    int j = blockIdx.x * 8 + (threadIdx.x >> 5);
    int lane = threadIdx.x & 31;
    if (j >= DD) return;
    float a = 0.f;
    for (int i = lane; i < DD; i += 32)
        a += g_cs[i] * __half2float(g_Ho16[(size_t)j * DD + i])
           + g_co[i] * __half2float(g_Hs16[(size_t)j * DD + i]);
#pragma unroll
    for (int off = 16; off > 0; off >>= 1) a += __shfl_xor_sync(0xFFFFFFFF, a, off);
    if (lane == 0) g_c3[j] = a;
}
__global__ void k_addc3() {
    int i = blockIdx.x * blockDim.x + threadIdx.x;
    if (i < NN * DD) g_S1[i] += g_c3[i & (DD - 1)];
}
__global__ void k_scal() {
    int n = blockIdx.x * 8 + (threadIdx.x >> 5);
    int lane = threadIdx.x & 31;
    if (n >= NN) return;
    const __half* Ts = g_T16 + 0 * NN * DD + (size_t)n * DD;
    const __half* Us = g_T16 + 1 * NN * DD + (size_t)n * DD;
    const __half* To = g_T16 + 2 * NN * DD + (size_t)n * DD;
    const __half* Uo = g_T16 + 3 * NN * DD + (size_t)n * DD;
    float t1 = 0.f, t2 = 0.f, t3 = 0.f;
    for (int c = lane; c < DD; c += 32) {
        float cs = g_cs[c], co = g_co[c];
        t1 += (__half2float(Ts[c]) + cs) * (__half2float(Uo[c]) + co);
        t2 += (__half2float(Us[c]) + cs) * (__half2float(To[c]) + co);
        t3 += cs * co;
    }
#pragma unroll
    for (int off = 16; off > 0; off >>= 1) {
        t1 += __shfl_xor_sync(0xFFFFFFFF, t1, off);
        t2 += __shfl_xor_sync(0xFFFFFFFF, t2, off);
        t3 += __shfl_xor_sync(0xFFFFFFFF, t3, off);
    }
    if (lane == 0) { g_d1[n] = t1; g_d2[n] = t2 - t3; }
}
__global__ void k_max(const int* __restrict__ sbj, const int* __restrict__ obj) {
    int e = blockIdx.x * blockDim.x + threadIdx.x;
    if (e < EE) {
        unsigned k = fkey(g_logits[e]);
        atomicMax(&g_maxS[sbj[e]], k);
        atomicMax(&g_maxO[obj[e]], k);
    }
}
__global__ void k_exp(const int* __restrict__ sbj, const int* __restrict__ obj) {
    int e = blockIdx.x * blockDim.x + threadIdx.x;
    if (e < EE) {
        float l = g_logits[e];
        float es = expf(l - funkey(g_maxS[sbj[e]]));
        float eo = expf(l - funkey(g_maxO[obj[e]]));
        g_wS[e] = es; g_wO[e] = eo;
        atomicAdd(&g_sumS[sbj[e]], es);
        atomicAdd(&g_sumO[obj[e]], eo);
    }
}
__global__ void k_ctxS(const int* __restrict__ obj, const float* __restrict__ vf) {
    int n = blockIdx.x, t = threadIdx.x;
    int beg = g_baseS[n], cnt = g_degS[n];
    if (cnt == 0) return;
    float inv = 1.f / g_sumS[n];
    const float4* vf4 = (const float4*)vf;
    float4 acc = make_float4(0.f, 0.f, 0.f, 0.f);
    for (int i = 0; i < cnt; i++) {
        int e = beg + i;
        float w = g_wS[e];
        float4 v = vf4[(size_t)obj[e] * 256 + t];
        acc.x += w * v.x; acc.y += w * v.y; acc.z += w * v.z; acc.w += w * v.w;
    }
    acc.x *= inv; acc.y *= inv; acc.z *= inv; acc.w *= inv;
    ((float4*)g_ctx)[(size_t)n * 256 + t] = acc;
}
// finalizes ALL rows; converts ctx to fp16 for gemm_vj16
__global__ void k_ctxO(const int* __restrict__ sbj, const float* __restrict__ vf) {
    int n = blockIdx.x, t = threadIdx.x;
    int beg = g_baseO[n], cnt = g_degO[n];
    float4* c4 = (float4*)g_ctx;
    float4 old = c4[(size_t)n * 256 + t];
    if (cnt > 0) {
        float inv = 1.f / g_sumO[n];
        const float4* vf4 = (const float4*)vf;
        float4 acc = make_float4(0.f, 0.f, 0.f, 0.f);
        for (int i = 0; i < cnt; i++) {
            int e = g_permO[beg + i];
            float w = g_wO[e];
            float4 v = vf4[(size_t)sbj[e] * 256 + t];
            acc.x += w * v.x; acc.y += w * v.y; acc.z += w * v.z; acc.w += w * v.w;
        }
        old.x += acc.x * inv; old.y += acc.y * inv; old.z += acc.z * inv; old.w += acc.w * inv;
    }
    __half2 h0, h1;
    h0.x = __float2half_rn(old.x); h0.y = __float2half_rn(old.y);
    h1.x = __float2half_rn(old.z); h1.y = __float2half_rn(old.w);
    ((__half2*)g_ctx16)[(size_t)n * 512 + 2 * t]     = h0;
    ((__half2*)g_ctx16)[(size_t)n * 512 + 2 * t + 1] = h1;
}

// ---------------- launch ----------------
extern "C" void kernel_launch(void* const* d_in, const int* in_sizes, int n_in,
                              void* d_out, int out_size) {
    const float* vf    = (const float*)d_in[0];
    const float* R     = (const float*)d_in[1];
    const float* W_rel = (const float*)d_in[2];
    const float* b_rel = (const float*)d_in[3];
    const float* W_sbj = (const float*)d_in[4];
    const float* b_sbj = (const float*)d_in[5];
    const float* W_obj = (const float*)d_in[6];
    const float* b_obj = (const float*)d_in[7];
    const float* W_ctx = (const float*)d_in[8];
    const float* b_ctx = (const float*)d_in[9];
    const int* sbj     = (const int*)d_in[10];
    const int* obj     = (const int*)d_in[11];
    float* out = (float*)d_out;

    cudaFuncSetAttribute(gemm_multi,   cudaFuncAttributeMaxDynamicSharedMemorySize, SMEM16_BYTES);
    cudaFuncSetAttribute(gemm_logit16, cudaFuncAttributeMaxDynamicSharedMemorySize, SMEM16_BYTES);
    cudaFuncSetAttribute(gemm_vj16,    cudaFuncAttributeMaxDynamicSharedMemorySize, SMEM16_BYTES);

    __half *pHs, *pHo, *pKt, *pMT, *pT, *pWr, *pWT, *pVf;
    cudaGetSymbolAddress((void**)&pHs, g_Hs16);
    cudaGetSymbolAddress((void**)&pHo, g_Ho16);
    cudaGetSymbolAddress((void**)&pKt, g_Kt16);
    cudaGetSymbolAddress((void**)&pMT, g_MT16);
    cudaGetSymbolAddress((void**)&pT,  g_T16);
    cudaGetSymbolAddress((void**)&pWr, g_Wr16);
    cudaGetSymbolAddress((void**)&pWT, g_WT16);
    cudaGetSymbolAddress((void**)&pVf, g_vf16);
    float *pS1, *pS2, *pG;
    cudaGetSymbolAddress((void**)&pS1, g_S1);
    cudaGetSymbolAddress((void**)&pS2, g_S2);
    cudaGetSymbolAddress((void**)&pG,  g_G);

    // fp16 weights (straight): Wr_s, Wr_o, Wr_r
    const __half* hWr_s = pWr + 0 * (size_t)DD * DD;
    const __half* hWr_o = pWr + 1 * (size_t)DD * DD;
    const __half* hWr_r = pWr + 2 * (size_t)DD * DD;
    // fp16 weights (transposed): Ws_rT, Wo_rT, WctxT, Ws_vT, Wo_vT
    __half* hWs_rT = pWT + 0 * (size_t)DD * DD;
    __half* hWo_rT = pWT + 1 * (size_t)DD * DD;
    __half* hWctxT = pWT + 2 * (size_t)DD * DD;
    __half* hWs_vT = pWT + 3 * (size_t)DD * DD;
    __half* hWo_vT = pWT + 4 * (size_t)DD * DD;

    const float* Ws_v = W_sbj;
    const float* Ws_r = W_sbj + (size_t)DD * DD;
    const float* Wo_v = W_obj;
    const float* Wo_r = W_obj + (size_t)DD * DD;

    // passthrough + fp16 copy of R
    k_copyround<<<EE * DD / 4 / 256, 256>>>(R, out);

    k_init<<<(NN * DD + 255) / 256, 256>>>();
    k_hist<<<(EE + 255) / 256, 256>>>(sbj, obj);
    k_scan<<<1, 32>>>();
    k_scatter<<<(EE + 255) / 256, 256>>>(obj);
    k_vecs1<<<4, 256>>>(b_rel, b_sbj, b_obj, Ws_r, Wo_r);

    // straight rounds
    k_roundh<<<(3 * DD * DD / 4 + 255) / 256, 256>>>(W_rel, pWr, 3 * DD * DD / 4);
    k_roundh<<<(NN * DD / 4 + 255) / 256, 256>>>(vf, pVf, NN * DD / 4);
    // transposed rounds
    {
        TBatch tb{};
        tb.p[0] = {Ws_r,  hWs_rT};
        tb.p[1] = {Wo_r,  hWo_rT};
        tb.p[2] = {W_ctx, hWctxT};
        tb.p[3] = {Ws_v,  hWs_vT};
        tb.p[4] = {Wo_v,  hWo_vT};
        k_troundh<<<dim3(32, 32, 5), dim3(32, 8)>>>(tb);
    }

    // L1: Hs, Ho, M1T..M4T   (all DD x DD, NT form)
    {
        Batch b{};
        b.d[0] = {hWr_r,  hWs_rT, nullptr, nullptr, nullptr, nullptr, pHs,                        DD, DD, DD, 0};
        b.d[1] = {hWr_r,  hWo_rT, nullptr, nullptr, nullptr, nullptr, pHo,                        DD, DD, DD, 0};
        b.d[2] = {hWs_rT, hWr_s,  nullptr, nullptr, hWs_vT,  nullptr, pMT + 0 * (size_t)DD * DD,  DD, DD, DD, 0};
        b.d[3] = {hWs_rT, hWr_o,  nullptr, nullptr, nullptr, nullptr, pMT + 1 * (size_t)DD * DD,  DD, DD, DD, 0};
        b.d[4] = {hWo_rT, hWr_o,  nullptr, nullptr, hWo_vT,  nullptr, pMT + 2 * (size_t)DD * DD,  DD, DD, DD, 0};
        b.d[5] = {hWo_rT, hWr_s,  nullptr, nullptr, nullptr, nullptr, pMT + 3 * (size_t)DD * DD,  DD, DD, DD, 0};
        gemm_multi<<<dim3(8, 8, 6), 128, SMEM16_BYTES>>>(b);
    }
    // L2: T_z = vf16 @ M_zT^T (z=0..3, M=768), Kt = Ho @ Hs^T
    {
        Batch b{};
        for (int z = 0; z < 4; z++)
            b.d[z] = {pVf, pMT + (size_t)z * DD * DD, nullptr, nullptr, nullptr, nullptr,
                      pT + (size_t)z * NN * DD, NN, DD, DD, 0};
        b.d[4] = {pHo, pHs, nullptr, nullptr, nullptr, nullptr, pKt, DD, DD, DD, 0};
        gemm_multi<<<dim3(8, 8, 5), 128, SMEM16_BYTES>>>(b);
    }
    // L3: S1, S2, G (fp32 outputs)
    {
        Batch b{};
        b.d[0] = {pT + 0 * (size_t)NN * DD, pHo, pT + 3 * (size_t)NN * DD, pHs, nullptr, pS1, nullptr,
                  NN, DD, DD, 1};
        b.d[1] = {pT + 1 * (size_t)NN * DD, pHo, pT + 2 * (size_t)NN * DD, pHs, nullptr, pS2, nullptr,
                  NN, DD, DD, 1};
        b.d[2] = {pT + 0 * (size_t)NN * DD, pT + 2 * (size_t)NN * DD,
                  pT + 3 * (size_t)NN * DD, pT + 1 * (size_t)NN * DD, nullptr, pG, nullptr,
                  NN, NN, NN, 1};
        gemm_multi<<<dim3(8, 6, 3), 128, SMEM16_BYTES>>>(b);
    }
    k_c3<<<128, 256>>>();
    k_addc3<<<(NN * DD + 255) / 256, 256>>>();
    k_scal<<<96, 256>>>();

    gemm_logit16<<<dim3(8, 192), 128, SMEM16_BYTES>>>(R, sbj, obj);

    k_max<<<(EE + 255) / 256, 256>>>(sbj, obj);
    k_exp<<<(EE + 255) / 256, 256>>>(sbj, obj);
    k_ctxS<<<NN, 256>>>(obj, vf);
    k_ctxO<<<NN, 256>>>(sbj, vf);

    gemm_vj16<<<dim3(8, 6), 128, SMEM16_BYTES>>>(hWctxT, b_ctx, vf, out + (size_t)EE * DD);

    (void)in_sizes; (void)n_in; (void)out_size;
}

// round 12
// speedup vs baseline: 1.7068x; 1.0523x over previous
#include <cuda_runtime.h>
#include <cuda_fp16.h>
#include <math.h>
#include <cstdint>

#define NN 768
#define EE 24576
#define DD 1024

// ---------------- fp16 GEMM operand scratch (all [x][1024] K-major) ----------------
__device__ __align__(128) __half g_Hs16[DD * DD];
__device__ __align__(128) __half g_Ho16[DD * DD];
__device__ __align__(128) __half g_Kt16[DD * DD];         // Kt[n,k] = K[k,n]
__device__ __align__(128) __half g_MT16[4 * DD * DD];     // M1T..M4T
__device__ __align__(128) __half g_T16 [4 * NN * DD];     // Ts,Us,To,Uo
__device__ __align__(128) __half g_Wr16[3 * DD * DD];     // Wr_s, Wr_o, Wr_r (straight round)
__device__ __align__(128) __half g_WT16[5 * DD * DD];     // Ws_rT, Wo_rT, WctxT, Ws_vT, Wo_vT
__device__ __align__(128) __half g_vf16[NN * DD];
__device__ __align__(128) __half g_R16 [(size_t)EE * DD];
__device__ __align__(128) __half g_ctx16[NN * DD];
// ---------------- fp32 scratch ----------------
__device__ __align__(128) float g_S1[NN * DD];
__device__ __align__(128) float g_S2[NN * DD];
__device__ __align__(128) float g_G [NN * NN];
__device__ __align__(128) float g_ctx[NN * DD];
__device__ float g_cs[DD], g_co[DD], g_c3[DD];
__device__ float g_d1[NN], g_d2[NN];
__device__ __align__(128) float g_logits[EE];
__device__ __align__(128) float g_wS[EE];
__device__ __align__(128) float g_wO[EE];
__device__ unsigned g_maxS[NN], g_maxO[NN];
__device__ float g_sumS[NN], g_sumO[NN];
__device__ int g_degS[NN], g_degO[NN], g_baseS[NN], g_baseO[NN], g_curO[NN];
__device__ int g_permO[EE];

// fp16 pipeline: per stage A tile 128 rows x 20 u32 (32 halves + pad), same for B
#define STR32 20
#define STG32 (128 * STR32)            // 2560 u32 per tile
#define SMEM16_BYTES (3 * 2 * STG32 * 4)  // 61440 B

// ---------------- helpers ----------------
__device__ __forceinline__ void mma16(float c[4], unsigned a0, unsigned a1, unsigned a2, unsigned a3,
                                      unsigned b0, unsigned b1) {
    asm volatile(
        "mma.sync.aligned.m16n8k16.row.col.f32.f16.f16.f32 "
        "{%0,%1,%2,%3},{%4,%5,%6,%7},{%8,%9},{%0,%1,%2,%3};"
        : "+f"(c[0]), "+f"(c[1]), "+f"(c[2]), "+f"(c[3])
        : "r"(a0), "r"(a1), "r"(a2), "r"(a3), "r"(b0), "r"(b1));
}
__device__ __forceinline__ void cpa16p(void* s, const void* g) {
    unsigned sa = (unsigned)__cvta_generic_to_shared(s);
    asm volatile("cp.async.cg.shared.global [%0], [%1], 16;" :: "r"(sa), "l"(g));
}
__device__ __forceinline__ void cpa_commit() { asm volatile("cp.async.commit_group;"); }
template<int N> __device__ __forceinline__ void cpa_wait() { asm volatile("cp.async.wait_group %0;" :: "n"(N)); }

__device__ __forceinline__ unsigned fkey(float f) {
    unsigned u = __float_as_uint(f);
    return (u & 0x80000000u) ? ~u : (u | 0x80000000u);
}
__device__ __forceinline__ float funkey(unsigned k) {
    return (k & 0x80000000u) ? __uint_as_float(k ^ 0x80000000u) : __uint_as_float(~k);
}

// ---------------- fp16 NT mainloop ----------------
// C[m,n] = sum_k A[m,k] * B[n,k], K=1024, BK=32, 3-stage cp.async, one sync/slab.
// 128x128 CTA tile, 4 warps, 64x64 warp tiles, m16n8k16.
__device__ __forceinline__ void run_ml16(const __half* __restrict__ A,
                                         const __half* __restrict__ B,
                                         int bm, int bn,
                                         float (&acc)[4][8][4],
                                         uint32_t* __restrict__ As,
                                         uint32_t* __restrict__ Bs) {
    int tid = threadIdx.x;
    int lane = tid & 31;
    int warp = tid >> 5;
    int wm = (warp & 1) * 64;
    int wn = (warp >> 1) * 64;
    int g = lane >> 2;
    int t4 = lane & 3;

    auto issue = [&](int s) {
        int stg = s % 3;
        uint32_t* as = As + stg * STG32;
        uint32_t* bs = Bs + stg * STG32;
#pragma unroll
        for (int p = 0; p < 4; p++) {
            int idx = p * 128 + tid;
            int row = idx >> 2;
            int c4 = idx & 3;
            cpa16p(as + row * STR32 + c4 * 4, A + (size_t)(bm + row) * DD + s * 32 + c4 * 8);
        }
#pragma unroll
        for (int p = 0; p < 4; p++) {
            int idx = p * 128 + tid;
            int row = idx >> 2;
            int c4 = idx & 3;
            cpa16p(bs + row * STR32 + c4 * 4, B + (size_t)(bn + row) * DD + s * 32 + c4 * 8);
        }
        cpa_commit();
    };

    issue(0);
    issue(1);
    for (int kt = 0; kt < 32; kt++) {
        cpa_wait<1>();
        __syncthreads();
        const uint32_t* as = As + (kt % 3) * STG32;
        const uint32_t* bs = Bs + (kt % 3) * STG32;
#pragma unroll
        for (int kk = 0; kk < 2; kk++) {
            int kb = kk * 8 + t4;
            unsigned af[4][4], bf[8][2];
#pragma unroll
            for (int mt = 0; mt < 4; mt++) {
                int r = wm + mt * 16 + g;
                af[mt][0] = as[r * STR32 + kb];
                af[mt][1] = as[(r + 8) * STR32 + kb];
                af[mt][2] = as[r * STR32 + kb + 4];
                af[mt][3] = as[(r + 8) * STR32 + kb + 4];
            }
#pragma unroll
            for (int nt = 0; nt < 8; nt++) {
                int cc = wn + nt * 8 + g;
                bf[nt][0] = bs[cc * STR32 + kb];
                bf[nt][1] = bs[cc * STR32 + kb + 4];
            }
#pragma unroll
            for (int mt = 0; mt < 4; mt++)
#pragma unroll
                for (int nt = 0; nt < 8; nt++)
                    mma16(acc[mt][nt], af[mt][0], af[mt][1], af[mt][2], af[mt][3],
                          bf[nt][0], bf[nt][1]);
        }
        if (kt + 2 < 32) issue(kt + 2);
    }
}

// ---------------- generalized batched NT GEMM ----------------
struct Desc {
    const __half* A; const __half* B; const __half* A2; const __half* B2;
    const __half* CaddH;          // optional half addend [m][n]
    float* C32; __half* C16;      // exactly one non-null
    int M; int N; int ldc; int dual;
};
struct Batch { Desc d[6]; };

__global__ __launch_bounds__(128) void gemm_multi(Batch p) {
    Desc d = p.d[blockIdx.z];
    int bm = blockIdx.y * 128;
    int bn = blockIdx.x * 128;
    if (bm >= d.M || bn >= d.N) return;

    extern __shared__ uint32_t sm16[];
    uint32_t* As = sm16;
    uint32_t* Bs = sm16 + 3 * STG32;

    float acc[4][8][4];
#pragma unroll
    for (int a = 0; a < 4; a++)
#pragma unroll
        for (int b = 0; b < 8; b++)
#pragma unroll
            for (int c = 0; c < 4; c++) acc[a][b][c] = 0.f;

    run_ml16(d.A, d.B, bm, bn, acc, As, Bs);
    if (d.dual) { __syncthreads(); run_ml16(d.A2, d.B2, bm, bn, acc, As, Bs); }

    int lane = threadIdx.x & 31;
    int warp = threadIdx.x >> 5;
    int wm = (warp & 1) * 64;
    int wn = (warp >> 1) * 64;
#pragma unroll
    for (int mt = 0; mt < 4; mt++)
#pragma unroll
        for (int half_ = 0; half_ < 2; half_++) {
            int r = bm + wm + mt * 16 + (lane >> 2) + half_ * 8;
#pragma unroll
            for (int nt = 0; nt < 8; nt++) {
                int c = bn + wn + nt * 8 + (lane & 3) * 2;
                float vx = acc[mt][nt][half_ * 2 + 0];
                float vy = acc[mt][nt][half_ * 2 + 1];
                if (d.CaddH) {
                    vx += __half2float(d.CaddH[(size_t)r * d.ldc + c]);
                    vy += __half2float(d.CaddH[(size_t)r * d.ldc + c + 1]);
                }
                if (d.C16) {
                    __half2 h;
                    h.x = __float2half_rn(vx);
                    h.y = __float2half_rn(vy);
                    *(__half2*)(d.C16 + (size_t)r * d.ldc + c) = h;
                } else {
                    float2 v; v.x = vx; v.y = vy;
                    *(float2*)(d.C32 + (size_t)r * d.ldc + c) = v;
                }
            }
        }
}

// ---------------- E-GEMM (fp16) with fused logit epilogue ----------------
__global__ __launch_bounds__(128) void gemm_logit16(const float* __restrict__ Rraw,
                                                    const int* __restrict__ sbj,
                                                    const int* __restrict__ obj) {
    extern __shared__ uint32_t sm16[];
    uint32_t* As = sm16;
    uint32_t* Bs = sm16 + 3 * STG32;
    int bm = blockIdx.y * 128;
    int bn = blockIdx.x * 128;

    float acc[4][8][4];
#pragma unroll
    for (int a = 0; a < 4; a++)
#pragma unroll
        for (int b = 0; b < 8; b++)
#pragma unroll
            for (int c = 0; c < 4; c++) acc[a][b][c] = 0.f;

    run_ml16(g_R16, g_Kt16, bm, bn, acc, As, Bs);

    int lane = threadIdx.x & 31;
    int warp = threadIdx.x >> 5;
    int wm = (warp & 1) * 64;
    int wn = (warp >> 1) * 64;
    const float scale = 0.03125f;

#pragma unroll
    for (int mt = 0; mt < 4; mt++) {
#pragma unroll
        for (int half_ = 0; half_ < 2; half_++) {
            int r = bm + wm + mt * 16 + (lane >> 2) + half_ * 8;
            int s = sbj[r], o = obj[r];
            const float* Rr  = Rraw + (size_t)r * DD;
            const float* S1r = g_S1 + (size_t)s * DD;
            const float* S2r = g_S2 + (size_t)o * DD;
            float part = 0.f;
#pragma unroll
            for (int nt = 0; nt < 8; nt++) {
                int c = bn + wn + nt * 8 + (lane & 3) * 2;
                float2 Rv  = *(const float2*)(Rr + c);
                float2 s1v = *(const float2*)(S1r + c);
                float2 s2v = *(const float2*)(S2r + c);
                part += (acc[mt][nt][half_ * 2 + 0] + s1v.x + s2v.x) * Rv.x;
                part += (acc[mt][nt][half_ * 2 + 1] + s1v.y + s2v.y) * Rv.y;
            }
            part += __shfl_xor_sync(0xFFFFFFFF, part, 1);
            part += __shfl_xor_sync(0xFFFFFFFF, part, 2);
            if ((lane & 3) == 0) {
                if (bn == 0 && wn == 0)
                    part += g_G[(size_t)s * NN + o] + g_d1[s] + g_d2[o];
                atomicAdd(&g_logits[r], part * scale);
            }
        }
    }
}

// ---------------- final vj GEMM (fp16) ----------------
__global__ __launch_bounds__(128) void gemm_vj16(const __half* __restrict__ WctxT,
                                                 const float* __restrict__ bias,
                                                 const float* __restrict__ vf,
                                                 float* __restrict__ out) {
    extern __shared__ uint32_t sm16[];
    uint32_t* As = sm16;
    uint32_t* Bs = sm16 + 3 * STG32;
    int bm = blockIdx.y * 128;
    int bn = blockIdx.x * 128;

    float acc[4][8][4];
#pragma unroll
    for (int a = 0; a < 4; a++)
#pragma unroll
        for (int b = 0; b < 8; b++)
#pragma unroll
            for (int c = 0; c < 4; c++) acc[a][b][c] = 0.f;

    run_ml16(g_ctx16, WctxT, bm, bn, acc, As, Bs);

    int lane = threadIdx.x & 31;
    int warp = threadIdx.x >> 5;
    int wm = (warp & 1) * 64;
    int wn = (warp >> 1) * 64;
#pragma unroll
    for (int mt = 0; mt < 4; mt++)
#pragma unroll
        for (int half_ = 0; half_ < 2; half_++) {
            int r = bm + wm + mt * 16 + (lane >> 2) + half_ * 8;
            bool inv = (g_degS[r] + g_degO[r]) > 0;
            const float* vfr = vf + (size_t)r * DD;
            float* outr = out + (size_t)r * DD;
#pragma unroll
            for (int nt = 0; nt < 8; nt++) {
                int c = bn + wn + nt * 8 + (lane & 3) * 2;
                float2 v;
                v.x = vfr[c]     + acc[mt][nt][half_ * 2 + 0] + (inv ? bias[c] : 0.f);
                v.y = vfr[c + 1] + acc[mt][nt][half_ * 2 + 1] + (inv ? bias[c + 1] : 0.f);
                *(float2*)(outr + c) = v;
            }
        }
}

// ---------------- conversion kernels ----------------
// passthrough fp32 + rounded fp16 copy of R
__global__ void k_copyround(const float* __restrict__ src, float* __restrict__ raw) {
    int i = blockIdx.x * 256 + threadIdx.x;   // float4 index (grid sized exactly)
    float4 v = ((const float4*)src)[i];
    ((float4*)raw)[i] = v;
    __half2 h0, h1;
    h0.x = __float2half_rn(v.x); h0.y = __float2half_rn(v.y);
    h1.x = __float2half_rn(v.z); h1.y = __float2half_rn(v.w);
    ((__half2*)g_R16)[2 * i] = h0;
    ((__half2*)g_R16)[2 * i + 1] = h1;
}
__global__ void k_roundh(const float* __restrict__ src, __half* __restrict__ dst, int n4) {
    int i = blockIdx.x * blockDim.x + threadIdx.x;
    if (i < n4) {
        float4 v = ((const float4*)src)[i];
        __half2 h0, h1;
        h0.x = __float2half_rn(v.x); h0.y = __float2half_rn(v.y);
        h1.x = __float2half_rn(v.z); h1.y = __float2half_rn(v.w);
        ((__half2*)dst)[2 * i] = h0;
        ((__half2*)dst)[2 * i + 1] = h1;
    }
}
// transpose + round: dst[n][k] = (half)src[k][n], DD x DD
struct TPair { const float* s; __half* d; };
struct TBatch { TPair p[5]; };
__global__ void k_troundh(TBatch tb) {
    __shared__ float t[32][33];
    TPair pr = tb.p[blockIdx.z];
    int x = blockIdx.x * 32 + threadIdx.x;       // n
    int y0 = blockIdx.y * 32 + threadIdx.y;      // k
#pragma unroll
    for (int j = 0; j < 4; j++)
        t[threadIdx.y + j * 8][threadIdx.x] = pr.s[(size_t)(y0 + j * 8) * DD + x];
    __syncthreads();
    int x2 = blockIdx.y * 32 + threadIdx.x;      // k
    int y2 = blockIdx.x * 32 + threadIdx.y;      // n
#pragma unroll
    for (int j = 0; j < 4; j++)
        pr.d[(size_t)(y2 + j * 8) * DD + x2] = __float2half_rn(t[threadIdx.x][threadIdx.y + j * 8]);
}

// ---------------- small kernels ----------------
__global__ void k_init() {
    int i = blockIdx.x * blockDim.x + threadIdx.x;
    if (i < NN * DD) g_ctx[i] = 0.f;
    if (i < EE) g_logits[i] = 0.f;
    if (i < NN) {
        g_sumS[i] = 0.f; g_sumO[i] = 0.f;
        g_maxS[i] = 0u; g_maxO[i] = 0u;
        g_degS[i] = 0; g_degO[i] = 0;
    }
}
__global__ void k_hist(const int* __restrict__ sbj, const int* __restrict__ obj) {
    int e = blockIdx.x * blockDim.x + threadIdx.x;
    if (e < EE) { atomicAdd(&g_degS[sbj[e]], 1); atomicAdd(&g_degO[obj[e]], 1); }
}
// parallel exclusive scan over 768 elements (one block of 768 threads) — integer, deterministic
__global__ void k_scan() {
    __shared__ int wsumS[24], wsumO[24];
    int t = threadIdx.x;              // 0..767
    int lane = t & 31, warp = t >> 5; // 24 warps
    int dS = g_degS[t], dO = g_degO[t];
    int iS = dS, iO = dO;
#pragma unroll
    for (int off = 1; off < 32; off <<= 1) {
        int vS = __shfl_up_sync(0xFFFFFFFF, iS, off);
        int vO = __shfl_up_sync(0xFFFFFFFF, iO, off);
        if (lane >= off) { iS += vS; iO += vO; }
    }
    if (lane == 31) { wsumS[warp] = iS; wsumO[warp] = iO; }
    __syncthreads();
    if (warp == 0 && lane < 24) {
        int sS = wsumS[lane], sO = wsumO[lane];
#pragma unroll
        for (int off = 1; off < 32; off <<= 1) {
            int vS = __shfl_up_sync(0x00FFFFFF, sS, off);
            int vO = __shfl_up_sync(0x00FFFFFF, sO, off);
            if (lane >= off) { sS += vS; sO += vO; }
        }
        wsumS[lane] = sS; wsumO[lane] = sO;
    }
    __syncthreads();
    int offS = (warp > 0) ? wsumS[warp - 1] : 0;
    int offO = (warp > 0) ? wsumO[warp - 1] : 0;
    g_baseS[t] = offS + iS - dS;
    g_baseO[t] = offO + iO - dO;
    g_curO[t]  = offO + iO - dO;
}
__global__ void k_scatter(const int* __restrict__ obj) {
    int e = blockIdx.x * blockDim.x + threadIdx.x;
    if (e < EE) { int p = atomicAdd(&g_curO[obj[e]], 1); g_permO[p] = e; }
}
__global__ void k_vecs1(const float* __restrict__ b_rel, const float* __restrict__ b_sbj,
                        const float* __restrict__ b_obj, const float* __restrict__ Ws_r,
                        const float* __restrict__ Wo_r) {
    int j = blockIdx.x * blockDim.x + threadIdx.x;
    if (j >= DD) return;
    float s = 0.f, o = 0.f;
    for (int i = 0; i < DD; i++) {
        float br = b_rel[i];
        s += br * Ws_r[(size_t)i * DD + j];
        o += br * Wo_r[(size_t)i * DD + j];
    }
    g_cs[j] = s + b_sbj[j];
    g_co[j] = o + b_obj[j];
}
// c3[j] = sum_i cs[i]*Ho[j,i] + co[i]*Hs[j,i]  (Hs/Ho fp16)
__global__ void k_c3() {
    int j = blockIdx.x * 8 + (threadIdx.x >> 5);
    int lane = threadIdx.x & 31;
    if (j >= DD) return;
    float a = 0.f;
    for (int i = lane; i < DD; i += 32)
        a += g_cs[i] * __half2float(g_Ho16[(size_t)j * DD + i])
           + g_co[i] * __half2float(g_Hs16[(size_t)j * DD + i]);
#pragma unroll
    for (int off = 16; off > 0; off >>= 1) a += __shfl_xor_sync(0xFFFFFFFF, a, off);
    if (lane == 0) g_c3[j] = a;
}
__global__ void k_addc3() {
    int i = blockIdx.x * blockDim.x + threadIdx.x;
    if (i < NN * DD) g_S1[i] += g_c3[i & (DD - 1)];
}
__global__ void k_scal() {
    int n = blockIdx.x * 8 + (threadIdx.x >> 5);
    int lane = threadIdx.x & 31;
    if (n >= NN) return;
    const __half* Ts = g_T16 + 0 * NN * DD + (size_t)n * DD;
    const __half* Us = g_T16 + 1 * NN * DD + (size_t)n * DD;
    const __half* To = g_T16 + 2 * NN * DD + (size_t)n * DD;
    const __half* Uo = g_T16 + 3 * NN * DD + (size_t)n * DD;
    float t1 = 0.f, t2 = 0.f, t3 = 0.f;
    for (int c = lane; c < DD; c += 32) {
        float cs = g_cs[c], co = g_co[c];
        t1 += (__half2float(Ts[c]) + cs) * (__half2float(Uo[c]) + co);
        t2 += (__half2float(Us[c]) + cs) * (__half2float(To[c]) + co);
        t3 += cs * co;
    }
#pragma unroll
    for (int off = 16; off > 0; off >>= 1) {
        t1 += __shfl_xor_sync(0xFFFFFFFF, t1, off);
        t2 += __shfl_xor_sync(0xFFFFFFFF, t2, off);
        t3 += __shfl_xor_sync(0xFFFFFFFF, t3, off);
    }
    if (lane == 0) { g_d1[n] = t1; g_d2[n] = t2 - t3; }
}
__global__ void k_max(const int* __restrict__ sbj, const int* __restrict__ obj) {
    int e = blockIdx.x * blockDim.x + threadIdx.x;
    if (e < EE) {
        unsigned k = fkey(g_logits[e]);
        atomicMax(&g_maxS[sbj[e]], k);
        atomicMax(&g_maxO[obj[e]], k);
    }
}
__global__ void k_exp(const int* __restrict__ sbj, const int* __restrict__ obj) {
    int e = blockIdx.x * blockDim.x + threadIdx.x;
    if (e < EE) {
        float l = g_logits[e];
        float es = expf(l - funkey(g_maxS[sbj[e]]));
        float eo = expf(l - funkey(g_maxO[obj[e]]));
        g_wS[e] = es; g_wO[e] = eo;
        atomicAdd(&g_sumS[sbj[e]], es);
        atomicAdd(&g_sumO[obj[e]], eo);
    }
}
__global__ void k_ctxS(const int* __restrict__ obj, const float* __restrict__ vf) {
    int n = blockIdx.x, t = threadIdx.x;
    int beg = g_baseS[n], cnt = g_degS[n];
    if (cnt == 0) return;
    float inv = 1.f / g_sumS[n];
    const float4* vf4 = (const float4*)vf;
    float4 acc = make_float4(0.f, 0.f, 0.f, 0.f);
    for (int i = 0; i < cnt; i++) {
        int e = beg + i;
        float w = g_wS[e];
        float4 v = vf4[(size_t)obj[e] * 256 + t];
        acc.x += w * v.x; acc.y += w * v.y; acc.z += w * v.z; acc.w += w * v.w;
    }
    acc.x *= inv; acc.y *= inv; acc.z *= inv; acc.w *= inv;
    ((float4*)g_ctx)[(size_t)n * 256 + t] = acc;
}
// finalizes ALL rows; converts ctx to fp16 for gemm_vj16
__global__ void k_ctxO(const int* __restrict__ sbj, const float* __restrict__ vf) {
    int n = blockIdx.x, t = threadIdx.x;
    int beg = g_baseO[n], cnt = g_degO[n];
    float4* c4 = (float4*)g_ctx;
    float4 old = c4[(size_t)n * 256 + t];
    if (cnt > 0) {
        float inv = 1.f / g_sumO[n];
        const float4* vf4 = (const float4*)vf;
        float4 acc = make_float4(0.f, 0.f, 0.f, 0.f);
        for (int i = 0; i < cnt; i++) {
            int e = g_permO[beg + i];
            float w = g_wO[e];
            float4 v = vf4[(size_t)sbj[e] * 256 + t];
            acc.x += w * v.x; acc.y += w * v.y; acc.z += w * v.z; acc.w += w * v.w;
        }
        old.x += acc.x * inv; old.y += acc.y * inv; old.z += acc.z * inv; old.w += acc.w * inv;
    }
    __half2 h0, h1;
    h0.x = __float2half_rn(old.x); h0.y = __float2half_rn(old.y);
    h1.x = __float2half_rn(old.z); h1.y = __float2half_rn(old.w);
    ((__half2*)g_ctx16)[(size_t)n * 512 + 2 * t]     = h0;
    ((__half2*)g_ctx16)[(size_t)n * 512 + 2 * t + 1] = h1;
}

// ---------------- launch ----------------
extern "C" void kernel_launch(void* const* d_in, const int* in_sizes, int n_in,
                              void* d_out, int out_size) {
    const float* vf    = (const float*)d_in[0];
    const float* R     = (const float*)d_in[1];
    const float* W_rel = (const float*)d_in[2];
    const float* b_rel = (const float*)d_in[3];
    const float* W_sbj = (const float*)d_in[4];
    const float* b_sbj = (const float*)d_in[5];
    const float* W_obj = (const float*)d_in[6];
    const float* b_obj = (const float*)d_in[7];
    const float* W_ctx = (const float*)d_in[8];
    const float* b_ctx = (const float*)d_in[9];
    const int* sbj     = (const int*)d_in[10];
    const int* obj     = (const int*)d_in[11];
    float* out = (float*)d_out;

    cudaFuncSetAttribute(gemm_multi,   cudaFuncAttributeMaxDynamicSharedMemorySize, SMEM16_BYTES);
    cudaFuncSetAttribute(gemm_logit16, cudaFuncAttributeMaxDynamicSharedMemorySize, SMEM16_BYTES);
    cudaFuncSetAttribute(gemm_vj16,    cudaFuncAttributeMaxDynamicSharedMemorySize, SMEM16_BYTES);

    __half *pHs, *pHo, *pKt, *pMT, *pT, *pWr, *pWT, *pVf;
    cudaGetSymbolAddress((void**)&pHs, g_Hs16);
    cudaGetSymbolAddress((void**)&pHo, g_Ho16);
    cudaGetSymbolAddress((void**)&pKt, g_Kt16);
    cudaGetSymbolAddress((void**)&pMT, g_MT16);
    cudaGetSymbolAddress((void**)&pT,  g_T16);
    cudaGetSymbolAddress((void**)&pWr, g_Wr16);
    cudaGetSymbolAddress((void**)&pWT, g_WT16);
    cudaGetSymbolAddress((void**)&pVf, g_vf16);
    float *pS1, *pS2, *pG;
    cudaGetSymbolAddress((void**)&pS1, g_S1);
    cudaGetSymbolAddress((void**)&pS2, g_S2);
    cudaGetSymbolAddress((void**)&pG,  g_G);

    // fp16 weights (straight): Wr_s, Wr_o, Wr_r
    const __half* hWr_s = pWr + 0 * (size_t)DD * DD;
    const __half* hWr_o = pWr + 1 * (size_t)DD * DD;
    const __half* hWr_r = pWr + 2 * (size_t)DD * DD;
    // fp16 weights (transposed): Ws_rT, Wo_rT, WctxT, Ws_vT, Wo_vT
    __half* hWs_rT = pWT + 0 * (size_t)DD * DD;
    __half* hWo_rT = pWT + 1 * (size_t)DD * DD;
    __half* hWctxT = pWT + 2 * (size_t)DD * DD;
    __half* hWs_vT = pWT + 3 * (size_t)DD * DD;
    __half* hWo_vT = pWT + 4 * (size_t)DD * DD;

    const float* Ws_v = W_sbj;
    const float* Ws_r = W_sbj + (size_t)DD * DD;
    const float* Wo_v = W_obj;
    const float* Wo_r = W_obj + (size_t)DD * DD;

    // passthrough + fp16 copy of R
    k_copyround<<<EE * DD / 4 / 256, 256>>>(R, out);

    k_init<<<(NN * DD + 255) / 256, 256>>>();
    k_hist<<<(EE + 255) / 256, 256>>>(sbj, obj);
    k_scan<<<1, 768>>>();
    k_scatter<<<(EE + 255) / 256, 256>>>(obj);
    k_vecs1<<<4, 256>>>(b_rel, b_sbj, b_obj, Ws_r, Wo_r);

    // straight rounds
    k_roundh<<<(3 * DD * DD / 4 + 255) / 256, 256>>>(W_rel, pWr, 3 * DD * DD / 4);
    k_roundh<<<(NN * DD / 4 + 255) / 256, 256>>>(vf, pVf, NN * DD / 4);
    // transposed rounds
    {
        TBatch tb{};
        tb.p[0] = {Ws_r,  hWs_rT};
        tb.p[1] = {Wo_r,  hWo_rT};
        tb.p[2] = {W_ctx, hWctxT};
        tb.p[3] = {Ws_v,  hWs_vT};
        tb.p[4] = {Wo_v,  hWo_vT};
        k_troundh<<<dim3(32, 32, 5), dim3(32, 8)>>>(tb);
    }

    // L1: Hs, Ho, M1T..M4T   (all DD x DD, NT form)
    {
        Batch b{};
        b.d[0] = {hWr_r,  hWs_rT, nullptr, nullptr, nullptr, nullptr, pHs,                        DD, DD, DD, 0};
        b.d[1] = {hWr_r,  hWo_rT, nullptr, nullptr, nullptr, nullptr, pHo,                        DD, DD, DD, 0};
        b.d[2] = {hWs_rT, hWr_s,  nullptr, nullptr, hWs_vT,  nullptr, pMT + 0 * (size_t)DD * DD,  DD, DD, DD, 0};
        b.d[3] = {hWs_rT, hWr_o,  nullptr, nullptr, nullptr, nullptr, pMT + 1 * (size_t)DD * DD,  DD, DD, DD, 0};
        b.d[4] = {hWo_rT, hWr_o,  nullptr, nullptr, hWo_vT,  nullptr, pMT + 2 * (size_t)DD * DD,  DD, DD, DD, 0};
        b.d[5] = {hWo_rT, hWr_s,  nullptr, nullptr, nullptr, nullptr, pMT + 3 * (size_t)DD * DD,  DD, DD, DD, 0};
        gemm_multi<<<dim3(8, 8, 6), 128, SMEM16_BYTES>>>(b);
    }
    // L2: T_z = vf16 @ M_zT^T (z=0..3, M=768), Kt = Ho @ Hs^T
    {
        Batch b{};
        for (int z = 0; z < 4; z++)
            b.d[z] = {pVf, pMT + (size_t)z * DD * DD, nullptr, nullptr, nullptr, nullptr,
                      pT + (size_t)z * NN * DD, NN, DD, DD, 0};
        b.d[4] = {pHo, pHs, nullptr, nullptr, nullptr, nullptr, pKt, DD, DD, DD, 0};
        gemm_multi<<<dim3(8, 8, 5), 128, SMEM16_BYTES>>>(b);
    }
    // L3: S1, S2, G (fp32 outputs)
    {
        Batch b{};
        b.d[0] = {pT + 0 * (size_t)NN * DD, pHo, pT + 3 * (size_t)NN * DD, pHs, nullptr, pS1, nullptr,
                  NN, DD, DD, 1};
        b.d[1] = {pT + 1 * (size_t)NN * DD, pHo, pT + 2 * (size_t)NN * DD, pHs, nullptr, pS2, nullptr,
                  NN, DD, DD, 1};
        b.d[2] = {pT + 0 * (size_t)NN * DD, pT + 2 * (size_t)NN * DD,
                  pT + 3 * (size_t)NN * DD, pT + 1 * (size_t)NN * DD, nullptr, pG, nullptr,
                  NN, NN, NN, 1};
        gemm_multi<<<dim3(8, 6, 3), 128, SMEM16_BYTES>>>(b);
    }
    k_c3<<<128, 256>>>();
    k_addc3<<<(NN * DD + 255) / 256, 256>>>();
    k_scal<<<96, 256>>>();

    gemm_logit16<<<dim3(8, 192), 128, SMEM16_BYTES>>>(R, sbj, obj);

    k_max<<<(EE + 255) / 256, 256>>>(sbj, obj);
    k_exp<<<(EE + 255) / 256, 256>>>(sbj, obj);
    k_ctxS<<<NN, 256>>>(obj, vf);
    k_ctxO<<<NN, 256>>>(sbj, vf);

    gemm_vj16<<<dim3(8, 6), 128, SMEM16_BYTES>>>(hWctxT, b_ctx, vf, out + (size_t)EE * DD);

    (void)in_sizes; (void)n_in; (void)out_size;
}

// round 13
// speedup vs baseline: 1.9125x; 1.1205x over previous
#include <cuda_runtime.h>
#include <cuda_fp16.h>
#include <math.h>
#include <cstdint>

#define NN 768
#define EE 24576
#define DD 1024

// ---------------- fp16 GEMM operand scratch (all [x][1024] K-major) ----------------
__device__ __align__(128) __half g_Hs16[DD * DD];
__device__ __align__(128) __half g_Ho16[DD * DD];
__device__ __align__(128) __half g_Kt16[DD * DD];         // Kt[n,k] = K[k,n]
__device__ __align__(128) __half g_MT16[4 * DD * DD];     // M1T..M4T
__device__ __align__(128) __half g_T16 [4 * NN * DD];     // Ts,Us,To,Uo
__device__ __align__(128) __half g_Wr16[3 * DD * DD];     // Wr_s, Wr_o, Wr_r (straight round)
__device__ __align__(128) __half g_WT16[5 * DD * DD];     // Ws_rT, Wo_rT, WctxT, Ws_vT, Wo_vT
__device__ __align__(128) __half g_vf16[NN * DD];
__device__ __align__(128) __half g_R16 [(size_t)EE * DD];
__device__ __align__(128) __half g_ctx16[NN * DD];
// ---------------- fp32 scratch ----------------
__device__ __align__(128) float g_S1[NN * DD];
__device__ __align__(128) float g_S2[NN * DD];
__device__ __align__(128) float g_G [NN * NN];
__device__ __align__(128) float g_ctx[NN * DD];
__device__ float g_cs[DD], g_co[DD], g_c3[DD];
__device__ float g_csp[8 * DD], g_cop[8 * DD];   // deterministic k_vecs1 partials
__device__ float g_d1[NN], g_d2[NN];
__device__ __align__(128) float g_logits[EE];
__device__ __align__(128) float g_wS[EE];
__device__ __align__(128) float g_wO[EE];
__device__ unsigned g_maxS[NN], g_maxO[NN];
__device__ float g_sumS[NN], g_sumO[NN];
__device__ int g_degS[NN], g_degO[NN], g_baseS[NN], g_baseO[NN], g_curO[NN];
__device__ int g_permO[EE];

// fp16 pipeline: per stage A tile 128 rows x 20 u32 (32 halves + pad), same for B
#define STR32 20
#define STG32 (128 * STR32)            // 2560 u32 per tile
#define SMEM16_BYTES (3 * 2 * STG32 * 4)  // 61440 B

// ---------------- helpers ----------------
__device__ __forceinline__ void mma16(float c[4], unsigned a0, unsigned a1, unsigned a2, unsigned a3,
                                      unsigned b0, unsigned b1) {
    asm volatile(
        "mma.sync.aligned.m16n8k16.row.col.f32.f16.f16.f32 "
        "{%0,%1,%2,%3},{%4,%5,%6,%7},{%8,%9},{%0,%1,%2,%3};"
        : "+f"(c[0]), "+f"(c[1]), "+f"(c[2]), "+f"(c[3])
        : "r"(a0), "r"(a1), "r"(a2), "r"(a3), "r"(b0), "r"(b1));
}
__device__ __forceinline__ void ldsm4(unsigned& r0, unsigned& r1, unsigned& r2, unsigned& r3, uint32_t addr) {
    asm volatile("ldmatrix.sync.aligned.m8n8.x4.shared.b16 {%0,%1,%2,%3}, [%4];"
        : "=r"(r0), "=r"(r1), "=r"(r2), "=r"(r3) : "r"(addr));
}
__device__ __forceinline__ void cpa16p(void* s, const void* g) {
    unsigned sa = (unsigned)__cvta_generic_to_shared(s);
    asm volatile("cp.async.cg.shared.global [%0], [%1], 16;" :: "r"(sa), "l"(g));
}
__device__ __forceinline__ void cpa_commit() { asm volatile("cp.async.commit_group;"); }
template<int N> __device__ __forceinline__ void cpa_wait() { asm volatile("cp.async.wait_group %0;" :: "n"(N)); }

__device__ __forceinline__ unsigned fkey(float f) {
    unsigned u = __float_as_uint(f);
    return (u & 0x80000000u) ? ~u : (u | 0x80000000u);
}
__device__ __forceinline__ float funkey(unsigned k) {
    return (k & 0x80000000u) ? __uint_as_float(k ^ 0x80000000u) : __uint_as_float(~k);
}

// ---------------- fp16 NT mainloop (ldmatrix fragment loads) ----------------
// C[m,n] = sum_k A[m,k] * B[n,k], K=1024, BK=32, 3-stage cp.async, one sync/slab.
// 128x128 CTA tile, 4 warps, 64x64 warp tiles, m16n8k16, ldmatrix.x4 loads.
__device__ __forceinline__ void run_ml16(const __half* __restrict__ A,
                                         const __half* __restrict__ B,
                                         int bm, int bn,
                                         float (&acc)[4][8][4],
                                         uint32_t* __restrict__ As,
                                         uint32_t* __restrict__ Bs) {
    int tid = threadIdx.x;
    int lane = tid & 31;
    int warp = tid >> 5;
    int wm = (warp & 1) * 64;
    int wn = (warp >> 1) * 64;

    uint32_t baseA = (uint32_t)__cvta_generic_to_shared(As);
    uint32_t baseB = (uint32_t)__cvta_generic_to_shared(Bs);

    // per-lane ldmatrix byte offsets within a tile (row stride 80 B)
    // A x4: m0 rows[wm+mt*16+0..7, k0-7], m1 rows[+8, k0-7], m2 rows[0..7, k8-15], m3 [+8, k8-15]
    uint32_t offA[4], offB[4];
#pragma unroll
    for (int mt = 0; mt < 4; mt++)
        offA[mt] = (uint32_t)((wm + mt * 16 + (lane & 7) + ((lane >> 3) & 1) * 8) * 80 + (lane >> 4) * 16);
    // B x4 (pair p -> nt=2p,2p+1): m0 rows[wn+p*16+0..7, k0-7], m1 same rows k8-15, m2 rows+8 k0-7, m3 rows+8 k8-15
#pragma unroll
    for (int p = 0; p < 4; p++)
        offB[p] = (uint32_t)((wn + p * 16 + (lane & 7) + ((lane >> 4) & 1) * 8) * 80 + ((lane >> 3) & 1) * 16);

    auto issue = [&](int s) {
        int stg = s % 3;
        uint32_t* as = As + stg * STG32;
        uint32_t* bs = Bs + stg * STG32;
#pragma unroll
        for (int p = 0; p < 4; p++) {
            int idx = p * 128 + tid;
            int row = idx >> 2;
            int c4 = idx & 3;
            cpa16p(as + row * STR32 + c4 * 4, A + (size_t)(bm + row) * DD + s * 32 + c4 * 8);
        }
#pragma unroll
        for (int p = 0; p < 4; p++) {
            int idx = p * 128 + tid;
            int row = idx >> 2;
            int c4 = idx & 3;
            cpa16p(bs + row * STR32 + c4 * 4, B + (size_t)(bn + row) * DD + s * 32 + c4 * 8);
        }
        cpa_commit();
    };

    issue(0);
    issue(1);
    for (int kt = 0; kt < 32; kt++) {
        cpa_wait<1>();
        __syncthreads();
        uint32_t ta = baseA + (uint32_t)((kt % 3) * STG32 * 4);
        uint32_t tb = baseB + (uint32_t)((kt % 3) * STG32 * 4);
#pragma unroll
        for (int kk = 0; kk < 2; kk++) {
            unsigned af[4][4], bf[8][2];
#pragma unroll
            for (int mt = 0; mt < 4; mt++)
                ldsm4(af[mt][0], af[mt][1], af[mt][2], af[mt][3], ta + offA[mt] + kk * 32);
#pragma unroll
            for (int p = 0; p < 4; p++)
                ldsm4(bf[2 * p][0], bf[2 * p][1], bf[2 * p + 1][0], bf[2 * p + 1][1],
                      tb + offB[p] + kk * 32);
#pragma unroll
            for (int mt = 0; mt < 4; mt++)
#pragma unroll
                for (int nt = 0; nt < 8; nt++)
                    mma16(acc[mt][nt], af[mt][0], af[mt][1], af[mt][2], af[mt][3],
                          bf[nt][0], bf[nt][1]);
        }
        if (kt + 2 < 32) issue(kt + 2);
    }
}

// ---------------- generalized batched NT GEMM ----------------
struct Desc {
    const __half* A; const __half* B; const __half* A2; const __half* B2;
    const __half* CaddH;          // optional half addend [m][n]
    float* C32; __half* C16;      // exactly one non-null
    int M; int N; int ldc; int dual;
};
struct Batch { Desc d[6]; };

__global__ __launch_bounds__(128) void gemm_multi(Batch p) {
    Desc d = p.d[blockIdx.z];
    int bm = blockIdx.y * 128;
    int bn = blockIdx.x * 128;
    if (bm >= d.M || bn >= d.N) return;

    extern __shared__ uint32_t sm16[];
    uint32_t* As = sm16;
    uint32_t* Bs = sm16 + 3 * STG32;

    float acc[4][8][4];
#pragma unroll
    for (int a = 0; a < 4; a++)
#pragma unroll
        for (int b = 0; b < 8; b++)
#pragma unroll
            for (int c = 0; c < 4; c++) acc[a][b][c] = 0.f;

    run_ml16(d.A, d.B, bm, bn, acc, As, Bs);
    if (d.dual) { __syncthreads(); run_ml16(d.A2, d.B2, bm, bn, acc, As, Bs); }

    int lane = threadIdx.x & 31;
    int warp = threadIdx.x >> 5;
    int wm = (warp & 1) * 64;
    int wn = (warp >> 1) * 64;
#pragma unroll
    for (int mt = 0; mt < 4; mt++)
#pragma unroll
        for (int half_ = 0; half_ < 2; half_++) {
            int r = bm + wm + mt * 16 + (lane >> 2) + half_ * 8;
#pragma unroll
            for (int nt = 0; nt < 8; nt++) {
                int c = bn + wn + nt * 8 + (lane & 3) * 2;
                float vx = acc[mt][nt][half_ * 2 + 0];
                float vy = acc[mt][nt][half_ * 2 + 1];
                if (d.CaddH) {
                    vx += __half2float(d.CaddH[(size_t)r * d.ldc + c]);
                    vy += __half2float(d.CaddH[(size_t)r * d.ldc + c + 1]);
                }
                if (d.C16) {
                    __half2 h;
                    h.x = __float2half_rn(vx);
                    h.y = __float2half_rn(vy);
                    *(__half2*)(d.C16 + (size_t)r * d.ldc + c) = h;
                } else {
                    float2 v; v.x = vx; v.y = vy;
                    *(float2*)(d.C32 + (size_t)r * d.ldc + c) = v;
                }
            }
        }
}

// ---------------- E-GEMM (fp16) with fused logit epilogue ----------------
__global__ __launch_bounds__(128) void gemm_logit16(const float* __restrict__ Rraw,
                                                    const int* __restrict__ sbj,
                                                    const int* __restrict__ obj) {
    extern __shared__ uint32_t sm16[];
    uint32_t* As = sm16;
    uint32_t* Bs = sm16 + 3 * STG32;
    int bm = blockIdx.y * 128;
    int bn = blockIdx.x * 128;

    float acc[4][8][4];
#pragma unroll
    for (int a = 0; a < 4; a++)
#pragma unroll
        for (int b = 0; b < 8; b++)
#pragma unroll
            for (int c = 0; c < 4; c++) acc[a][b][c] = 0.f;

    run_ml16(g_R16, g_Kt16, bm, bn, acc, As, Bs);

    int lane = threadIdx.x & 31;
    int warp = threadIdx.x >> 5;
    int wm = (warp & 1) * 64;
    int wn = (warp >> 1) * 64;
    const float scale = 0.03125f;

#pragma unroll
    for (int mt = 0; mt < 4; mt++) {
#pragma unroll
        for (int half_ = 0; half_ < 2; half_++) {
            int r = bm + wm + mt * 16 + (lane >> 2) + half_ * 8;
            int s = sbj[r], o = obj[r];
            const float* Rr  = Rraw + (size_t)r * DD;
            const float* S1r = g_S1 + (size_t)s * DD;
            const float* S2r = g_S2 + (size_t)o * DD;
            float part = 0.f;
#pragma unroll
            for (int nt = 0; nt < 8; nt++) {
                int c = bn + wn + nt * 8 + (lane & 3) * 2;
                float2 Rv  = *(const float2*)(Rr + c);
                float2 s1v = *(const float2*)(S1r + c);
                float2 s2v = *(const float2*)(S2r + c);
                part += (acc[mt][nt][half_ * 2 + 0] + s1v.x + s2v.x) * Rv.x;
                part += (acc[mt][nt][half_ * 2 + 1] + s1v.y + s2v.y) * Rv.y;
            }
            part += __shfl_xor_sync(0xFFFFFFFF, part, 1);
            part += __shfl_xor_sync(0xFFFFFFFF, part, 2);
            if ((lane & 3) == 0) {
                if (bn == 0 && wn == 0)
                    part += g_G[(size_t)s * NN + o] + g_d1[s] + g_d2[o];
                atomicAdd(&g_logits[r], part * scale);
            }
        }
    }
}

// ---------------- final vj GEMM (fp16) ----------------
__global__ __launch_bounds__(128) void gemm_vj16(const __half* __restrict__ WctxT,
                                                 const float* __restrict__ bias,
                                                 const float* __restrict__ vf,
                                                 float* __restrict__ out) {
    extern __shared__ uint32_t sm16[];
    uint32_t* As = sm16;
    uint32_t* Bs = sm16 + 3 * STG32;
    int bm = blockIdx.y * 128;
    int bn = blockIdx.x * 128;

    float acc[4][8][4];
#pragma unroll
    for (int a = 0; a < 4; a++)
#pragma unroll
        for (int b = 0; b < 8; b++)
#pragma unroll
            for (int c = 0; c < 4; c++) acc[a][b][c] = 0.f;

    run_ml16(g_ctx16, WctxT, bm, bn, acc, As, Bs);

    int lane = threadIdx.x & 31;
    int warp = threadIdx.x >> 5;
    int wm = (warp & 1) * 64;
    int wn = (warp >> 1) * 64;
#pragma unroll
    for (int mt = 0; mt < 4; mt++)
#pragma unroll
        for (int half_ = 0; half_ < 2; half_++) {
            int r = bm + wm + mt * 16 + (lane >> 2) + half_ * 8;
            bool inv = (g_degS[r] + g_degO[r]) > 0;
            const float* vfr = vf + (size_t)r * DD;
            float* outr = out + (size_t)r * DD;
#pragma unroll
            for (int nt = 0; nt < 8; nt++) {
                int c = bn + wn + nt * 8 + (lane & 3) * 2;
                float2 v;
                v.x = vfr[c]     + acc[mt][nt][half_ * 2 + 0] + (inv ? bias[c] : 0.f);
                v.y = vfr[c + 1] + acc[mt][nt][half_ * 2 + 1] + (inv ? bias[c + 1] : 0.f);
                *(float2*)(outr + c) = v;
            }
        }
}

// ---------------- conversion kernels ----------------
// passthrough fp32 + rounded fp16 copy of R
__global__ void k_copyround(const float* __restrict__ src, float* __restrict__ raw) {
    int i = blockIdx.x * 256 + threadIdx.x;   // float4 index (grid sized exactly)
    float4 v = ((const float4*)src)[i];
    ((float4*)raw)[i] = v;
    __half2 h0, h1;
    h0.x = __float2half_rn(v.x); h0.y = __float2half_rn(v.y);
    h1.x = __float2half_rn(v.z); h1.y = __float2half_rn(v.w);
    ((__half2*)g_R16)[2 * i] = h0;
    ((__half2*)g_R16)[2 * i + 1] = h1;
}
__global__ void k_roundh(const float* __restrict__ src, __half* __restrict__ dst, int n4) {
    int i = blockIdx.x * blockDim.x + threadIdx.x;
    if (i < n4) {
        float4 v = ((const float4*)src)[i];
        __half2 h0, h1;
        h0.x = __float2half_rn(v.x); h0.y = __float2half_rn(v.y);
        h1.x = __float2half_rn(v.z); h1.y = __float2half_rn(v.w);
        ((__half2*)dst)[2 * i] = h0;
        ((__half2*)dst)[2 * i + 1] = h1;
    }
}
// transpose + round: dst[n][k] = (half)src[k][n], DD x DD
struct TPair { const float* s; __half* d; };
struct TBatch { TPair p[5]; };
__global__ void k_troundh(TBatch tb) {
    __shared__ float t[32][33];
    TPair pr = tb.p[blockIdx.z];
    int x = blockIdx.x * 32 + threadIdx.x;       // n
    int y0 = blockIdx.y * 32 + threadIdx.y;      // k
#pragma unroll
    for (int j = 0; j < 4; j++)
        t[threadIdx.y + j * 8][threadIdx.x] = pr.s[(size_t)(y0 + j * 8) * DD + x];
    __syncthreads();
    int x2 = blockIdx.y * 32 + threadIdx.x;      // k
    int y2 = blockIdx.x * 32 + threadIdx.y;      // n
#pragma unroll
    for (int j = 0; j < 4; j++)
        pr.d[(size_t)(y2 + j * 8) * DD + x2] = __float2half_rn(t[threadIdx.x][threadIdx.y + j * 8]);
}

// ---------------- small kernels ----------------
__global__ void k_init() {
    int i = blockIdx.x * blockDim.x + threadIdx.x;
    if (i < NN * DD) g_ctx[i] = 0.f;
    if (i < EE) g_logits[i] = 0.f;
    if (i < NN) {
        g_sumS[i] = 0.f; g_sumO[i] = 0.f;
        g_maxS[i] = 0u; g_maxO[i] = 0u;
        g_degS[i] = 0; g_degO[i] = 0;
    }
}
__global__ void k_hist(const int* __restrict__ sbj, const int* __restrict__ obj) {
    int e = blockIdx.x * blockDim.x + threadIdx.x;
    if (e < EE) { atomicAdd(&g_degS[sbj[e]], 1); atomicAdd(&g_degO[obj[e]], 1); }
}
// parallel exclusive scan over 768 elements (one block of 768 threads) — integer, deterministic
__global__ void k_scan() {
    __shared__ int wsumS[24], wsumO[24];
    int t = threadIdx.x;              // 0..767
    int lane = t & 31, warp = t >> 5; // 24 warps
    int dS = g_degS[t], dO = g_degO[t];
    int iS = dS, iO = dO;
#pragma unroll
    for (int off = 1; off < 32; off <<= 1) {
        int vS = __shfl_up_sync(0xFFFFFFFF, iS, off);
        int vO = __shfl_up_sync(0xFFFFFFFF, iO, off);
        if (lane >= off) { iS += vS; iO += vO; }
    }
    if (lane == 31) { wsumS[warp] = iS; wsumO[warp] = iO; }
    __syncthreads();
    if (warp == 0 && lane < 24) {
        int sS = wsumS[lane], sO = wsumO[lane];
#pragma unroll
        for (int off = 1; off < 32; off <<= 1) {
            int vS = __shfl_up_sync(0x00FFFFFF, sS, off);
            int vO = __shfl_up_sync(0x00FFFFFF, sO, off);
            if (lane >= off) { sS += vS; sO += vO; }
        }
        wsumS[lane] = sS; wsumO[lane] = sO;
    }
    __syncthreads();
    int offS = (warp > 0) ? wsumS[warp - 1] : 0;
    int offO = (warp > 0) ? wsumO[warp - 1] : 0;
    g_baseS[t] = offS + iS - dS;
    g_baseO[t] = offO + iO - dO;
    g_curO[t]  = offO + iO - dO;
}
__global__ void k_scatter(const int* __restrict__ obj) {
    int e = blockIdx.x * blockDim.x + threadIdx.x;
    if (e < EE) { int p = atomicAdd(&g_curO[obj[e]], 1); g_permO[p] = e; }
}
// deterministic parallel k_vecs1: stage 1 — per-chunk partials (no atomics)
__global__ void k_vecs1p(const float* __restrict__ b_rel,
                         const float* __restrict__ Ws_r,
                         const float* __restrict__ Wo_r) {
    int j = blockIdx.x * 256 + threadIdx.x;      // 0..1023 (grid.x = 4)
    int c = blockIdx.y;                          // chunk 0..7
    int i0 = c * 128;
    float s = 0.f, o = 0.f;
    for (int i = i0; i < i0 + 128; i++) {
        float br = b_rel[i];
        s += br * Ws_r[(size_t)i * DD + j];
        o += br * Wo_r[(size_t)i * DD + j];
    }
    g_csp[c * DD + j] = s;
    g_cop[c * DD + j] = o;
}
// stage 2 — fixed-order reduction (deterministic)
__global__ void k_vecs1r(const float* __restrict__ b_sbj, const float* __restrict__ b_obj) {
    int j = blockIdx.x * 256 + threadIdx.x;      // grid.x = 4
    float s = b_sbj[j], o = b_obj[j];
#pragma unroll
    for (int c = 0; c < 8; c++) {
        s += g_csp[c * DD + j];
        o += g_cop[c * DD + j];
    }
    g_cs[j] = s;
    g_co[j] = o;
}
// c3[j] = sum_i cs[i]*Ho[j,i] + co[i]*Hs[j,i]  (Hs/Ho fp16)
__global__ void k_c3() {
    int j = blockIdx.x * 8 + (threadIdx.x >> 5);
    int lane = threadIdx.x & 31;
    if (j >= DD) return;
    float a = 0.f;
    for (int i = lane; i < DD; i += 32)
        a += g_cs[i] * __half2float(g_Ho16[(size_t)j * DD + i])
           + g_co[i] * __half2float(g_Hs16[(size_t)j * DD + i]);
#pragma unroll
    for (int off = 16; off > 0; off >>= 1) a += __shfl_xor_sync(0xFFFFFFFF, a, off);
    if (lane == 0) g_c3[j] = a;
}
__global__ void k_addc3() {
    int i = blockIdx.x * blockDim.x + threadIdx.x;
    if (i < NN * DD) g_S1[i] += g_c3[i & (DD - 1)];
}
__global__ void k_scal() {
    int n = blockIdx.x * 8 + (threadIdx.x >> 5);
    int lane = threadIdx.x & 31;
    if (n >= NN) return;
    const __half* Ts = g_T16 + 0 * NN * DD + (size_t)n * DD;
    const __half* Us = g_T16 + 1 * NN * DD + (size_t)n * DD;
    const __half* To = g_T16 + 2 * NN * DD + (size_t)n * DD;
    const __half* Uo = g_T16 + 3 * NN * DD + (size_t)n * DD;
    float t1 = 0.f, t2 = 0.f, t3 = 0.f;
    for (int c = lane; c < DD; c += 32) {
        float cs = g_cs[c], co = g_co[c];
        t1 += (__half2float(Ts[c]) + cs) * (__half2float(Uo[c]) + co);
        t2 += (__half2float(Us[c]) + cs) * (__half2float(To[c]) + co);
        t3 += cs * co;
    }
#pragma unroll
    for (int off = 16; off > 0; off >>= 1) {
        t1 += __shfl_xor_sync(0xFFFFFFFF, t1, off);
        t2 += __shfl_xor_sync(0xFFFFFFFF, t2, off);
        t3 += __shfl_xor_sync(0xFFFFFFFF, t3, off);
    }
    if (lane == 0) { g_d1[n] = t1; g_d2[n] = t2 - t3; }
}
__global__ void k_max(const int* __restrict__ sbj, const int* __restrict__ obj) {
    int e = blockIdx.x * blockDim.x + threadIdx.x;
    if (e < EE) {
        unsigned k = fkey(g_logits[e]);
        atomicMax(&g_maxS[sbj[e]], k);
        atomicMax(&g_maxO[obj[e]], k);
    }
}
__global__ void k_exp(const int* __restrict__ sbj, const int* __restrict__ obj) {
    int e = blockIdx.x * blockDim.x + threadIdx.x;
    if (e < EE) {
        float l = g_logits[e];
        float es = expf(l - funkey(g_maxS[sbj[e]]));
        float eo = expf(l - funkey(g_maxO[obj[e]]));
        g_wS[e] = es; g_wO[e] = eo;
        atomicAdd(&g_sumS[sbj[e]], es);
        atomicAdd(&g_sumO[obj[e]], eo);
    }
}
__global__ void k_ctxS(const int* __restrict__ obj, const float* __restrict__ vf) {
    int n = blockIdx.x, t = threadIdx.x;
    int beg = g_baseS[n], cnt = g_degS[n];
    if (cnt == 0) return;
    float inv = 1.f / g_sumS[n];
    const float4* vf4 = (const float4*)vf;
    float4 acc = make_float4(0.f, 0.f, 0.f, 0.f);
    for (int i = 0; i < cnt; i++) {
        int e = beg + i;
        float w = g_wS[e];
        float4 v = vf4[(size_t)obj[e] * 256 + t];
        acc.x += w * v.x; acc.y += w * v.y; acc.z += w * v.z; acc.w += w * v.w;
    }
    acc.x *= inv; acc.y *= inv; acc.z *= inv; acc.w *= inv;
    ((float4*)g_ctx)[(size_t)n * 256 + t] = acc;
}
// finalizes ALL rows; converts ctx to fp16 for gemm_vj16
__global__ void k_ctxO(const int* __restrict__ sbj, const float* __restrict__ vf) {
    int n = blockIdx.x, t = threadIdx.x;
    int beg = g_baseO[n], cnt = g_degO[n];
    float4* c4 = (float4*)g_ctx;
    float4 old = c4[(size_t)n * 256 + t];
    if (cnt > 0) {
        float inv = 1.f / g_sumO[n];
        const float4* vf4 = (const float4*)vf;
        float4 acc = make_float4(0.f, 0.f, 0.f, 0.f);
        for (int i = 0; i < cnt; i++) {
            int e = g_permO[beg + i];
            float w = g_wO[e];
            float4 v = vf4[(size_t)sbj[e] * 256 + t];
            acc.x += w * v.x; acc.y += w * v.y; acc.z += w * v.z; acc.w += w * v.w;
        }
        old.x += acc.x * inv; old.y += acc.y * inv; old.z += acc.z * inv; old.w += acc.w * inv;
    }
    __half2 h0, h1;
    h0.x = __float2half_rn(old.x); h0.y = __float2half_rn(old.y);
    h1.x = __float2half_rn(old.z); h1.y = __float2half_rn(old.w);
    ((__half2*)g_ctx16)[(size_t)n * 512 + 2 * t]     = h0;
    ((__half2*)g_ctx16)[(size_t)n * 512 + 2 * t + 1] = h1;
}

// ---------------- launch ----------------
extern "C" void kernel_launch(void* const* d_in, const int* in_sizes, int n_in,
                              void* d_out, int out_size) {
    const float* vf    = (const float*)d_in[0];
    const float* R     = (const float*)d_in[1];
    const float* W_rel = (const float*)d_in[2];
    const float* b_rel = (const float*)d_in[3];
    const float* W_sbj = (const float*)d_in[4];
    const float* b_sbj = (const float*)d_in[5];
    const float* W_obj = (const float*)d_in[6];
    const float* b_obj = (const float*)d_in[7];
    const float* W_ctx = (const float*)d_in[8];
    const float* b_ctx = (const float*)d_in[9];
    const int* sbj     = (const int*)d_in[10];
    const int* obj     = (const int*)d_in[11];
    float* out = (float*)d_out;

    cudaFuncSetAttribute(gemm_multi,   cudaFuncAttributeMaxDynamicSharedMemorySize, SMEM16_BYTES);
    cudaFuncSetAttribute(gemm_logit16, cudaFuncAttributeMaxDynamicSharedMemorySize, SMEM16_BYTES);
    cudaFuncSetAttribute(gemm_vj16,    cudaFuncAttributeMaxDynamicSharedMemorySize, SMEM16_BYTES);

    __half *pHs, *pHo, *pKt, *pMT, *pT, *pWr, *pWT, *pVf;
    cudaGetSymbolAddress((void**)&pHs, g_Hs16);
    cudaGetSymbolAddress((void**)&pHo, g_Ho16);
    cudaGetSymbolAddress((void**)&pKt, g_Kt16);
    cudaGetSymbolAddress((void**)&pMT, g_MT16);
    cudaGetSymbolAddress((void**)&pT,  g_T16);
    cudaGetSymbolAddress((void**)&pWr, g_Wr16);
    cudaGetSymbolAddress((void**)&pWT, g_WT16);
    cudaGetSymbolAddress((void**)&pVf, g_vf16);
    float *pS1, *pS2, *pG;
    cudaGetSymbolAddress((void**)&pS1, g_S1);
    cudaGetSymbolAddress((void**)&pS2, g_S2);
    cudaGetSymbolAddress((void**)&pG,  g_G);

    // fp16 weights (straight): Wr_s, Wr_o, Wr_r
    const __half* hWr_s = pWr + 0 * (size_t)DD * DD;
    const __half* hWr_o = pWr + 1 * (size_t)DD * DD;
    const __half* hWr_r = pWr + 2 * (size_t)DD * DD;
    // fp16 weights (transposed): Ws_rT, Wo_rT, WctxT, Ws_vT, Wo_vT
    __half* hWs_rT = pWT + 0 * (size_t)DD * DD;
    __half* hWo_rT = pWT + 1 * (size_t)DD * DD;
    __half* hWctxT = pWT + 2 * (size_t)DD * DD;
    __half* hWs_vT = pWT + 3 * (size_t)DD * DD;
    __half* hWo_vT = pWT + 4 * (size_t)DD * DD;

    const float* Ws_v = W_sbj;
    const float* Ws_r = W_sbj + (size_t)DD * DD;
    const float* Wo_v = W_obj;
    const float* Wo_r = W_obj + (size_t)DD * DD;

    // passthrough + fp16 copy of R
    k_copyround<<<EE * DD / 4 / 256, 256>>>(R, out);

    k_init<<<(NN * DD + 255) / 256, 256>>>();
    k_hist<<<(EE + 255) / 256, 256>>>(sbj, obj);
    k_scan<<<1, 768>>>();
    k_scatter<<<(EE + 255) / 256, 256>>>(obj);
    k_vecs1p<<<dim3(4, 8), 256>>>(b_rel, Ws_r, Wo_r);
    k_vecs1r<<<4, 256>>>(b_sbj, b_obj);

    // straight rounds
    k_roundh<<<(3 * DD * DD / 4 + 255) / 256, 256>>>(W_rel, pWr, 3 * DD * DD / 4);
    k_roundh<<<(NN * DD / 4 + 255) / 256, 256>>>(vf, pVf, NN * DD / 4);
    // transposed rounds
    {
        TBatch tb{};
        tb.p[0] = {Ws_r,  hWs_rT};
        tb.p[1] = {Wo_r,  hWo_rT};
        tb.p[2] = {W_ctx, hWctxT};
        tb.p[3] = {Ws_v,  hWs_vT};
        tb.p[4] = {Wo_v,  hWo_vT};
        k_troundh<<<dim3(32, 32, 5), dim3(32, 8)>>>(tb);
    }

    // L1: Hs, Ho, M1T..M4T   (all DD x DD, NT form)
    {
        Batch b{};
        b.d[0] = {hWr_r,  hWs_rT, nullptr, nullptr, nullptr, nullptr, pHs,                        DD, DD, DD, 0};
        b.d[1] = {hWr_r,  hWo_rT, nullptr, nullptr, nullptr, nullptr, pHo,                        DD, DD, DD, 0};
        b.d[2] = {hWs_rT, hWr_s,  nullptr, nullptr, hWs_vT,  nullptr, pMT + 0 * (size_t)DD * DD,  DD, DD, DD, 0};
        b.d[3] = {hWs_rT, hWr_o,  nullptr, nullptr, nullptr, nullptr, pMT + 1 * (size_t)DD * DD,  DD, DD, DD, 0};
        b.d[4] = {hWo_rT, hWr_o,  nullptr, nullptr, hWo_vT,  nullptr, pMT + 2 * (size_t)DD * DD,  DD, DD, DD, 0};
        b.d[5] = {hWo_rT, hWr_s,  nullptr, nullptr, nullptr, nullptr, pMT + 3 * (size_t)DD * DD,  DD, DD, DD, 0};
        gemm_multi<<<dim3(8, 8, 6), 128, SMEM16_BYTES>>>(b);
    }
    // L2: T_z = vf16 @ M_zT^T (z=0..3, M=768), Kt = Ho @ Hs^T
    {
        Batch b{};
        for (int z = 0; z < 4; z++)
            b.d[z] = {pVf, pMT + (size_t)z * DD * DD, nullptr, nullptr, nullptr, nullptr,
                      pT + (size_t)z * NN * DD, NN, DD, DD, 0};
        b.d[4] = {pHo, pHs, nullptr, nullptr, nullptr, nullptr, pKt, DD, DD, DD, 0};
        gemm_multi<<<dim3(8, 8, 5), 128, SMEM16_BYTES>>>(b);
    }
    // L3: S1, S2, G (fp32 outputs)
    {
        Batch b{};
        b.d[0] = {pT + 0 * (size_t)NN * DD, pHo, pT + 3 * (size_t)NN * DD, pHs, nullptr, pS1, nullptr,
                  NN, DD, DD, 1};
        b.d[1] = {pT + 1 * (size_t)NN * DD, pHo, pT + 2 * (size_t)NN * DD, pHs, nullptr, pS2, nullptr,
                  NN, DD, DD, 1};
        b.d[2] = {pT + 0 * (size_t)NN * DD, pT + 2 * (size_t)NN * DD,
                  pT + 3 * (size_t)NN * DD, pT + 1 * (size_t)NN * DD, nullptr, pG, nullptr,
                  NN, NN, NN, 1};
        gemm_multi<<<dim3(8, 6, 3), 128, SMEM16_BYTES>>>(b);
    }
    k_c3<<<128, 256>>>();
    k_addc3<<<(NN * DD + 255) / 256, 256>>>();
    k_scal<<<96, 256>>>();

    gemm_logit16<<<dim3(8, 192), 128, SMEM16_BYTES>>>(R, sbj, obj);

    k_max<<<(EE + 255) / 256, 256>>>(sbj, obj);
    k_exp<<<(EE + 255) / 256, 256>>>(sbj, obj);
    k_ctxS<<<NN, 256>>>(obj, vf);
    k_ctxO<<<NN, 256>>>(sbj, vf);

    gemm_vj16<<<dim3(8, 6), 128, SMEM16_BYTES>>>(hWctxT, b_ctx, vf, out + (size_t)EE * DD);

    (void)in_sizes; (void)n_in; (void)out_size;
}

// round 14
// speedup vs baseline: 2.0414x; 1.0674x over previous
#include <cuda_runtime.h>
#include <cuda_fp16.h>
#include <math.h>
#include <cstdint>

#define NN 768
#define EE 24576
#define DD 1024

// ---------------- fp16 GEMM operand scratch (all [x][1024] K-major) ----------------
__device__ __align__(128) __half g_Hs16[DD * DD];
__device__ __align__(128) __half g_Ho16[DD * DD];
__device__ __align__(128) __half g_Kt16[DD * DD];         // Kt[n,k] = K[k,n]
__device__ __align__(128) __half g_MT16[4 * DD * DD];     // M1T..M4T
__device__ __align__(128) __half g_T16 [4 * NN * DD];     // Ts,Us,To,Uo
__device__ __align__(128) __half g_Wr16[3 * DD * DD];     // Wr_s, Wr_o, Wr_r (straight round)
__device__ __align__(128) __half g_WT16[5 * DD * DD];     // Ws_rT, Wo_rT, WctxT, Ws_vT, Wo_vT
__device__ __align__(128) __half g_vf16[NN * DD];
__device__ __align__(128) __half g_R16 [(size_t)EE * DD];
__device__ __align__(128) __half g_ctx16[NN * DD];
// ---------------- fp32 scratch ----------------
__device__ __align__(128) float g_S1[NN * DD];
__device__ __align__(128) float g_S2[NN * DD];
__device__ __align__(128) float g_G [NN * NN];
__device__ __align__(128) float g_ctx[NN * DD];
__device__ float g_cs[DD], g_co[DD], g_c3[DD];
__device__ float g_csp[8 * DD], g_cop[8 * DD];
__device__ float g_d1[NN], g_d2[NN];
__device__ __align__(128) float g_logits[EE];
__device__ __align__(128) float g_wS[EE];
__device__ __align__(128) float g_wO[EE];
__device__ unsigned g_maxS[NN], g_maxO[NN];
__device__ float g_sumS[NN], g_sumO[NN];
__device__ int g_degS[NN], g_degO[NN], g_baseS[NN], g_baseO[NN], g_curO[NN];
__device__ int g_permO[EE];

// fp16 pipeline: 4 stages, per stage A tile 128 rows x 20 u32 (32 halves + pad)
#define STR32 20
#define STG32 (128 * STR32)            // 2560 u32 per tile
#define NSTG 4
#define SMEM16_BYTES (NSTG * 2 * STG32 * 4)  // 81920 B

// ---------------- helpers ----------------
__device__ __forceinline__ void mma16(float c[4], unsigned a0, unsigned a1, unsigned a2, unsigned a3,
                                      unsigned b0, unsigned b1) {
    asm volatile(
        "mma.sync.aligned.m16n8k16.row.col.f32.f16.f16.f32 "
        "{%0,%1,%2,%3},{%4,%5,%6,%7},{%8,%9},{%0,%1,%2,%3};"
        : "+f"(c[0]), "+f"(c[1]), "+f"(c[2]), "+f"(c[3])
        : "r"(a0), "r"(a1), "r"(a2), "r"(a3), "r"(b0), "r"(b1));
}
__device__ __forceinline__ void ldsm4(unsigned& r0, unsigned& r1, unsigned& r2, unsigned& r3, uint32_t addr) {
    asm volatile("ldmatrix.sync.aligned.m8n8.x4.shared.b16 {%0,%1,%2,%3}, [%4];"
        : "=r"(r0), "=r"(r1), "=r"(r2), "=r"(r3) : "r"(addr));
}
__device__ __forceinline__ void cpa16p(void* s, const void* g) {
    unsigned sa = (unsigned)__cvta_generic_to_shared(s);
    asm volatile("cp.async.cg.shared.global [%0], [%1], 16;" :: "r"(sa), "l"(g));
}
__device__ __forceinline__ void cpa_commit() { asm volatile("cp.async.commit_group;"); }
template<int N> __device__ __forceinline__ void cpa_wait() { asm volatile("cp.async.wait_group %0;" :: "n"(N)); }

__device__ __forceinline__ unsigned fkey(float f) {
    unsigned u = __float_as_uint(f);
    return (u & 0x80000000u) ? ~u : (u | 0x80000000u);
}
__device__ __forceinline__ float funkey(unsigned k) {
    return (k & 0x80000000u) ? __uint_as_float(k ^ 0x80000000u) : __uint_as_float(~k);
}

// ---------------- fp16 NT mainloop (ldmatrix, 4-stage) ----------------
__device__ __forceinline__ void run_ml16(const __half* __restrict__ A,
                                         const __half* __restrict__ B,
                                         int bm, int bn,
                                         float (&acc)[4][8][4],
                                         uint32_t* __restrict__ As,
                                         uint32_t* __restrict__ Bs) {
    int tid = threadIdx.x;
    int lane = tid & 31;
    int warp = tid >> 5;
    int wm = (warp & 1) * 64;
    int wn = (warp >> 1) * 64;

    uint32_t baseA = (uint32_t)__cvta_generic_to_shared(As);
    uint32_t baseB = (uint32_t)__cvta_generic_to_shared(Bs);

    uint32_t offA[4], offB[4];
#pragma unroll
    for (int mt = 0; mt < 4; mt++)
        offA[mt] = (uint32_t)((wm + mt * 16 + (lane & 7) + ((lane >> 3) & 1) * 8) * 80 + (lane >> 4) * 16);
#pragma unroll
    for (int p = 0; p < 4; p++)
        offB[p] = (uint32_t)((wn + p * 16 + (lane & 7) + ((lane >> 4) & 1) * 8) * 80 + ((lane >> 3) & 1) * 16);

    auto issue = [&](int s) {
        int stg = s % NSTG;
        uint32_t* as = As + stg * STG32;
        uint32_t* bs = Bs + stg * STG32;
#pragma unroll
        for (int p = 0; p < 4; p++) {
            int idx = p * 128 + tid;
            int row = idx >> 2;
            int c4 = idx & 3;
            cpa16p(as + row * STR32 + c4 * 4, A + (size_t)(bm + row) * DD + s * 32 + c4 * 8);
        }
#pragma unroll
        for (int p = 0; p < 4; p++) {
            int idx = p * 128 + tid;
            int row = idx >> 2;
            int c4 = idx & 3;
            cpa16p(bs + row * STR32 + c4 * 4, B + (size_t)(bn + row) * DD + s * 32 + c4 * 8);
        }
        cpa_commit();
    };

    issue(0);
    issue(1);
    issue(2);
    for (int kt = 0; kt < 32; kt++) {
        cpa_wait<2>();
        __syncthreads();
        uint32_t ta = baseA + (uint32_t)((kt % NSTG) * STG32 * 4);
        uint32_t tb = baseB + (uint32_t)((kt % NSTG) * STG32 * 4);
#pragma unroll
        for (int kk = 0; kk < 2; kk++) {
            unsigned af[4][4], bf[8][2];
#pragma unroll
            for (int mt = 0; mt < 4; mt++)
                ldsm4(af[mt][0], af[mt][1], af[mt][2], af[mt][3], ta + offA[mt] + kk * 32);
#pragma unroll
            for (int p = 0; p < 4; p++)
                ldsm4(bf[2 * p][0], bf[2 * p][1], bf[2 * p + 1][0], bf[2 * p + 1][1],
                      tb + offB[p] + kk * 32);
#pragma unroll
            for (int mt = 0; mt < 4; mt++)
#pragma unroll
                for (int nt = 0; nt < 8; nt++)
                    mma16(acc[mt][nt], af[mt][0], af[mt][1], af[mt][2], af[mt][3],
                          bf[nt][0], bf[nt][1]);
        }
        if (kt + 3 < 32) issue(kt + 3);
    }
}

// ---------------- generalized batched NT GEMM ----------------
struct Desc {
    const __half* A; const __half* B; const __half* A2; const __half* B2;
    const __half* CaddH;
    float* C32; __half* C16;
    int M; int N; int ldc; int dual;
};
struct Batch { Desc d[6]; };

__global__ __launch_bounds__(128) void gemm_multi(Batch p) {
    Desc d = p.d[blockIdx.z];
    int bm = blockIdx.y * 128;
    int bn = blockIdx.x * 128;
    if (bm >= d.M || bn >= d.N) return;

    extern __shared__ uint32_t sm16[];
    uint32_t* As = sm16;
    uint32_t* Bs = sm16 + NSTG * STG32;

    float acc[4][8][4];
#pragma unroll
    for (int a = 0; a < 4; a++)
#pragma unroll
        for (int b = 0; b < 8; b++)
#pragma unroll
            for (int c = 0; c < 4; c++) acc[a][b][c] = 0.f;

    run_ml16(d.A, d.B, bm, bn, acc, As, Bs);
    if (d.dual) { __syncthreads(); run_ml16(d.A2, d.B2, bm, bn, acc, As, Bs); }

    int lane = threadIdx.x & 31;
    int warp = threadIdx.x >> 5;
    int wm = (warp & 1) * 64;
    int wn = (warp >> 1) * 64;
#pragma unroll
    for (int mt = 0; mt < 4; mt++)
#pragma unroll
        for (int half_ = 0; half_ < 2; half_++) {
            int r = bm + wm + mt * 16 + (lane >> 2) + half_ * 8;
#pragma unroll
            for (int nt = 0; nt < 8; nt++) {
                int c = bn + wn + nt * 8 + (lane & 3) * 2;
                float vx = acc[mt][nt][half_ * 2 + 0];
                float vy = acc[mt][nt][half_ * 2 + 1];
                if (d.CaddH) {
                    vx += __half2float(d.CaddH[(size_t)r * d.ldc + c]);
                    vy += __half2float(d.CaddH[(size_t)r * d.ldc + c + 1]);
                }
                if (d.C16) {
                    __half2 h;
                    h.x = __float2half_rn(vx);
                    h.y = __float2half_rn(vy);
                    *(__half2*)(d.C16 + (size_t)r * d.ldc + c) = h;
                } else {
                    float2 v; v.x = vx; v.y = vy;
                    *(float2*)(d.C32 + (size_t)r * d.ldc + c) = v;
                }
            }
        }
}

// ---------------- E-GEMM (fp16) with fused logit epilogue ----------------
__global__ __launch_bounds__(128) void gemm_logit16(const int* __restrict__ sbj,
                                                    const int* __restrict__ obj) {
    extern __shared__ uint32_t sm16[];
    uint32_t* As = sm16;
    uint32_t* Bs = sm16 + NSTG * STG32;
    int bm = blockIdx.y * 128;
    int bn = blockIdx.x * 128;

    float acc[4][8][4];
#pragma unroll
    for (int a = 0; a < 4; a++)
#pragma unroll
        for (int b = 0; b < 8; b++)
#pragma unroll
            for (int c = 0; c < 4; c++) acc[a][b][c] = 0.f;

    run_ml16(g_R16, g_Kt16, bm, bn, acc, As, Bs);

    int lane = threadIdx.x & 31;
    int warp = threadIdx.x >> 5;
    int wm = (warp & 1) * 64;
    int wn = (warp >> 1) * 64;
    const float scale = 0.03125f;

#pragma unroll
    for (int mt = 0; mt < 4; mt++) {
#pragma unroll
        for (int half_ = 0; half_ < 2; half_++) {
            int r = bm + wm + mt * 16 + (lane >> 2) + half_ * 8;
            int s = sbj[r], o = obj[r];
            const __half2* Rr = (const __half2*)(g_R16 + (size_t)r * DD);
            const float* S1r = g_S1 + (size_t)s * DD;
            const float* S2r = g_S2 + (size_t)o * DD;
            float part = 0.f;
#pragma unroll
            for (int nt = 0; nt < 8; nt++) {
                int c = bn + wn + nt * 8 + (lane & 3) * 2;
                float2 Rv = __half22float2(Rr[c >> 1]);
                float2 s1v = *(const float2*)(S1r + c);
                float2 s2v = *(const float2*)(S2r + c);
                part += (acc[mt][nt][half_ * 2 + 0] + s1v.x + s2v.x) * Rv.x;
                part += (acc[mt][nt][half_ * 2 + 1] + s1v.y + s2v.y) * Rv.y;
            }
            part += __shfl_xor_sync(0xFFFFFFFF, part, 1);
            part += __shfl_xor_sync(0xFFFFFFFF, part, 2);
            if ((lane & 3) == 0) {
                if (bn == 0 && wn == 0)
                    part += g_G[(size_t)s * NN + o] + g_d1[s] + g_d2[o];
                atomicAdd(&g_logits[r], part * scale);
            }
        }
    }
}

// ---------------- final vj GEMM (fp16) ----------------
__global__ __launch_bounds__(128) void gemm_vj16(const __half* __restrict__ WctxT,
                                                 const float* __restrict__ bias,
                                                 const float* __restrict__ vf,
                                                 float* __restrict__ out) {
    extern __shared__ uint32_t sm16[];
    uint32_t* As = sm16;
    uint32_t* Bs = sm16 + NSTG * STG32;
    int bm = blockIdx.y * 128;
    int bn = blockIdx.x * 128;

    float acc[4][8][4];
#pragma unroll
    for (int a = 0; a < 4; a++)
#pragma unroll
        for (int b = 0; b < 8; b++)
#pragma unroll
            for (int c = 0; c < 4; c++) acc[a][b][c] = 0.f;

    run_ml16(g_ctx16, WctxT, bm, bn, acc, As, Bs);

    int lane = threadIdx.x & 31;
    int warp = threadIdx.x >> 5;
    int wm = (warp & 1) * 64;
    int wn = (warp >> 1) * 64;
#pragma unroll
    for (int mt = 0; mt < 4; mt++)
#pragma unroll
        for (int half_ = 0; half_ < 2; half_++) {
            int r = bm + wm + mt * 16 + (lane >> 2) + half_ * 8;
            bool inv = (g_degS[r] + g_degO[r]) > 0;
            const float* vfr = vf + (size_t)r * DD;
            float* outr = out + (size_t)r * DD;
#pragma unroll
            for (int nt = 0; nt < 8; nt++) {
                int c = bn + wn + nt * 8 + (lane & 3) * 2;
                float2 v;
                v.x = vfr[c]     + acc[mt][nt][half_ * 2 + 0] + (inv ? bias[c] : 0.f);
                v.y = vfr[c + 1] + acc[mt][nt][half_ * 2 + 1] + (inv ? bias[c + 1] : 0.f);
                *(float2*)(outr + c) = v;
            }
        }
}

// ---------------- conversion kernels ----------------
__global__ void k_copyround(const float* __restrict__ src, float* __restrict__ raw) {
    int i = blockIdx.x * 256 + threadIdx.x;
    float4 v = ((const float4*)src)[i];
    ((float4*)raw)[i] = v;
    __half2 h0, h1;
    h0.x = __float2half_rn(v.x); h0.y = __float2half_rn(v.y);
    h1.x = __float2half_rn(v.z); h1.y = __float2half_rn(v.w);
    ((__half2*)g_R16)[2 * i] = h0;
    ((__half2*)g_R16)[2 * i + 1] = h1;
}
__global__ void k_roundh(const float* __restrict__ src, __half* __restrict__ dst, int n4) {
    int i = blockIdx.x * blockDim.x + threadIdx.x;
    if (i < n4) {
        float4 v = ((const float4*)src)[i];
        __half2 h0, h1;
        h0.x = __float2half_rn(v.x); h0.y = __float2half_rn(v.y);
        h1.x = __float2half_rn(v.z); h1.y = __float2half_rn(v.w);
        ((__half2*)dst)[2 * i] = h0;
        ((__half2*)dst)[2 * i + 1] = h1;
    }
}
struct TPair { const float* s; __half* d; };
struct TBatch { TPair p[5]; };
__global__ void k_troundh(TBatch tb) {
    __shared__ float t[32][33];
    TPair pr = tb.p[blockIdx.z];
    int x = blockIdx.x * 32 + threadIdx.x;
    int y0 = blockIdx.y * 32 + threadIdx.y;
#pragma unroll
    for (int j = 0; j < 4; j++)
        t[threadIdx.y + j * 8][threadIdx.x] = pr.s[(size_t)(y0 + j * 8) * DD + x];
    __syncthreads();
    int x2 = blockIdx.y * 32 + threadIdx.x;
    int y2 = blockIdx.x * 32 + threadIdx.y;
#pragma unroll
    for (int j = 0; j < 4; j++)
        pr.d[(size_t)(y2 + j * 8) * DD + x2] = __float2half_rn(t[threadIdx.x][threadIdx.y + j * 8]);
}

// ---------------- small kernels ----------------
__global__ void k_init() {
    int i = blockIdx.x * blockDim.x + threadIdx.x;
    if (i < NN * DD) g_ctx[i] = 0.f;
    if (i < EE) g_logits[i] = 0.f;
    if (i < NN) {
        g_sumS[i] = 0.f; g_sumO[i] = 0.f;
        g_maxS[i] = 0u; g_maxO[i] = 0u;
        g_degS[i] = 0; g_degO[i] = 0;
    }
}
__global__ void k_hist(const int* __restrict__ sbj, const int* __restrict__ obj) {
    int e = blockIdx.x * blockDim.x + threadIdx.x;
    if (e < EE) { atomicAdd(&g_degS[sbj[e]], 1); atomicAdd(&g_degO[obj[e]], 1); }
}
__global__ void k_scan() {
    __shared__ int wsumS[24], wsumO[24];
    int t = threadIdx.x;
    int lane = t & 31, warp = t >> 5;
    int dS = g_degS[t], dO = g_degO[t];
    int iS = dS, iO = dO;
#pragma unroll
    for (int off = 1; off < 32; off <<= 1) {
        int vS = __shfl_up_sync(0xFFFFFFFF, iS, off);
        int vO = __shfl_up_sync(0xFFFFFFFF, iO, off);
        if (lane >= off) { iS += vS; iO += vO; }
    }
    if (lane == 31) { wsumS[warp] = iS; wsumO[warp] = iO; }
    __syncthreads();
    if (warp == 0 && lane < 24) {
        int sS = wsumS[lane], sO = wsumO[lane];
#pragma unroll
        for (int off = 1; off < 32; off <<= 1) {
            int vS = __shfl_up_sync(0x00FFFFFF, sS, off);
            int vO = __shfl_up_sync(0x00FFFFFF, sO, off);
            if (lane >= off) { sS += vS; sO += vO; }
        }
        wsumS[lane] = sS; wsumO[lane] = sO;
    }
    __syncthreads();
    int offS = (warp > 0) ? wsumS[warp - 1] : 0;
    int offO = (warp > 0) ? wsumO[warp - 1] : 0;
    g_baseS[t] = offS + iS - dS;
    g_baseO[t] = offO + iO - dO;
    g_curO[t]  = offO + iO - dO;
}
__global__ void k_scatter(const int* __restrict__ obj) {
    int e = blockIdx.x * blockDim.x + threadIdx.x;
    if (e < EE) { int p = atomicAdd(&g_curO[obj[e]], 1); g_permO[p] = e; }
}
__global__ void k_vecs1p(const float* __restrict__ b_rel,
                         const float* __restrict__ Ws_r,
                         const float* __restrict__ Wo_r) {
    int j = blockIdx.x * 256 + threadIdx.x;
    int c = blockIdx.y;
    int i0 = c * 128;
    float s = 0.f, o = 0.f;
    for (int i = i0; i < i0 + 128; i++) {
        float br = b_rel[i];
        s += br * Ws_r[(size_t)i * DD + j];
        o += br * Wo_r[(size_t)i * DD + j];
    }
    g_csp[c * DD + j] = s;
    g_cop[c * DD + j] = o;
}
__global__ void k_vecs1r(const float* __restrict__ b_sbj, const float* __restrict__ b_obj) {
    int j = blockIdx.x * 256 + threadIdx.x;
    float s = b_sbj[j], o = b_obj[j];
#pragma unroll
    for (int c = 0; c < 8; c++) {
        s += g_csp[c * DD + j];
        o += g_cop[c * DD + j];
    }
    g_cs[j] = s;
    g_co[j] = o;
}
__global__ void k_c3() {
    int j = blockIdx.x * 8 + (threadIdx.x >> 5);
    int lane = threadIdx.x & 31;
    if (j >= DD) return;
    float a = 0.f;
    for (int i = lane; i < DD; i += 32)
        a += g_cs[i] * __half2float(g_Ho16[(size_t)j * DD + i])
           + g_co[i] * __half2float(g_Hs16[(size_t)j * DD + i]);
#pragma unroll
    for (int off = 16; off > 0; off >>= 1) a += __shfl_xor_sync(0xFFFFFFFF, a, off);
    if (lane == 0) g_c3[j] = a;
}
__global__ void k_addc3() {
    int i = blockIdx.x * blockDim.x + threadIdx.x;
    if (i < NN * DD) g_S1[i] += g_c3[i & (DD - 1)];
}
__global__ void k_scal() {
    int n = blockIdx.x * 8 + (threadIdx.x >> 5);
    int lane = threadIdx.x & 31;
    if (n >= NN) return;
    const __half* Ts = g_T16 + 0 * NN * DD + (size_t)n * DD;
    const __half* Us = g_T16 + 1 * NN * DD + (size_t)n * DD;
    const __half* To = g_T16 + 2 * NN * DD + (size_t)n * DD;
    const __half* Uo = g_T16 + 3 * NN * DD + (size_t)n * DD;
    float t1 = 0.f, t2 = 0.f, t3 = 0.f;
    for (int c = lane; c < DD; c += 32) {
        float cs = g_cs[c], co = g_co[c];
        t1 += (__half2float(Ts[c]) + cs) * (__half2float(Uo[c]) + co);
        t2 += (__half2float(Us[c]) + cs) * (__half2float(To[c]) + co);
        t3 += cs * co;
    }
#pragma unroll
    for (int off = 16; off > 0; off >>= 1) {
        t1 += __shfl_xor_sync(0xFFFFFFFF, t1, off);
        t2 += __shfl_xor_sync(0xFFFFFFFF, t2, off);
        t3 += __shfl_xor_sync(0xFFFFFFFF, t3, off);
    }
    if (lane == 0) { g_d1[n] = t1; g_d2[n] = t2 - t3; }
}
__global__ void k_max(const int* __restrict__ sbj, const int* __restrict__ obj) {
    int e = blockIdx.x * blockDim.x + threadIdx.x;
    if (e < EE) {
        unsigned k = fkey(g_logits[e]);
        atomicMax(&g_maxS[sbj[e]], k);
        atomicMax(&g_maxO[obj[e]], k);
    }
}
__global__ void k_exp(const int* __restrict__ sbj, const int* __restrict__ obj) {
    int e = blockIdx.x * blockDim.x + threadIdx.x;
    if (e < EE) {
        float l = g_logits[e];
        float es = expf(l - funkey(g_maxS[sbj[e]]));
        float eo = expf(l - funkey(g_maxO[obj[e]]));
        g_wS[e] = es; g_wO[e] = eo;
        atomicAdd(&g_sumS[sbj[e]], es);
        atomicAdd(&g_sumO[obj[e]], eo);
    }
}
__global__ void k_ctxS(const int* __restrict__ obj, const float* __restrict__ vf) {
    int n = blockIdx.x, t = threadIdx.x;
    int beg = g_baseS[n], cnt = g_degS[n];
    if (cnt == 0) return;
    float inv = 1.f / g_sumS[n];
    const float4* vf4 = (const float4*)vf;
    float4 acc = make_float4(0.f, 0.f, 0.f, 0.f);
    for (int i = 0; i < cnt; i++) {
        int e = beg + i;
        float w = g_wS[e];
        float4 v = vf4[(size_t)obj[e] * 256 + t];
        acc.x += w * v.x; acc.y += w * v.y; acc.z += w * v.z; acc.w += w * v.w;
    }
    acc.x *= inv; acc.y *= inv; acc.z *= inv; acc.w *= inv;
    ((float4*)g_ctx)[(size_t)n * 256 + t] = acc;
}
__global__ void k_ctxO(const int* __restrict__ sbj, const float* __restrict__ vf) {
    int n = blockIdx.x, t = threadIdx.x;
    int beg = g_baseO[n], cnt = g_degO[n];
    float4* c4 = (float4*)g_ctx;
    float4 old = c4[(size_t)n * 256 + t];
    if (cnt > 0) {
        float inv = 1.f / g_sumO[n];
        const float4* vf4 = (const float4*)vf;
        float4 acc = make_float4(0.f, 0.f, 0.f, 0.f);
        for (int i = 0; i < cnt; i++) {
            int e = g_permO[beg + i];
            float w = g_wO[e];
            float4 v = vf4[(size_t)sbj[e] * 256 + t];
            acc.x += w * v.x; acc.y += w * v.y; acc.z += w * v.z; acc.w += w * v.w;
        }
        old.x += acc.x * inv; old.y += acc.y * inv; old.z += acc.z * inv; old.w += acc.w * inv;
    }
    __half2 h0, h1;
    h0.x = __float2half_rn(old.x); h0.y = __float2half_rn(old.y);
    h1.x = __float2half_rn(old.z); h1.y = __float2half_rn(old.w);
    ((__half2*)g_ctx16)[(size_t)n * 512 + 2 * t]     = h0;
    ((__half2*)g_ctx16)[(size_t)n * 512 + 2 * t + 1] = h1;
}

// ---------------- launch ----------------
extern "C" void kernel_launch(void* const* d_in, const int* in_sizes, int n_in,
                              void* d_out, int out_size) {
    const float* vf    = (const float*)d_in[0];
    const float* R     = (const float*)d_in[1];
    const float* W_rel = (const float*)d_in[2];
    const float* b_rel = (const float*)d_in[3];
    const float* W_sbj = (const float*)d_in[4];
    const float* b_sbj = (const float*)d_in[5];
    const float* W_obj = (const float*)d_in[6];
    const float* b_obj = (const float*)d_in[7];
    const float* W_ctx = (const float*)d_in[8];
    const float* b_ctx = (const float*)d_in[9];
    const int* sbj     = (const int*)d_in[10];
    const int* obj     = (const int*)d_in[11];
    float* out = (float*)d_out;

    cudaFuncSetAttribute(gemm_multi,   cudaFuncAttributeMaxDynamicSharedMemorySize, SMEM16_BYTES);
    cudaFuncSetAttribute(gemm_logit16, cudaFuncAttributeMaxDynamicSharedMemorySize, SMEM16_BYTES);
    cudaFuncSetAttribute(gemm_vj16,    cudaFuncAttributeMaxDynamicSharedMemorySize, SMEM16_BYTES);

    __half *pHs, *pHo, *pKt, *pMT, *pT, *pWr, *pWT, *pVf;
    cudaGetSymbolAddress((void**)&pHs, g_Hs16);
    cudaGetSymbolAddress((void**)&pHo, g_Ho16);
    cudaGetSymbolAddress((void**)&pKt, g_Kt16);
    cudaGetSymbolAddress((void**)&pMT, g_MT16);
    cudaGetSymbolAddress((void**)&pT,  g_T16);
    cudaGetSymbolAddress((void**)&pWr, g_Wr16);
    cudaGetSymbolAddress((void**)&pWT, g_WT16);
    cudaGetSymbolAddress((void**)&pVf, g_vf16);
    float *pS1, *pS2, *pG;
    cudaGetSymbolAddress((void**)&pS1, g_S1);
    cudaGetSymbolAddress((void**)&pS2, g_S2);
    cudaGetSymbolAddress((void**)&pG,  g_G);

    const __half* hWr_s = pWr + 0 * (size_t)DD * DD;
    const __half* hWr_o = pWr + 1 * (size_t)DD * DD;
    const __half* hWr_r = pWr + 2 * (size_t)DD * DD;
    __half* hWs_rT = pWT + 0 * (size_t)DD * DD;
    __half* hWo_rT = pWT + 1 * (size_t)DD * DD;
    __half* hWctxT = pWT + 2 * (size_t)DD * DD;
    __half* hWs_vT = pWT + 3 * (size_t)DD * DD;
    __half* hWo_vT = pWT + 4 * (size_t)DD * DD;

    const float* Ws_v = W_sbj;
    const float* Ws_r = W_sbj + (size_t)DD * DD;
    const float* Wo_v = W_obj;
    const float* Wo_r = W_obj + (size_t)DD * DD;

    k_copyround<<<EE * DD / 4 / 256, 256>>>(R, out);

    k_init<<<(NN * DD + 255) / 256, 256>>>();
    k_hist<<<(EE + 255) / 256, 256>>>(sbj, obj);
    k_scan<<<1, 768>>>();
    k_scatter<<<(EE + 255) / 256, 256>>>(obj);
    k_vecs1p<<<dim3(4, 8), 256>>>(b_rel, Ws_r, Wo_r);
    k_vecs1r<<<4, 256>>>(b_sbj, b_obj);

    k_roundh<<<(3 * DD * DD / 4 + 255) / 256, 256>>>(W_rel, pWr, 3 * DD * DD / 4);
    k_roundh<<<(NN * DD / 4 + 255) / 256, 256>>>(vf, pVf, NN * DD / 4);
    {
        TBatch tb{};
        tb.p[0] = {Ws_r,  hWs_rT};
        tb.p[1] = {Wo_r,  hWo_rT};
        tb.p[2] = {W_ctx, hWctxT};
        tb.p[3] = {Ws_v,  hWs_vT};
        tb.p[4] = {Wo_v,  hWo_vT};
        k_troundh<<<dim3(32, 32, 5), dim3(32, 8)>>>(tb);
    }

    // L1: Hs, Ho, M1T..M4T
    {
        Batch b{};
        b.d[0] = {hWr_r,  hWs_rT, nullptr, nullptr, nullptr, nullptr, pHs,                        DD, DD, DD, 0};
        b.d[1] = {hWr_r,  hWo_rT, nullptr, nullptr, nullptr, nullptr, pHo,                        DD, DD, DD, 0};
        b.d[2] = {hWs_rT, hWr_s,  nullptr, nullptr, hWs_vT,  nullptr, pMT + 0 * (size_t)DD * DD,  DD, DD, DD, 0};
        b.d[3] = {hWs_rT, hWr_o,  nullptr, nullptr, nullptr, nullptr, pMT + 1 * (size_t)DD * DD,  DD, DD, DD, 0};
        b.d[4] = {hWo_rT, hWr_o,  nullptr, nullptr, hWo_vT,  nullptr, pMT + 2 * (size_t)DD * DD,  DD, DD, DD, 0};
        b.d[5] = {hWo_rT, hWr_s,  nullptr, nullptr, nullptr, nullptr, pMT + 3 * (size_t)DD * DD,  DD, DD, DD, 0};
        gemm_multi<<<dim3(8, 8, 6), 128, SMEM16_BYTES>>>(b);
    }
    // L2: T_z (M=768) + Kt
    {
        Batch b{};
        for (int z = 0; z < 4; z++)
            b.d[z] = {pVf, pMT + (size_t)z * DD * DD, nullptr, nullptr, nullptr, nullptr,
                      pT + (size_t)z * NN * DD, NN, DD, DD, 0};
        b.d[4] = {pHo, pHs, nullptr, nullptr, nullptr, nullptr, pKt, DD, DD, DD, 0};
        gemm_multi<<<dim3(8, 8, 5), 128, SMEM16_BYTES>>>(b);
    }
    // L3: S1, S2, G
    {
        Batch b{};
        b.d[0] = {pT + 0 * (size_t)NN * DD, pHo, pT + 3 * (size_t)NN * DD, pHs, nullptr, pS1, nullptr,
                  NN, DD, DD, 1};
        b.d[1] = {pT + 1 * (size_t)NN * DD, pHo, pT + 2 * (size_t)NN * DD, pHs, nullptr, pS2, nullptr,
                  NN, DD, DD, 1};
        b.d[2] = {pT + 0 * (size_t)NN * DD, pT + 2 * (size_t)NN * DD,
                  pT + 3 * (size_t)NN * DD, pT + 1 * (size_t)NN * DD, nullptr, pG, nullptr,
                  NN, NN, NN, 1};
        gemm_multi<<<dim3(8, 6, 3), 128, SMEM16_BYTES>>>(b);
    }
    k_c3<<<128, 256>>>();
    k_addc3<<<(NN * DD + 255) / 256, 256>>>();
    k_scal<<<96, 256>>>();

    gemm_logit16<<<dim3(8, 192), 128, SMEM16_BYTES>>>(sbj, obj);

    k_max<<<(EE + 255) / 256, 256>>>(sbj, obj);
    k_exp<<<(EE + 255) / 256, 256>>>(sbj, obj);
    k_ctxS<<<NN, 256>>>(obj, vf);
    k_ctxO<<<NN, 256>>>(sbj, vf);

    gemm_vj16<<<dim3(8, 6), 128, SMEM16_BYTES>>>(hWctxT, b_ctx, vf, out + (size_t)EE * DD);

    (void)in_sizes; (void)n_in; (void)out_size;
}